// round 3
// baseline (speedup 1.0000x reference)
#include <cuda_runtime.h>
#include <cstdint>

#define NMAX   50000
#define EMAX   800000
#define FDIM   128
#define DDIM   32
#define CUT    5.0f
#define PI_F   3.14159265358979323846f

// ---------------- device scratch (static, allocation-free) ----------------
__device__ float  g_q [NMAX * DDIM];
__device__ float  g_q2[NMAX * DDIM];
__device__ int    g_cnt[NMAX];
__device__ int    g_off[NMAX];
__device__ int    g_cur[NMAX];
__device__ int    g_bsum[64];
__device__ float4 g_cwv[EMAX];

__device__ __forceinline__ float swish_f(float v) {
    return v / (1.0f + __expf(-v));
}

// ---- packed f32x2 helpers (FFMA2: ptxas never emits this from C++) -------
__device__ __forceinline__ unsigned long long pack2(float a) {
    unsigned long long r;
    asm("mov.b64 %0, {%1, %1};" : "=l"(r) : "f"(a));
    return r;
}
__device__ __forceinline__ void fma2(unsigned long long& d,
                                     unsigned long long a,
                                     unsigned long long b) {
    asm("fma.rn.f32x2 %0, %1, %2, %0;" : "+l"(d) : "l"(a), "l"(b));
}
__device__ __forceinline__ float2 unpack2(unsigned long long v) {
    float2 f;
    asm("mov.b64 {%0, %1}, %2;" : "=f"(f.x), "=f"(f.y) : "l"(v));
    return f;
}

// ---------------- node transform: q = swish(swish(x@W1+b1)@W2+b2) ----------
// 64 rows/block, 256 threads, f32x2 packed-FMA GEMM.
// smem: sW1 [128][128] | sXd [128][130] transposed+duplicated x (reused as
//       sH [64][258] duplicated h) | sW2 [128][32]
#define SW1_F  (128 * 128)           // 16384
#define SXD_LD 130
#define SXD_F  (128 * SXD_LD)        // 16640  (>= 64*258 = 16512 for sH)
#define SH_LD  258
#define SW2_F  (128 * 32)            // 4096
#define SMEM_F (SW1_F + SXD_F + SW2_F)   // 37120 floats = 148480 bytes

__global__ __launch_bounds__(256, 1) void transform_kernel(
    const float* __restrict__ x,
    const float* __restrict__ W1, const float* __restrict__ b1,
    const float* __restrict__ W2, const float* __restrict__ b2,
    int branch, int nrows)
{
    extern __shared__ float sm[];
    float* sW1 = sm;                 // [k][c], stride 128
    float* sXd = sm + SW1_F;         // [k][2r+h], stride 130 (later sH)
    float* sW2 = sm + SW1_F + SXD_F; // [k][c], stride 32
    float* q_out = branch ? g_q2 : g_q;

    const int tid  = threadIdx.x;
    const int row0 = blockIdx.x * 64;

    // ---- phase 0: load W1, W2, x-tile (transposed + duplicated) ----
    for (int i = tid; i < 4096; i += 256)
        *reinterpret_cast<float4*>(sW1 + 4 * i) =
            *reinterpret_cast<const float4*>(W1 + 4 * i);
    for (int i = tid; i < 1024; i += 256)
        *reinterpret_cast<float4*>(sW2 + 4 * i) =
            *reinterpret_cast<const float4*>(W2 + 4 * i);
    for (int i = tid; i < 2048; i += 256) {
        int r  = i >> 5;             // 0..63
        int c4 = (i & 31) << 2;      // 0..124 (k-chunk of 4)
        int row = row0 + r;
        float4 v = make_float4(0.f, 0.f, 0.f, 0.f);
        if (row < nrows)
            v = *reinterpret_cast<const float4*>(x + (size_t)row * 128 + c4);
        *reinterpret_cast<float2*>(sXd + (c4 + 0) * SXD_LD + 2 * r) = make_float2(v.x, v.x);
        *reinterpret_cast<float2*>(sXd + (c4 + 1) * SXD_LD + 2 * r) = make_float2(v.y, v.y);
        *reinterpret_cast<float2*>(sXd + (c4 + 2) * SXD_LD + 2 * r) = make_float2(v.z, v.z);
        *reinterpret_cast<float2*>(sXd + (c4 + 3) * SXD_LD + 2 * r) = make_float2(v.w, v.w);
    }
    __syncthreads();

    // ---- phase 1: layer1 = x @ W1 via f32x2 -------------------------------
    // thread (ty,tx): rows ty*4+i (i<4); cols {tx*4..+3} and {64+tx*4..+3}
    const int ty = tid >> 4;         // 0..15
    const int tx = tid & 15;         // 0..15
    const int cA = tx << 2;          // 0..60
    const int cB = 64 + cA;          // 64..124

    unsigned long long accA[4][2], accB[4][2];
    #pragma unroll
    for (int i = 0; i < 4; i++) {
        accA[i][0] = accA[i][1] = 0ull;
        accB[i][0] = accB[i][1] = 0ull;
    }

    #pragma unroll 4
    for (int k = 0; k < 128; k++) {
        unsigned long long ap[4];
        #pragma unroll
        for (int i = 0; i < 4; i++)
            ap[i] = *reinterpret_cast<const unsigned long long*>(
                        sXd + k * SXD_LD + 2 * (ty * 4 + i));
        float4 wa4 = *reinterpret_cast<const float4*>(sW1 + k * 128 + cA);
        float4 wb4 = *reinterpret_cast<const float4*>(sW1 + k * 128 + cB);
        const unsigned long long* wa = reinterpret_cast<const unsigned long long*>(&wa4);
        const unsigned long long* wb = reinterpret_cast<const unsigned long long*>(&wb4);
        #pragma unroll
        for (int i = 0; i < 4; i++) {
            fma2(accA[i][0], ap[i], wa[0]);
            fma2(accA[i][1], ap[i], wa[1]);
            fma2(accB[i][0], ap[i], wb[0]);
            fma2(accB[i][1], ap[i], wb[1]);
        }
    }
    __syncthreads();   // all sXd reads done before overwrite as sH

    // ---- phase 2: h = swish(layer1 + b1) -> sH duplicated -----------------
    float* sH = sXd;   // [r][2k+h], stride SH_LD
    {
        float bA0 = __ldg(b1 + cA),     bA1 = __ldg(b1 + cA + 1);
        float bA2 = __ldg(b1 + cA + 2), bA3 = __ldg(b1 + cA + 3);
        float bB0 = __ldg(b1 + cB),     bB1 = __ldg(b1 + cB + 1);
        float bB2 = __ldg(b1 + cB + 2), bB3 = __ldg(b1 + cB + 3);
        #pragma unroll
        for (int i = 0; i < 4; i++) {
            int r = ty * 4 + i;
            float2 a0 = unpack2(accA[i][0]);
            float2 a1 = unpack2(accA[i][1]);
            float2 b0 = unpack2(accB[i][0]);
            float2 b1v = unpack2(accB[i][1]);
            float h0 = swish_f(a0.x + bA0);
            float h1 = swish_f(a0.y + bA1);
            float h2 = swish_f(a1.x + bA2);
            float h3 = swish_f(a1.y + bA3);
            float h4 = swish_f(b0.x + bB0);
            float h5 = swish_f(b0.y + bB1);
            float h6 = swish_f(b1v.x + bB2);
            float h7 = swish_f(b1v.y + bB3);
            float* hp = sH + r * SH_LD;
            *reinterpret_cast<float2*>(hp + 2 * (cA + 0)) = make_float2(h0, h0);
            *reinterpret_cast<float2*>(hp + 2 * (cA + 1)) = make_float2(h1, h1);
            *reinterpret_cast<float2*>(hp + 2 * (cA + 2)) = make_float2(h2, h2);
            *reinterpret_cast<float2*>(hp + 2 * (cA + 3)) = make_float2(h3, h3);
            *reinterpret_cast<float2*>(hp + 2 * (cB + 0)) = make_float2(h4, h4);
            *reinterpret_cast<float2*>(hp + 2 * (cB + 1)) = make_float2(h5, h5);
            *reinterpret_cast<float2*>(hp + 2 * (cB + 2)) = make_float2(h6, h6);
            *reinterpret_cast<float2*>(hp + 2 * (cB + 3)) = make_float2(h7, h7);
        }
    }
    __syncthreads();

    // ---- phase 3: q = swish(h @ W2 + b2), f32x2 ---------------------------
    const int r2 = tid >> 2;         // 0..63
    const int c0 = (tid & 3) << 3;   // 0,8,16,24
    unsigned long long acc2[4];
    #pragma unroll
    for (int j = 0; j < 4; j++) acc2[j] = 0ull;

    #pragma unroll 4
    for (int k = 0; k < 128; k++) {
        unsigned long long a = *reinterpret_cast<const unsigned long long*>(
                                   sH + r2 * SH_LD + 2 * k);
        float4 w0 = *reinterpret_cast<const float4*>(sW2 + k * 32 + c0);
        float4 w1 = *reinterpret_cast<const float4*>(sW2 + k * 32 + c0 + 4);
        const unsigned long long* wp0 = reinterpret_cast<const unsigned long long*>(&w0);
        const unsigned long long* wp1 = reinterpret_cast<const unsigned long long*>(&w1);
        fma2(acc2[0], a, wp0[0]);
        fma2(acc2[1], a, wp0[1]);
        fma2(acc2[2], a, wp1[0]);
        fma2(acc2[3], a, wp1[1]);
    }

    int row = row0 + r2;
    if (row < nrows) {
        float o[8];
        #pragma unroll
        for (int j = 0; j < 4; j++) {
            float2 v = unpack2(acc2[j]);
            o[2 * j]     = swish_f(v.x + __ldg(b2 + c0 + 2 * j));
            o[2 * j + 1] = swish_f(v.y + __ldg(b2 + c0 + 2 * j + 1));
        }
        float* qp = q_out + (size_t)row * DDIM + c0;
        *reinterpret_cast<float4*>(qp)     = reinterpret_cast<float4*>(o)[0];
        *reinterpret_cast<float4*>(qp + 4) = reinterpret_cast<float4*>(o)[1];
    }
}

// ---------------- CSR build ----------------
__global__ void zero_cnt_kernel(int n) {
    int i = blockIdx.x * blockDim.x + threadIdx.x;
    if (i < n) g_cnt[i] = 0;
}

__global__ void count_kernel(const int* __restrict__ dst,
                             const float* __restrict__ rij, int E) {
    int e = blockIdx.x * blockDim.x + threadIdx.x;
    if (e < E && rij[e] < CUT) atomicAdd(&g_cnt[dst[e]], 1);
}

// 2048 elems per block (256 thr x 8), 3-kernel exclusive scan
__global__ void scan1_kernel(int n) {
    __shared__ int s[256];
    int base = blockIdx.x * 2048 + threadIdx.x * 8;
    int v[8];
    int sum = 0;
    #pragma unroll
    for (int j = 0; j < 8; j++) {
        int idx = base + j;
        int t = (idx < n) ? g_cnt[idx] : 0;
        v[j] = sum;
        sum += t;
    }
    s[threadIdx.x] = sum;
    __syncthreads();
    for (int off = 1; off < 256; off <<= 1) {
        int t = (threadIdx.x >= off) ? s[threadIdx.x - off] : 0;
        __syncthreads();
        s[threadIdx.x] += t;
        __syncthreads();
    }
    int excl = s[threadIdx.x] - sum;
    if (threadIdx.x == 255) g_bsum[blockIdx.x] = s[255];
    #pragma unroll
    for (int j = 0; j < 8; j++) {
        int idx = base + j;
        if (idx < n) g_off[idx] = excl + v[j];
    }
}

__global__ void scan2_kernel(int nb) {
    if (threadIdx.x == 0) {
        int a = 0;
        for (int i = 0; i < nb; i++) { int t = g_bsum[i]; g_bsum[i] = a; a += t; }
    }
}

__global__ void scan3_kernel(int n) {
    int i = blockIdx.x * blockDim.x + threadIdx.x;
    if (i < n) {
        int o = g_off[i] + g_bsum[i >> 11];
        g_off[i] = o;
        g_cur[i] = o;
    }
}

__global__ void scatter_kernel(const int* __restrict__ src,
                               const int* __restrict__ dst,
                               const float* __restrict__ rij,
                               const float* __restrict__ vij, int E) {
    int e = blockIdx.x * blockDim.x + threadIdx.x;
    if (e >= E) return;
    float r = rij[e];
    if (r < CUT) {
        float c = 0.5f * (cosf(PI_F * r / CUT) + 1.0f);
        int p = atomicAdd(&g_cur[dst[e]], 1);
        g_cwv[p] = make_float4(c * vij[3 * e], c * vij[3 * e + 1],
                               c * vij[3 * e + 2], __int_as_float(src[e]));
    }
}

// ---------------- gather + cross + mix, one warp per node, lane = d --------
__global__ __launch_bounds__(256) void gather_kernel(
    const float* __restrict__ wmix, const float* __restrict__ bmix,
    float* __restrict__ out, int nNodes)
{
    int gw   = (blockIdx.x * 256 + threadIdx.x) >> 5;
    int lane = threadIdx.x & 31;
    if (gw >= nNodes) return;

    int start = g_off[gw];
    int m     = g_cnt[gw];

    float ax = 0.f, ay = 0.f, az = 0.f;
    float bx = 0.f, by = 0.f, bz = 0.f;

    int i = 0;
    for (; i + 2 <= m; i += 2) {
        float4 w0 = __ldg(&g_cwv[start + i]);
        float4 w1 = __ldg(&g_cwv[start + i + 1]);
        int s0 = __float_as_int(w0.w);
        int s1 = __float_as_int(w1.w);
        float qa = __ldg(&g_q [s0 * DDIM + lane]);
        float pa = __ldg(&g_q2[s0 * DDIM + lane]);
        float qb = __ldg(&g_q [s1 * DDIM + lane]);
        float pb = __ldg(&g_q2[s1 * DDIM + lane]);
        ax = fmaf(w0.x, qa, ax); ax = fmaf(w1.x, qb, ax);
        ay = fmaf(w0.y, qa, ay); ay = fmaf(w1.y, qb, ay);
        az = fmaf(w0.z, qa, az); az = fmaf(w1.z, qb, az);
        bx = fmaf(w0.x, pa, bx); bx = fmaf(w1.x, pb, bx);
        by = fmaf(w0.y, pa, by); by = fmaf(w1.y, pb, by);
        bz = fmaf(w0.z, pa, bz); bz = fmaf(w1.z, pb, bz);
    }
    if (i < m) {
        float4 w0 = __ldg(&g_cwv[start + i]);
        int s0 = __float_as_int(w0.w);
        float qa = __ldg(&g_q [s0 * DDIM + lane]);
        float pa = __ldg(&g_q2[s0 * DDIM + lane]);
        ax = fmaf(w0.x, qa, ax);
        ay = fmaf(w0.y, qa, ay);
        az = fmaf(w0.z, qa, az);
        bx = fmaf(w0.x, pa, bx);
        by = fmaf(w0.y, pa, by);
        bz = fmaf(w0.z, pa, bz);
    }

    float m0 = __ldg(wmix), m1 = __ldg(wmix + 1), m2 = __ldg(wmix + 2);
    float bm = __ldg(bmix);

    // cross(mu, mu2)
    float cx = ay * bz - az * by;
    float cy = az * bx - ax * bz;
    float cz = ax * by - ay * bx;

    size_t p = (size_t)gw * (DDIM * 3) + lane * 3;
    out[p + 0] = ax * m0 + bx * m1 + cx * m2 + bm;
    out[p + 1] = ay * m0 + by * m1 + cy * m2 + bm;
    out[p + 2] = az * m0 + bz * m1 + cz * m2 + bm;
}

// ---------------- launch ----------------
extern "C" void kernel_launch(void* const* d_in, const int* in_sizes, int n_in,
                              void* d_out, int out_size)
{
    const float* x    = (const float*)d_in[0];
    const float* rij  = (const float*)d_in[1];
    const float* vij  = (const float*)d_in[2];
    const int*   src  = (const int*)  d_in[3];
    const int*   dst  = (const int*)  d_in[4];
    const float* W1   = (const float*)d_in[5];
    const float* b1   = (const float*)d_in[6];
    const float* W2   = (const float*)d_in[7];
    const float* b2   = (const float*)d_in[8];
    const float* W1b  = (const float*)d_in[9];
    const float* b1b  = (const float*)d_in[10];
    const float* W2b  = (const float*)d_in[11];
    const float* b2b  = (const float*)d_in[12];
    const float* wmix = (const float*)d_in[13];
    const float* bmix = (const float*)d_in[14];
    float* out = (float*)d_out;

    int N = in_sizes[0] / FDIM;
    int E = in_sizes[1];
    if (N > NMAX) N = NMAX;
    if (E > EMAX) E = EMAX;

    const size_t smem_bytes = SMEM_F * sizeof(float);  // 148480
    cudaFuncSetAttribute(transform_kernel,
                         cudaFuncAttributeMaxDynamicSharedMemorySize,
                         (int)smem_bytes);

    int gT = (N + 63) / 64;
    transform_kernel<<<gT, 256, smem_bytes>>>(x, W1,  b1,  W2,  b2,  0, N);
    transform_kernel<<<gT, 256, smem_bytes>>>(x, W1b, b1b, W2b, b2b, 1, N);

    int gE = (E + 255) / 256;
    int gN = (N + 255) / 256;
    int nb = (N + 2047) / 2048;

    zero_cnt_kernel<<<gN, 256>>>(N);
    count_kernel<<<gE, 256>>>(dst, rij, E);
    scan1_kernel<<<nb, 256>>>(N);
    scan2_kernel<<<1, 32>>>(nb);
    scan3_kernel<<<gN, 256>>>(N);
    scatter_kernel<<<gE, 256>>>(src, dst, rij, vij, E);

    int gG = (N * 32 + 255) / 256;
    gather_kernel<<<gG, 256>>>(wmix, bmix, out, N);
}

// round 4
// speedup vs baseline: 1.2351x; 1.2351x over previous
#include <cuda_runtime.h>
#include <cstdint>

#define NMAX   50000
#define EMAX   800000
#define FDIM   128
#define DDIM   32
#define CUT    5.0f
#define PI_F   3.14159265358979323846f

// ---------------- device scratch (static, allocation-free) ----------------
__device__ float  g_q [NMAX * DDIM];
__device__ float  g_q2[NMAX * DDIM];
__device__ int    g_cnt[NMAX];
__device__ int    g_off[NMAX];
__device__ int    g_cur[NMAX];
__device__ int    g_bsum[64];
__device__ float4 g_cwv[EMAX];

__device__ __forceinline__ float swish_f(float v) {
    return v / (1.0f + __expf(-v));
}

// ---------------- node transform: q = swish(swish(x@W1+b1)@W2+b2) ----------
// 128 rows/block, 256 threads (16x16), 8x8 register tile per thread.
// blockIdx.y = branch. smem: sW1[128][128] | sXT[128][132] transposed x
// (reused as sH[128][132] row-major h) | sW2[128][32]
#define SW1_F  (128 * 128)              // 16384
#define SXT_LD 132
#define SXT_F  (128 * SXT_LD)           // 16896
#define SW2_F  (128 * 32)               // 4096
#define SMEM_F (SW1_F + SXT_F + SW2_F)  // 37376 floats = 149504 bytes

__global__ __launch_bounds__(256, 1) void transform_kernel(
    const float* __restrict__ x,
    const float* __restrict__ W1a, const float* __restrict__ b1a,
    const float* __restrict__ W2a, const float* __restrict__ b2a,
    const float* __restrict__ W1b, const float* __restrict__ b1b,
    const float* __restrict__ W2b, const float* __restrict__ b2b,
    int nrows)
{
    extern __shared__ float sm[];
    float* sW1 = sm;                 // [k][c], stride 128
    float* sXT = sm + SW1_F;         // [k][r], stride 132 (later sH [r][k])
    float* sW2 = sm + SW1_F + SXT_F; // [k][c], stride 32

    const int branch = blockIdx.y;
    const float* W1 = branch ? W1b : W1a;
    const float* b1 = branch ? b1b : b1a;
    const float* W2 = branch ? W2b : W2a;
    const float* b2 = branch ? b2b : b2a;
    float* q_out = branch ? g_q2 : g_q;

    const int tid  = threadIdx.x;
    const int row0 = blockIdx.x * 128;

    // ---- phase 0: load W1, W2, x-tile (transposed) ----
    for (int i = tid; i < 4096; i += 256)
        *reinterpret_cast<float4*>(sW1 + 4 * i) =
            *reinterpret_cast<const float4*>(W1 + 4 * i);
    for (int i = tid; i < 1024; i += 256)
        *reinterpret_cast<float4*>(sW2 + 4 * i) =
            *reinterpret_cast<const float4*>(W2 + 4 * i);
    for (int i = tid; i < 4096; i += 256) {
        int r  = i & 127;            // 0..127 (warp-consecutive -> STS banks ok)
        int c4 = (i >> 7) << 2;      // 0..124
        int row = row0 + r;
        float4 v = make_float4(0.f, 0.f, 0.f, 0.f);
        if (row < nrows)
            v = *reinterpret_cast<const float4*>(x + (size_t)row * 128 + c4);
        sXT[(c4 + 0) * SXT_LD + r] = v.x;
        sXT[(c4 + 1) * SXT_LD + r] = v.y;
        sXT[(c4 + 2) * SXT_LD + r] = v.z;
        sXT[(c4 + 3) * SXT_LD + r] = v.w;
    }
    __syncthreads();

    // ---- phase 1: layer1 = x @ W1 ; thread (ty,tx): rows ty*8.., cols tx*8..
    const int ty = tid >> 4;         // 0..15
    const int tx = tid & 15;         // 0..15
    float acc[8][8];
    #pragma unroll
    for (int i = 0; i < 8; i++)
        #pragma unroll
        for (int j = 0; j < 8; j++) acc[i][j] = 0.f;

    #pragma unroll 2
    for (int k = 0; k < 128; k++) {
        float a[8], w[8];
        reinterpret_cast<float4*>(a)[0] =
            *reinterpret_cast<const float4*>(sXT + k * SXT_LD + (ty << 3));
        reinterpret_cast<float4*>(a)[1] =
            *reinterpret_cast<const float4*>(sXT + k * SXT_LD + (ty << 3) + 4);
        reinterpret_cast<float4*>(w)[0] =
            *reinterpret_cast<const float4*>(sW1 + k * 128 + (tx << 3));
        reinterpret_cast<float4*>(w)[1] =
            *reinterpret_cast<const float4*>(sW1 + k * 128 + (tx << 3) + 4);
        #pragma unroll
        for (int i = 0; i < 8; i++)
            #pragma unroll
            for (int j = 0; j < 8; j++)
                acc[i][j] = fmaf(a[i], w[j], acc[i][j]);
    }
    __syncthreads();   // all sXT reads done before overwrite as sH

    // ---- phase 2: h = swish(layer1 + b1) -> sH row-major [r][k] stride 132 --
    float* sH = sXT;
    {
        float bj[8];
        reinterpret_cast<float4*>(bj)[0] =
            *reinterpret_cast<const float4*>(b1 + (tx << 3));
        reinterpret_cast<float4*>(bj)[1] =
            *reinterpret_cast<const float4*>(b1 + (tx << 3) + 4);
        #pragma unroll
        for (int i = 0; i < 8; i++) {
            float h[8];
            #pragma unroll
            for (int j = 0; j < 8; j++)
                h[j] = swish_f(acc[i][j] + bj[j]);
            float* hp = sH + ((ty << 3) + i) * SXT_LD + (tx << 3);
            *reinterpret_cast<float4*>(hp)     = reinterpret_cast<float4*>(h)[0];
            *reinterpret_cast<float4*>(hp + 4) = reinterpret_cast<float4*>(h)[1];
        }
    }
    __syncthreads();

    // ---- phase 3: q = swish(h @ W2 + b2) ; thread: row tid>>1, 16 cols ----
    const int r2 = tid >> 1;          // 0..127
    const int c0 = (tid & 1) << 4;    // 0,16
    float acc2[16];
    #pragma unroll
    for (int j = 0; j < 16; j++) acc2[j] = 0.f;

    #pragma unroll 4
    for (int k = 0; k < 128; k++) {
        float a = sH[r2 * SXT_LD + k];
        float w[16];
        reinterpret_cast<float4*>(w)[0] =
            *reinterpret_cast<const float4*>(sW2 + k * 32 + c0);
        reinterpret_cast<float4*>(w)[1] =
            *reinterpret_cast<const float4*>(sW2 + k * 32 + c0 + 4);
        reinterpret_cast<float4*>(w)[2] =
            *reinterpret_cast<const float4*>(sW2 + k * 32 + c0 + 8);
        reinterpret_cast<float4*>(w)[3] =
            *reinterpret_cast<const float4*>(sW2 + k * 32 + c0 + 12);
        #pragma unroll
        for (int j = 0; j < 16; j++) acc2[j] = fmaf(a, w[j], acc2[j]);
    }

    int row = row0 + r2;
    if (row < nrows) {
        float o[16];
        #pragma unroll
        for (int j = 0; j < 16; j++)
            o[j] = swish_f(acc2[j] + __ldg(b2 + c0 + j));
        float* qp = q_out + (size_t)row * DDIM + c0;
        *reinterpret_cast<float4*>(qp)      = reinterpret_cast<float4*>(o)[0];
        *reinterpret_cast<float4*>(qp + 4)  = reinterpret_cast<float4*>(o)[1];
        *reinterpret_cast<float4*>(qp + 8)  = reinterpret_cast<float4*>(o)[2];
        *reinterpret_cast<float4*>(qp + 12) = reinterpret_cast<float4*>(o)[3];
    }
}

// ---------------- CSR build ----------------
__global__ void zero_cnt_kernel(int n) {
    int i = blockIdx.x * blockDim.x + threadIdx.x;
    if (i < n) g_cnt[i] = 0;
}

__global__ void count_kernel(const int* __restrict__ dst,
                             const float* __restrict__ rij, int E) {
    int e = blockIdx.x * blockDim.x + threadIdx.x;
    if (e < E && rij[e] < CUT) atomicAdd(&g_cnt[dst[e]], 1);
}

// 2048 elems per block (256 thr x 8), 3-kernel exclusive scan
__global__ void scan1_kernel(int n) {
    __shared__ int s[256];
    int base = blockIdx.x * 2048 + threadIdx.x * 8;
    int v[8];
    int sum = 0;
    #pragma unroll
    for (int j = 0; j < 8; j++) {
        int idx = base + j;
        int t = (idx < n) ? g_cnt[idx] : 0;
        v[j] = sum;
        sum += t;
    }
    s[threadIdx.x] = sum;
    __syncthreads();
    for (int off = 1; off < 256; off <<= 1) {
        int t = (threadIdx.x >= off) ? s[threadIdx.x - off] : 0;
        __syncthreads();
        s[threadIdx.x] += t;
        __syncthreads();
    }
    int excl = s[threadIdx.x] - sum;
    if (threadIdx.x == 255) g_bsum[blockIdx.x] = s[255];
    #pragma unroll
    for (int j = 0; j < 8; j++) {
        int idx = base + j;
        if (idx < n) g_off[idx] = excl + v[j];
    }
}

__global__ void scan2_kernel(int nb) {
    if (threadIdx.x == 0) {
        int a = 0;
        for (int i = 0; i < nb; i++) { int t = g_bsum[i]; g_bsum[i] = a; a += t; }
    }
}

__global__ void scan3_kernel(int n) {
    int i = blockIdx.x * blockDim.x + threadIdx.x;
    if (i < n) {
        int o = g_off[i] + g_bsum[i >> 11];
        g_off[i] = o;
        g_cur[i] = o;
    }
}

__global__ void scatter_kernel(const int* __restrict__ src,
                               const int* __restrict__ dst,
                               const float* __restrict__ rij,
                               const float* __restrict__ vij, int E) {
    int e = blockIdx.x * blockDim.x + threadIdx.x;
    if (e >= E) return;
    float r = rij[e];
    if (r < CUT) {
        float c = 0.5f * (cosf(PI_F * r / CUT) + 1.0f);
        int p = atomicAdd(&g_cur[dst[e]], 1);
        g_cwv[p] = make_float4(c * vij[3 * e], c * vij[3 * e + 1],
                               c * vij[3 * e + 2], __int_as_float(src[e]));
    }
}

// ---------------- gather + cross + mix, one warp per node, lane = d --------
__global__ __launch_bounds__(256) void gather_kernel(
    const float* __restrict__ wmix, const float* __restrict__ bmix,
    float* __restrict__ out, int nNodes)
{
    int gw   = (blockIdx.x * 256 + threadIdx.x) >> 5;
    int lane = threadIdx.x & 31;
    if (gw >= nNodes) return;

    int start = g_off[gw];
    int m     = g_cnt[gw];

    float ax = 0.f, ay = 0.f, az = 0.f;
    float bx = 0.f, by = 0.f, bz = 0.f;

    int i = 0;
    for (; i + 2 <= m; i += 2) {
        float4 w0 = __ldg(&g_cwv[start + i]);
        float4 w1 = __ldg(&g_cwv[start + i + 1]);
        int s0 = __float_as_int(w0.w);
        int s1 = __float_as_int(w1.w);
        float qa = __ldg(&g_q [s0 * DDIM + lane]);
        float pa = __ldg(&g_q2[s0 * DDIM + lane]);
        float qb = __ldg(&g_q [s1 * DDIM + lane]);
        float pb = __ldg(&g_q2[s1 * DDIM + lane]);
        ax = fmaf(w0.x, qa, ax); ax = fmaf(w1.x, qb, ax);
        ay = fmaf(w0.y, qa, ay); ay = fmaf(w1.y, qb, ay);
        az = fmaf(w0.z, qa, az); az = fmaf(w1.z, qb, az);
        bx = fmaf(w0.x, pa, bx); bx = fmaf(w1.x, pb, bx);
        by = fmaf(w0.y, pa, by); by = fmaf(w1.y, pb, by);
        bz = fmaf(w0.z, pa, bz); bz = fmaf(w1.z, pb, bz);
    }
    if (i < m) {
        float4 w0 = __ldg(&g_cwv[start + i]);
        int s0 = __float_as_int(w0.w);
        float qa = __ldg(&g_q [s0 * DDIM + lane]);
        float pa = __ldg(&g_q2[s0 * DDIM + lane]);
        ax = fmaf(w0.x, qa, ax);
        ay = fmaf(w0.y, qa, ay);
        az = fmaf(w0.z, qa, az);
        bx = fmaf(w0.x, pa, bx);
        by = fmaf(w0.y, pa, by);
        bz = fmaf(w0.z, pa, bz);
    }

    float m0 = __ldg(wmix), m1 = __ldg(wmix + 1), m2 = __ldg(wmix + 2);
    float bm = __ldg(bmix);

    // cross(mu, mu2)
    float cx = ay * bz - az * by;
    float cy = az * bx - ax * bz;
    float cz = ax * by - ay * bx;

    size_t p = (size_t)gw * (DDIM * 3) + lane * 3;
    out[p + 0] = ax * m0 + bx * m1 + cx * m2 + bm;
    out[p + 1] = ay * m0 + by * m1 + cy * m2 + bm;
    out[p + 2] = az * m0 + bz * m1 + cz * m2 + bm;
}

// ---------------- launch ----------------
extern "C" void kernel_launch(void* const* d_in, const int* in_sizes, int n_in,
                              void* d_out, int out_size)
{
    const float* x    = (const float*)d_in[0];
    const float* rij  = (const float*)d_in[1];
    const float* vij  = (const float*)d_in[2];
    const int*   src  = (const int*)  d_in[3];
    const int*   dst  = (const int*)  d_in[4];
    const float* W1   = (const float*)d_in[5];
    const float* b1   = (const float*)d_in[6];
    const float* W2   = (const float*)d_in[7];
    const float* b2   = (const float*)d_in[8];
    const float* W1b  = (const float*)d_in[9];
    const float* b1b  = (const float*)d_in[10];
    const float* W2b  = (const float*)d_in[11];
    const float* b2b  = (const float*)d_in[12];
    const float* wmix = (const float*)d_in[13];
    const float* bmix = (const float*)d_in[14];
    float* out = (float*)d_out;

    int N = in_sizes[0] / FDIM;
    int E = in_sizes[1];
    if (N > NMAX) N = NMAX;
    if (E > EMAX) E = EMAX;

    const size_t smem_bytes = SMEM_F * sizeof(float);  // 149504
    cudaFuncSetAttribute(transform_kernel,
                         cudaFuncAttributeMaxDynamicSharedMemorySize,
                         (int)smem_bytes);

    dim3 gT((N + 127) / 128, 2);
    transform_kernel<<<gT, 256, smem_bytes>>>(x, W1, b1, W2, b2,
                                              W1b, b1b, W2b, b2b, N);

    int gE = (E + 255) / 256;
    int gN = (N + 255) / 256;
    int nb = (N + 2047) / 2048;

    zero_cnt_kernel<<<gN, 256>>>(N);
    count_kernel<<<gE, 256>>>(dst, rij, E);
    scan1_kernel<<<nb, 256>>>(N);
    scan2_kernel<<<1, 32>>>(nb);
    scan3_kernel<<<gN, 256>>>(N);
    scatter_kernel<<<gE, 256>>>(src, dst, rij, vij, E);

    int gG = (N * 32 + 255) / 256;
    gather_kernel<<<gG, 256>>>(wmix, bmix, out, N);
}

// round 6
// speedup vs baseline: 1.8497x; 1.4976x over previous
#include <cuda_runtime.h>
#include <cuda_bf16.h>
#include <cstdint>

#define NMAX   50000
#define EMAX   800000
#define FDIM   128
#define DDIM   32
#define CUT    5.0f
#define PI_F   3.14159265358979323846f

// ---------------- device scratch (static, allocation-free) ----------------
__device__ float  g_q [NMAX * DDIM];
__device__ float  g_q2[NMAX * DDIM];
__device__ int    g_cnt[NMAX];
__device__ int    g_off[NMAX];
__device__ int    g_cur[NMAX];
__device__ int    g_bsum[64];
__device__ float4 g_cwv[EMAX];

__device__ __forceinline__ float swish_f(float v) {
    return v * __fdividef(1.0f, 1.0f + __expf(-v));
}

// ---------------- warp-MMA helpers (baseline PTX, no arch-a features) -----
__device__ __forceinline__ uint32_t smem_u32(const void* p) {
    uint32_t a;
    asm("{ .reg .u64 t; cvta.to.shared.u64 t, %1; cvt.u32.u64 %0, t; }"
        : "=r"(a) : "l"(p));
    return a;
}
__device__ __forceinline__ void ldsm_x4(uint32_t* r, uint32_t addr) {
    asm volatile("ldmatrix.sync.aligned.m8n8.x4.shared.b16 {%0,%1,%2,%3}, [%4];"
                 : "=r"(r[0]), "=r"(r[1]), "=r"(r[2]), "=r"(r[3]) : "r"(addr));
}
__device__ __forceinline__ void ldsm_x4t(uint32_t* r, uint32_t addr) {
    asm volatile("ldmatrix.sync.aligned.m8n8.x4.trans.shared.b16 {%0,%1,%2,%3}, [%4];"
                 : "=r"(r[0]), "=r"(r[1]), "=r"(r[2]), "=r"(r[3]) : "r"(addr));
}
__device__ __forceinline__ void mma16816(float* c, const uint32_t* a,
                                         const uint32_t* b) {
    asm volatile(
        "mma.sync.aligned.m16n8k16.row.col.f32.bf16.bf16.f32 "
        "{%0,%1,%2,%3}, {%4,%5,%6,%7}, {%8,%9}, {%0,%1,%2,%3};"
        : "+f"(c[0]), "+f"(c[1]), "+f"(c[2]), "+f"(c[3])
        : "r"(a[0]), "r"(a[1]), "r"(a[2]), "r"(a[3]), "r"(b[0]), "r"(b[1]));
}
__device__ __forceinline__ uint32_t pack_bf(float a, float b) {
    __nv_bfloat16 ha = __float2bfloat16(a);
    __nv_bfloat16 hb = __float2bfloat16(b);
    return (uint32_t)__bfloat16_as_ushort(ha)
         | ((uint32_t)__bfloat16_as_ushort(hb) << 16);
}

// smem layout (bf16 arrays, padded strides for conflict-free ldmatrix)
#define LDA   136   // A / h tiles: [128][136]
#define LDB2  40    // W2 tile:     [128][40]
#define SA_HI  0
#define SA_LO  (SA_HI  + 128 * LDA * 2)   // 34816
#define SB1_HI (SA_LO  + 128 * LDA * 2)   // 69632
#define SB1_LO (SB1_HI + 128 * LDA * 2)   // 104448
#define SB2_HI (SB1_LO + 128 * LDA * 2)   // 139264
#define SB2_LO (SB2_HI + 128 * LDB2 * 2)  // 149504
#define SM_TOTAL (SB2_LO + 128 * LDB2 * 2) // 159744 bytes

// ============ node transform: mma.sync bf16x3 split ========================
__global__ __launch_bounds__(256, 1) void transform_kernel(
    const float* __restrict__ x,
    const float* __restrict__ W1a, const float* __restrict__ b1a,
    const float* __restrict__ W2a, const float* __restrict__ b2a,
    const float* __restrict__ W1b, const float* __restrict__ b1b,
    const float* __restrict__ W2b, const float* __restrict__ b2b,
    int nrows)
{
    extern __shared__ char smc[];
    const uint32_t sb = smem_u32(smc);

    const int branch = blockIdx.y;
    const float* W1 = branch ? W1b : W1a;
    const float* b1 = branch ? b1b : b1a;
    const float* W2 = branch ? W2b : W2a;
    const float* b2 = branch ? b2b : b2a;
    float* q_out = branch ? g_q2 : g_q;

    const int tid  = threadIdx.x;
    const int wid  = tid >> 5;
    const int lane = tid & 31;
    const int row0 = blockIdx.x * 128;

    // ---- convert W1 [k][n] -> sB1 hi/lo (no transpose needed) ----
    for (int i = tid; i < 4096; i += 256) {
        int k  = i >> 5;
        int c4 = (i & 31) << 2;
        float4 v = *reinterpret_cast<const float4*>(W1 + k * 128 + c4);
        float hx = __bfloat162float(__float2bfloat16(v.x));
        float hy = __bfloat162float(__float2bfloat16(v.y));
        float hz = __bfloat162float(__float2bfloat16(v.z));
        float hw = __bfloat162float(__float2bfloat16(v.w));
        uint32_t* hp = reinterpret_cast<uint32_t*>(smc + SB1_HI + (k * LDA + c4) * 2);
        uint32_t* lp = reinterpret_cast<uint32_t*>(smc + SB1_LO + (k * LDA + c4) * 2);
        hp[0] = pack_bf(v.x, v.y);           hp[1] = pack_bf(v.z, v.w);
        lp[0] = pack_bf(v.x - hx, v.y - hy); lp[1] = pack_bf(v.z - hz, v.w - hw);
    }
    // ---- convert W2 [k][n] -> sB2 hi/lo ----
    for (int i = tid; i < 1024; i += 256) {
        int k  = i >> 3;
        int c4 = (i & 7) << 2;
        float4 v = *reinterpret_cast<const float4*>(W2 + k * 32 + c4);
        float hx = __bfloat162float(__float2bfloat16(v.x));
        float hy = __bfloat162float(__float2bfloat16(v.y));
        float hz = __bfloat162float(__float2bfloat16(v.z));
        float hw = __bfloat162float(__float2bfloat16(v.w));
        uint32_t* hp = reinterpret_cast<uint32_t*>(smc + SB2_HI + (k * LDB2 + c4) * 2);
        uint32_t* lp = reinterpret_cast<uint32_t*>(smc + SB2_LO + (k * LDB2 + c4) * 2);
        hp[0] = pack_bf(v.x, v.y);           hp[1] = pack_bf(v.z, v.w);
        lp[0] = pack_bf(v.x - hx, v.y - hy); lp[1] = pack_bf(v.z - hz, v.w - hw);
    }
    // ---- convert x tile [r][k] -> sA hi/lo ----
    for (int i = tid; i < 4096; i += 256) {
        int r  = i >> 5;
        int c4 = (i & 31) << 2;
        int row = row0 + r;
        float4 v = make_float4(0.f, 0.f, 0.f, 0.f);
        if (row < nrows)
            v = *reinterpret_cast<const float4*>(x + (size_t)row * 128 + c4);
        float hx = __bfloat162float(__float2bfloat16(v.x));
        float hy = __bfloat162float(__float2bfloat16(v.y));
        float hz = __bfloat162float(__float2bfloat16(v.z));
        float hw = __bfloat162float(__float2bfloat16(v.w));
        uint32_t* hp = reinterpret_cast<uint32_t*>(smc + SA_HI + (r * LDA + c4) * 2);
        uint32_t* lp = reinterpret_cast<uint32_t*>(smc + SA_LO + (r * LDA + c4) * 2);
        hp[0] = pack_bf(v.x, v.y);           hp[1] = pack_bf(v.z, v.w);
        lp[0] = pack_bf(v.x - hx, v.y - hy); lp[1] = pack_bf(v.z - hz, v.w - hw);
    }
    __syncthreads();

    // ======== layer1: C[128][128] = x @ W1, warp tile 32 rows x 64 cols ====
    const int wm = (wid & 3) * 32;
    const int wn = (wid >> 2) * 64;
    float acc[2][8][4];
    #pragma unroll
    for (int mt = 0; mt < 2; mt++)
        #pragma unroll
        for (int nt = 0; nt < 8; nt++)
            #pragma unroll
            for (int r = 0; r < 4; r++) acc[mt][nt][r] = 0.f;

    const int arow = lane & 15, ac8 = (lane >> 4) << 3;   // ldmatrix lane addr
    #pragma unroll
    for (int ks = 0; ks < 8; ks++) {
        const int k0 = ks << 4;
        uint32_t aH[2][4], aL[2][4];
        #pragma unroll
        for (int mt = 0; mt < 2; mt++) {
            uint32_t off = ((wm + mt * 16 + arow) * LDA + k0 + ac8) * 2;
            ldsm_x4(aH[mt], sb + SA_HI + off);
            ldsm_x4(aL[mt], sb + SA_LO + off);
        }
        uint32_t bH[4][4], bL[4][4];
        #pragma unroll
        for (int g = 0; g < 4; g++) {   // each x4t covers n16 = 2 n-tiles
            uint32_t off = ((k0 + arow) * LDA + wn + g * 16 + ac8) * 2;
            ldsm_x4t(bH[g], sb + SB1_HI + off);
            ldsm_x4t(bL[g], sb + SB1_LO + off);
        }
        #pragma unroll
        for (int mt = 0; mt < 2; mt++)
            #pragma unroll
            for (int nt = 0; nt < 8; nt++) {
                const uint32_t* bh = &bH[nt >> 1][(nt & 1) * 2];
                const uint32_t* bl = &bL[nt >> 1][(nt & 1) * 2];
                mma16816(acc[mt][nt], aH[mt], bh);
                mma16816(acc[mt][nt], aH[mt], bl);
                mma16816(acc[mt][nt], aL[mt], bh);
            }
    }
    __syncthreads();   // all warps done reading sA before overwrite with h

    // ---- epilogue 1: h = swish(C + b1), split -> sA hi/lo ----
    {
        const int rbase = lane >> 2;
        const int cbase = (lane & 3) << 1;
        #pragma unroll
        for (int mt = 0; mt < 2; mt++)
            #pragma unroll
            for (int nt = 0; nt < 8; nt++) {
                int col = wn + nt * 8 + cbase;
                float g0 = __ldg(b1 + col), g1 = __ldg(b1 + col + 1);
                #pragma unroll
                for (int hh = 0; hh < 2; hh++) {
                    int row = wm + mt * 16 + rbase + hh * 8;
                    float v0 = swish_f(acc[mt][nt][2 * hh]     + g0);
                    float v1 = swish_f(acc[mt][nt][2 * hh + 1] + g1);
                    float h0 = __bfloat162float(__float2bfloat16(v0));
                    float h1 = __bfloat162float(__float2bfloat16(v1));
                    uint32_t o = (row * LDA + col) * 2;
                    *reinterpret_cast<uint32_t*>(smc + SA_HI + o) = pack_bf(v0, v1);
                    *reinterpret_cast<uint32_t*>(smc + SA_LO + o) =
                        pack_bf(v0 - h0, v1 - h1);
                }
            }
    }
    __syncthreads();

    // ======== layer2: q[128][32] = h @ W2, warp tile 16 rows x 32 cols =====
    const int m0 = wid << 4;
    float acc2[4][4];
    #pragma unroll
    for (int nt = 0; nt < 4; nt++)
        #pragma unroll
        for (int r = 0; r < 4; r++) acc2[nt][r] = 0.f;

    #pragma unroll
    for (int ks = 0; ks < 8; ks++) {
        const int k0 = ks << 4;
        uint32_t aH[4], aL[4];
        uint32_t offa = ((m0 + arow) * LDA + k0 + ac8) * 2;
        ldsm_x4(aH, sb + SA_HI + offa);
        ldsm_x4(aL, sb + SA_LO + offa);
        uint32_t bH[2][4], bL[2][4];
        #pragma unroll
        for (int g = 0; g < 2; g++) {
            uint32_t off = ((k0 + arow) * LDB2 + g * 16 + ac8) * 2;
            ldsm_x4t(bH[g], sb + SB2_HI + off);
            ldsm_x4t(bL[g], sb + SB2_LO + off);
        }
        #pragma unroll
        for (int nt = 0; nt < 4; nt++) {
            const uint32_t* bh = &bH[nt >> 1][(nt & 1) * 2];
            const uint32_t* bl = &bL[nt >> 1][(nt & 1) * 2];
            mma16816(acc2[nt], aH, bh);
            mma16816(acc2[nt], aH, bl);
            mma16816(acc2[nt], aL, bh);
        }
    }

    // ---- epilogue 2: q = swish(C2 + b2) -> gmem ----
    {
        const int rbase = lane >> 2;
        const int cbase = (lane & 3) << 1;
        #pragma unroll
        for (int nt = 0; nt < 4; nt++) {
            int col = nt * 8 + cbase;
            float g0 = __ldg(b2 + col), g1 = __ldg(b2 + col + 1);
            #pragma unroll
            for (int hh = 0; hh < 2; hh++) {
                int row = row0 + m0 + rbase + hh * 8;
                if (row < nrows) {
                    float* qp = q_out + (size_t)row * DDIM + col;
                    qp[0] = swish_f(acc2[nt][2 * hh]     + g0);
                    qp[1] = swish_f(acc2[nt][2 * hh + 1] + g1);
                }
            }
        }
    }
}

// ---------------- CSR build ----------------
__global__ void zero_cnt_kernel(int n) {
    int i = blockIdx.x * blockDim.x + threadIdx.x;
    if (i < n) g_cnt[i] = 0;
}

__global__ void count_kernel(const int* __restrict__ dst,
                             const float* __restrict__ rij, int E) {
    int e = blockIdx.x * blockDim.x + threadIdx.x;
    if (e < E && rij[e] < CUT) atomicAdd(&g_cnt[dst[e]], 1);
}

__global__ void scan1_kernel(int n) {
    __shared__ int s[256];
    int base = blockIdx.x * 2048 + threadIdx.x * 8;
    int v[8];
    int sum = 0;
    #pragma unroll
    for (int j = 0; j < 8; j++) {
        int idx = base + j;
        int t = (idx < n) ? g_cnt[idx] : 0;
        v[j] = sum;
        sum += t;
    }
    s[threadIdx.x] = sum;
    __syncthreads();
    for (int off = 1; off < 256; off <<= 1) {
        int t = (threadIdx.x >= off) ? s[threadIdx.x - off] : 0;
        __syncthreads();
        s[threadIdx.x] += t;
        __syncthreads();
    }
    int excl = s[threadIdx.x] - sum;
    if (threadIdx.x == 255) g_bsum[blockIdx.x] = s[255];
    #pragma unroll
    for (int j = 0; j < 8; j++) {
        int idx = base + j;
        if (idx < n) g_off[idx] = excl + v[j];
    }
}

__global__ void scan2_kernel(int nb) {
    if (threadIdx.x == 0) {
        int a = 0;
        for (int i = 0; i < nb; i++) { int t = g_bsum[i]; g_bsum[i] = a; a += t; }
    }
}

__global__ void scan3_kernel(int n) {
    int i = blockIdx.x * blockDim.x + threadIdx.x;
    if (i < n) {
        int o = g_off[i] + g_bsum[i >> 11];
        g_off[i] = o;
        g_cur[i] = o;
    }
}

__global__ void scatter_kernel(const int* __restrict__ src,
                               const int* __restrict__ dst,
                               const float* __restrict__ rij,
                               const float* __restrict__ vij, int E) {
    int e = blockIdx.x * blockDim.x + threadIdx.x;
    if (e >= E) return;
    float r = rij[e];
    if (r < CUT) {
        float c = 0.5f * (cosf(PI_F * r / CUT) + 1.0f);
        int p = atomicAdd(&g_cur[dst[e]], 1);
        g_cwv[p] = make_float4(c * vij[3 * e], c * vij[3 * e + 1],
                               c * vij[3 * e + 2], __int_as_float(src[e]));
    }
}

// ---------------- gather + cross + mix, one warp per node, lane = d --------
__global__ __launch_bounds__(256) void gather_kernel(
    const float* __restrict__ wmix, const float* __restrict__ bmix,
    float* __restrict__ out, int nNodes)
{
    int gw   = (blockIdx.x * 256 + threadIdx.x) >> 5;
    int lane = threadIdx.x & 31;
    if (gw >= nNodes) return;

    int start = g_off[gw];
    int m     = g_cnt[gw];

    float ax = 0.f, ay = 0.f, az = 0.f;
    float bx = 0.f, by = 0.f, bz = 0.f;

    int i = 0;
    for (; i + 2 <= m; i += 2) {
        float4 w0 = __ldg(&g_cwv[start + i]);
        float4 w1 = __ldg(&g_cwv[start + i + 1]);
        int s0 = __float_as_int(w0.w);
        int s1 = __float_as_int(w1.w);
        float qa = __ldg(&g_q [s0 * DDIM + lane]);
        float pa = __ldg(&g_q2[s0 * DDIM + lane]);
        float qb = __ldg(&g_q [s1 * DDIM + lane]);
        float pb = __ldg(&g_q2[s1 * DDIM + lane]);
        ax = fmaf(w0.x, qa, ax); ax = fmaf(w1.x, qb, ax);
        ay = fmaf(w0.y, qa, ay); ay = fmaf(w1.y, qb, ay);
        az = fmaf(w0.z, qa, az); az = fmaf(w1.z, qb, az);
        bx = fmaf(w0.x, pa, bx); bx = fmaf(w1.x, pb, bx);
        by = fmaf(w0.y, pa, by); by = fmaf(w1.y, pb, by);
        bz = fmaf(w0.z, pa, bz); bz = fmaf(w1.z, pb, bz);
    }
    if (i < m) {
        float4 w0 = __ldg(&g_cwv[start + i]);
        int s0 = __float_as_int(w0.w);
        float qa = __ldg(&g_q [s0 * DDIM + lane]);
        float pa = __ldg(&g_q2[s0 * DDIM + lane]);
        ax = fmaf(w0.x, qa, ax);
        ay = fmaf(w0.y, qa, ay);
        az = fmaf(w0.z, qa, az);
        bx = fmaf(w0.x, pa, bx);
        by = fmaf(w0.y, pa, by);
        bz = fmaf(w0.z, pa, bz);
    }

    float m0 = __ldg(wmix), m1 = __ldg(wmix + 1), m2 = __ldg(wmix + 2);
    float bm = __ldg(bmix);

    float cx = ay * bz - az * by;
    float cy = az * bx - ax * bz;
    float cz = ax * by - ay * bx;

    size_t p = (size_t)gw * (DDIM * 3) + lane * 3;
    out[p + 0] = ax * m0 + bx * m1 + cx * m2 + bm;
    out[p + 1] = ay * m0 + by * m1 + cy * m2 + bm;
    out[p + 2] = az * m0 + bz * m1 + cz * m2 + bm;
}

// ---------------- launch ----------------
extern "C" void kernel_launch(void* const* d_in, const int* in_sizes, int n_in,
                              void* d_out, int out_size)
{
    const float* x    = (const float*)d_in[0];
    const float* rij  = (const float*)d_in[1];
    const float* vij  = (const float*)d_in[2];
    const int*   src  = (const int*)  d_in[3];
    const int*   dst  = (const int*)  d_in[4];
    const float* W1   = (const float*)d_in[5];
    const float* b1   = (const float*)d_in[6];
    const float* W2   = (const float*)d_in[7];
    const float* b2   = (const float*)d_in[8];
    const float* W1b  = (const float*)d_in[9];
    const float* b1b  = (const float*)d_in[10];
    const float* W2b  = (const float*)d_in[11];
    const float* b2b  = (const float*)d_in[12];
    const float* wmix = (const float*)d_in[13];
    const float* bmix = (const float*)d_in[14];
    float* out = (float*)d_out;

    int N = in_sizes[0] / FDIM;
    int E = in_sizes[1];
    if (N > NMAX) N = NMAX;
    if (E > EMAX) E = EMAX;

    cudaFuncSetAttribute(transform_kernel,
                         cudaFuncAttributeMaxDynamicSharedMemorySize, SM_TOTAL);

    dim3 gT((N + 127) / 128, 2);
    transform_kernel<<<gT, 256, SM_TOTAL>>>(x, W1, b1, W2, b2,
                                            W1b, b1b, W2b, b2b, N);

    int gE = (E + 255) / 256;
    int gN = (N + 255) / 256;
    int nb = (N + 2047) / 2048;

    zero_cnt_kernel<<<gN, 256>>>(N);
    count_kernel<<<gE, 256>>>(dst, rij, E);
    scan1_kernel<<<nb, 256>>>(N);
    scan2_kernel<<<1, 32>>>(nb);
    scan3_kernel<<<gN, 256>>>(N);
    scatter_kernel<<<gE, 256>>>(src, dst, rij, vij, E);

    int gG = (N * 32 + 255) / 256;
    gather_kernel<<<gG, 256>>>(wmix, bmix, out, N);
}

// round 7
// speedup vs baseline: 2.3156x; 1.2519x over previous
#include <cuda_runtime.h>
#include <cuda_bf16.h>
#include <cstdint>

#define NMAX   50000
#define EMAX   800000
#define FDIM   128
#define DDIM   32
#define CUT    5.0f
#define PI_F   3.14159265358979323846f

// ---------------- device scratch (static, allocation-free) ----------------
__device__ float  g_q [NMAX * DDIM];
__device__ float  g_q2[NMAX * DDIM];
__device__ int    g_cnt[NMAX];
__device__ int    g_off[NMAX];
__device__ int    g_cur[NMAX];
__device__ int    g_bsum[64];
__device__ float4 g_cwv[EMAX];
// pre-split bf16 operands: [part 0=hi 1=lo]
__device__ __nv_bfloat16 g_xsp [2][NMAX * FDIM];
__device__ __nv_bfloat16 g_w1sp[2][2][FDIM * FDIM];   // [branch][part]
__device__ __nv_bfloat16 g_w2sp[2][2][FDIM * DDIM];

__device__ __forceinline__ float swish_f(float v) {
    return v * __fdividef(1.0f, 1.0f + __expf(-v));
}

// ---------------- helpers (baseline PTX only) -----------------------------
__device__ __forceinline__ uint32_t smem_u32(const void* p) {
    uint32_t a;
    asm("{ .reg .u64 t; cvta.to.shared.u64 t, %1; cvt.u32.u64 %0, t; }"
        : "=r"(a) : "l"(p));
    return a;
}
__device__ __forceinline__ void ldsm_x4(uint32_t* r, uint32_t addr) {
    asm volatile("ldmatrix.sync.aligned.m8n8.x4.shared.b16 {%0,%1,%2,%3}, [%4];"
                 : "=r"(r[0]), "=r"(r[1]), "=r"(r[2]), "=r"(r[3]) : "r"(addr));
}
__device__ __forceinline__ void ldsm_x4t(uint32_t* r, uint32_t addr) {
    asm volatile("ldmatrix.sync.aligned.m8n8.x4.trans.shared.b16 {%0,%1,%2,%3}, [%4];"
                 : "=r"(r[0]), "=r"(r[1]), "=r"(r[2]), "=r"(r[3]) : "r"(addr));
}
__device__ __forceinline__ void mma16816(float* c, const uint32_t* a,
                                         const uint32_t* b) {
    asm volatile(
        "mma.sync.aligned.m16n8k16.row.col.f32.bf16.bf16.f32 "
        "{%0,%1,%2,%3}, {%4,%5,%6,%7}, {%8,%9}, {%0,%1,%2,%3};"
        : "+f"(c[0]), "+f"(c[1]), "+f"(c[2]), "+f"(c[3])
        : "r"(a[0]), "r"(a[1]), "r"(a[2]), "r"(a[3]), "r"(b[0]), "r"(b[1]));
}
__device__ __forceinline__ uint32_t pack_bf(float a, float b) {
    __nv_bfloat16 ha = __float2bfloat16(a);
    __nv_bfloat16 hb = __float2bfloat16(b);
    return (uint32_t)__bfloat16_as_ushort(ha)
         | ((uint32_t)__bfloat16_as_ushort(hb) << 16);
}
// cp.async 16B with zfill (src_size in bytes; 0 -> all zeros)
__device__ __forceinline__ void cpa16(uint32_t d, const void* s, int sz) {
    asm volatile("cp.async.cg.shared.global [%0], [%1], 16, %2;"
                 :: "r"(d), "l"(s), "r"(sz) : "memory");
}
__device__ __forceinline__ void cpa_commit_wait() {
    asm volatile("cp.async.commit_group;" ::: "memory");
    asm volatile("cp.async.wait_group 0;" ::: "memory");
}

// split one float -> bf16 hi/lo pair
__device__ __forceinline__ void split_bf(float v, __nv_bfloat16& h, __nv_bfloat16& l) {
    h = __float2bfloat16(v);
    l = __float2bfloat16(v - __bfloat162float(h));
}

// ---------------- prep kernels --------------------------------------------
__global__ void prep_x_kernel(const float* __restrict__ x, int n4) {
    int i = blockIdx.x * blockDim.x + threadIdx.x;
    if (i >= n4) return;
    float4 v = *reinterpret_cast<const float4*>(x + 4 * (size_t)i);
    __nv_bfloat16 h[4], l[4];
    split_bf(v.x, h[0], l[0]); split_bf(v.y, h[1], l[1]);
    split_bf(v.z, h[2], l[2]); split_bf(v.w, h[3], l[3]);
    *reinterpret_cast<uint2*>(&g_xsp[0][4 * (size_t)i]) =
        make_uint2(pack_bf(v.x, v.y), pack_bf(v.z, v.w));
    float lx = __bfloat162float(l[0]), ly = __bfloat162float(l[1]);
    float lz = __bfloat162float(l[2]), lw = __bfloat162float(l[3]);
    *reinterpret_cast<uint2*>(&g_xsp[1][4 * (size_t)i]) =
        make_uint2(pack_bf(lx, ly), pack_bf(lz, lw));
}

__global__ void prep_w_kernel(const float* __restrict__ W1a,
                              const float* __restrict__ W1b,
                              const float* __restrict__ W2a,
                              const float* __restrict__ W2b) {
    int i = blockIdx.x * blockDim.x + threadIdx.x;   // float4 index
    const float* srcs[4] = {W1a, W1b, W2a, W2b};
    int which, local;
    if (i < 8192)       { which = i >> 12;       local = i & 4095; }       // W1a/W1b
    else if (i < 10240) { which = 2 + ((i - 8192) >> 10); local = (i - 8192) & 1023; }
    else return;
    float4 v = *reinterpret_cast<const float4*>(srcs[which] + 4 * local);
    __nv_bfloat16 h[4], l[4];
    split_bf(v.x, h[0], l[0]); split_bf(v.y, h[1], l[1]);
    split_bf(v.z, h[2], l[2]); split_bf(v.w, h[3], l[3]);
    uint2 hv = make_uint2(pack_bf(v.x, v.y), pack_bf(v.z, v.w));
    uint2 lv = make_uint2(
        pack_bf(__bfloat162float(l[0]), __bfloat162float(l[1])),
        pack_bf(__bfloat162float(l[2]), __bfloat162float(l[3])));
    if (which < 2) {
        *reinterpret_cast<uint2*>(&g_w1sp[which][0][4 * local]) = hv;
        *reinterpret_cast<uint2*>(&g_w1sp[which][1][4 * local]) = lv;
    } else {
        *reinterpret_cast<uint2*>(&g_w2sp[which - 2][0][4 * local]) = hv;
        *reinterpret_cast<uint2*>(&g_w2sp[which - 2][1][4 * local]) = lv;
    }
}

// smem layout (bf16, padded strides for conflict-free ldmatrix)
#define LDA   136
#define LDB2  40
#define SA_HI  0
#define SA_LO  (SA_HI  + 128 * LDA * 2)
#define SB1_HI (SA_LO  + 128 * LDA * 2)
#define SB1_LO (SB1_HI + 128 * LDA * 2)
#define SB2_HI (SB1_LO + 128 * LDA * 2)
#define SB2_LO (SB2_HI + 128 * LDB2 * 2)
#define SM_TOTAL (SB2_LO + 128 * LDB2 * 2)   // 159744 bytes

// ============ node transform: mma.sync bf16x3, cp.async preamble ==========
__global__ __launch_bounds__(256, 1) void transform_kernel(
    const float* __restrict__ b1a, const float* __restrict__ b2a,
    const float* __restrict__ b1b, const float* __restrict__ b2b,
    int nrows)
{
    extern __shared__ char smc[];
    const uint32_t sb = smem_u32(smc);

    const int branch = blockIdx.y;
    const float* b1 = branch ? b1b : b1a;
    const float* b2 = branch ? b2b : b2a;
    float* q_out = branch ? g_q2 : g_q;

    const int tid  = threadIdx.x;
    const int wid  = tid >> 5;
    const int lane = tid & 31;
    const int row0 = blockIdx.x * 128;

    // ---- async load pre-split tiles ----
    for (int i = tid; i < 2048; i += 256) {           // A: 128 rows x 16 chunks
        int r = i >> 4, ch = (i & 15) << 3;
        int row = row0 + r;
        int rc = row < nrows ? row : (nrows - 1);
        int sz = row < nrows ? 16 : 0;
        cpa16(sb + SA_HI + (r * LDA + ch) * 2, &g_xsp[0][(size_t)rc * 128 + ch], sz);
        cpa16(sb + SA_LO + (r * LDA + ch) * 2, &g_xsp[1][(size_t)rc * 128 + ch], sz);
    }
    for (int i = tid; i < 2048; i += 256) {           // B1: 128 rows x 16 chunks
        int k = i >> 4, ch = (i & 15) << 3;
        cpa16(sb + SB1_HI + (k * LDA + ch) * 2, &g_w1sp[branch][0][k * 128 + ch], 16);
        cpa16(sb + SB1_LO + (k * LDA + ch) * 2, &g_w1sp[branch][1][k * 128 + ch], 16);
    }
    for (int i = tid; i < 512; i += 256) {            // B2: 128 rows x 4 chunks
        int k = i >> 2, ch = (i & 3) << 3;
        cpa16(sb + SB2_HI + (k * LDB2 + ch) * 2, &g_w2sp[branch][0][k * 32 + ch], 16);
        cpa16(sb + SB2_LO + (k * LDB2 + ch) * 2, &g_w2sp[branch][1][k * 32 + ch], 16);
    }
    cpa_commit_wait();
    __syncthreads();

    // ======== layer1: C[128][128] = x @ W1, warp tile 32 rows x 64 cols ====
    const int wm = (wid & 3) * 32;
    const int wn = (wid >> 2) * 64;
    float acc[2][8][4];
    #pragma unroll
    for (int mt = 0; mt < 2; mt++)
        #pragma unroll
        for (int nt = 0; nt < 8; nt++)
            #pragma unroll
            for (int r = 0; r < 4; r++) acc[mt][nt][r] = 0.f;

    const int arow = lane & 15, ac8 = (lane >> 4) << 3;
    #pragma unroll
    for (int ks = 0; ks < 8; ks++) {
        const int k0 = ks << 4;
        uint32_t aH[2][4], aL[2][4];
        #pragma unroll
        for (int mt = 0; mt < 2; mt++) {
            uint32_t off = ((wm + mt * 16 + arow) * LDA + k0 + ac8) * 2;
            ldsm_x4(aH[mt], sb + SA_HI + off);
            ldsm_x4(aL[mt], sb + SA_LO + off);
        }
        uint32_t bH[4][4], bL[4][4];
        #pragma unroll
        for (int g = 0; g < 4; g++) {
            uint32_t off = ((k0 + arow) * LDA + wn + g * 16 + ac8) * 2;
            ldsm_x4t(bH[g], sb + SB1_HI + off);
            ldsm_x4t(bL[g], sb + SB1_LO + off);
        }
        #pragma unroll
        for (int mt = 0; mt < 2; mt++)
            #pragma unroll
            for (int nt = 0; nt < 8; nt++) {
                const uint32_t* bh = &bH[nt >> 1][(nt & 1) * 2];
                const uint32_t* bl = &bL[nt >> 1][(nt & 1) * 2];
                mma16816(acc[mt][nt], aH[mt], bh);
                mma16816(acc[mt][nt], aH[mt], bl);
                mma16816(acc[mt][nt], aL[mt], bh);
            }
    }
    __syncthreads();

    // ---- epilogue 1: h = swish(C + b1), split -> sA hi/lo ----
    {
        const int rbase = lane >> 2;
        const int cbase = (lane & 3) << 1;
        #pragma unroll
        for (int mt = 0; mt < 2; mt++)
            #pragma unroll
            for (int nt = 0; nt < 8; nt++) {
                int col = wn + nt * 8 + cbase;
                float g0 = __ldg(b1 + col), g1 = __ldg(b1 + col + 1);
                #pragma unroll
                for (int hh = 0; hh < 2; hh++) {
                    int row = wm + mt * 16 + rbase + hh * 8;
                    float v0 = swish_f(acc[mt][nt][2 * hh]     + g0);
                    float v1 = swish_f(acc[mt][nt][2 * hh + 1] + g1);
                    float h0 = __bfloat162float(__float2bfloat16(v0));
                    float h1 = __bfloat162float(__float2bfloat16(v1));
                    uint32_t o = (row * LDA + col) * 2;
                    *reinterpret_cast<uint32_t*>(smc + SA_HI + o) = pack_bf(v0, v1);
                    *reinterpret_cast<uint32_t*>(smc + SA_LO + o) =
                        pack_bf(v0 - h0, v1 - h1);
                }
            }
    }
    __syncthreads();

    // ======== layer2: q[128][32] = h @ W2, warp tile 16 rows x 32 cols =====
    const int m0 = wid << 4;
    float acc2[4][4];
    #pragma unroll
    for (int nt = 0; nt < 4; nt++)
        #pragma unroll
        for (int r = 0; r < 4; r++) acc2[nt][r] = 0.f;

    #pragma unroll
    for (int ks = 0; ks < 8; ks++) {
        const int k0 = ks << 4;
        uint32_t aH[4], aL[4];
        uint32_t offa = ((m0 + arow) * LDA + k0 + ac8) * 2;
        ldsm_x4(aH, sb + SA_HI + offa);
        ldsm_x4(aL, sb + SA_LO + offa);
        uint32_t bH[2][4], bL[2][4];
        #pragma unroll
        for (int g = 0; g < 2; g++) {
            uint32_t off = ((k0 + arow) * LDB2 + g * 16 + ac8) * 2;
            ldsm_x4t(bH[g], sb + SB2_HI + off);
            ldsm_x4t(bL[g], sb + SB2_LO + off);
        }
        #pragma unroll
        for (int nt = 0; nt < 4; nt++) {
            const uint32_t* bh = &bH[nt >> 1][(nt & 1) * 2];
            const uint32_t* bl = &bL[nt >> 1][(nt & 1) * 2];
            mma16816(acc2[nt], aH, bh);
            mma16816(acc2[nt], aH, bl);
            mma16816(acc2[nt], aL, bh);
        }
    }

    // ---- epilogue 2: q = swish(C2 + b2) -> gmem ----
    {
        const int rbase = lane >> 2;
        const int cbase = (lane & 3) << 1;
        #pragma unroll
        for (int nt = 0; nt < 4; nt++) {
            int col = nt * 8 + cbase;
            float g0 = __ldg(b2 + col), g1 = __ldg(b2 + col + 1);
            #pragma unroll
            for (int hh = 0; hh < 2; hh++) {
                int row = row0 + m0 + rbase + hh * 8;
                if (row < nrows) {
                    float* qp = q_out + (size_t)row * DDIM + col;
                    qp[0] = swish_f(acc2[nt][2 * hh]     + g0);
                    qp[1] = swish_f(acc2[nt][2 * hh + 1] + g1);
                }
            }
        }
    }
}

// ---------------- CSR build ----------------
__global__ void zero_cnt_kernel(int n) {
    int i = blockIdx.x * blockDim.x + threadIdx.x;
    if (i < n) g_cnt[i] = 0;
}

__global__ void count_kernel(const int* __restrict__ dst,
                             const float* __restrict__ rij, int E) {
    int e = (blockIdx.x * blockDim.x + threadIdx.x) * 2;
    if (e + 1 < E) {
        float2 r2 = *reinterpret_cast<const float2*>(rij + e);
        int2   d2 = *reinterpret_cast<const int2*>(dst + e);
        if (r2.x < CUT) atomicAdd(&g_cnt[d2.x], 1);
        if (r2.y < CUT) atomicAdd(&g_cnt[d2.y], 1);
    } else if (e < E) {
        if (rij[e] < CUT) atomicAdd(&g_cnt[dst[e]], 1);
    }
}

__global__ void scan1_kernel(int n) {
    __shared__ int s[256];
    int base = blockIdx.x * 2048 + threadIdx.x * 8;
    int v[8];
    int sum = 0;
    #pragma unroll
    for (int j = 0; j < 8; j++) {
        int idx = base + j;
        int t = (idx < n) ? g_cnt[idx] : 0;
        v[j] = sum;
        sum += t;
    }
    s[threadIdx.x] = sum;
    __syncthreads();
    for (int off = 1; off < 256; off <<= 1) {
        int t = (threadIdx.x >= off) ? s[threadIdx.x - off] : 0;
        __syncthreads();
        s[threadIdx.x] += t;
        __syncthreads();
    }
    int excl = s[threadIdx.x] - sum;
    if (threadIdx.x == 255) g_bsum[blockIdx.x] = s[255];
    #pragma unroll
    for (int j = 0; j < 8; j++) {
        int idx = base + j;
        if (idx < n) g_off[idx] = excl + v[j];
    }
}

__global__ void scan2_kernel(int nb) {
    if (threadIdx.x == 0) {
        int a = 0;
        for (int i = 0; i < nb; i++) { int t = g_bsum[i]; g_bsum[i] = a; a += t; }
    }
}

__global__ void scan3_kernel(int n) {
    int i = blockIdx.x * blockDim.x + threadIdx.x;
    if (i < n) {
        int o = g_off[i] + g_bsum[i >> 11];
        g_off[i] = o;
        g_cur[i] = o;
    }
}

__global__ void scatter_kernel(const int* __restrict__ src,
                               const int* __restrict__ dst,
                               const float* __restrict__ rij,
                               const float* __restrict__ vij, int E) {
    int e = blockIdx.x * blockDim.x + threadIdx.x;
    if (e >= E) return;
    float r = rij[e];
    if (r < CUT) {
        float c = 0.5f * (cosf(PI_F * r / CUT) + 1.0f);
        int p = atomicAdd(&g_cur[dst[e]], 1);
        g_cwv[p] = make_float4(c * vij[3 * e], c * vij[3 * e + 1],
                               c * vij[3 * e + 2], __int_as_float(src[e]));
    }
}

// ---------------- gather + cross + mix, one warp per node, lane = d --------
__global__ __launch_bounds__(256) void gather_kernel(
    const float* __restrict__ wmix, const float* __restrict__ bmix,
    float* __restrict__ out, int nNodes)
{
    int gw   = (blockIdx.x * 256 + threadIdx.x) >> 5;
    int lane = threadIdx.x & 31;
    if (gw >= nNodes) return;

    int start = g_off[gw];
    int m     = g_cnt[gw];

    float ax = 0.f, ay = 0.f, az = 0.f;
    float bx = 0.f, by = 0.f, bz = 0.f;

    int i = 0;
    for (; i + 2 <= m; i += 2) {
        float4 w0 = __ldg(&g_cwv[start + i]);
        float4 w1 = __ldg(&g_cwv[start + i + 1]);
        int s0 = __float_as_int(w0.w);
        int s1 = __float_as_int(w1.w);
        float qa = __ldg(&g_q [s0 * DDIM + lane]);
        float pa = __ldg(&g_q2[s0 * DDIM + lane]);
        float qb = __ldg(&g_q [s1 * DDIM + lane]);
        float pb = __ldg(&g_q2[s1 * DDIM + lane]);
        ax = fmaf(w0.x, qa, ax); ax = fmaf(w1.x, qb, ax);
        ay = fmaf(w0.y, qa, ay); ay = fmaf(w1.y, qb, ay);
        az = fmaf(w0.z, qa, az); az = fmaf(w1.z, qb, az);
        bx = fmaf(w0.x, pa, bx); bx = fmaf(w1.x, pb, bx);
        by = fmaf(w0.y, pa, by); by = fmaf(w1.y, pb, by);
        bz = fmaf(w0.z, pa, bz); bz = fmaf(w1.z, pb, bz);
    }
    if (i < m) {
        float4 w0 = __ldg(&g_cwv[start + i]);
        int s0 = __float_as_int(w0.w);
        float qa = __ldg(&g_q [s0 * DDIM + lane]);
        float pa = __ldg(&g_q2[s0 * DDIM + lane]);
        ax = fmaf(w0.x, qa, ax);
        ay = fmaf(w0.y, qa, ay);
        az = fmaf(w0.z, qa, az);
        bx = fmaf(w0.x, pa, bx);
        by = fmaf(w0.y, pa, by);
        bz = fmaf(w0.z, pa, bz);
    }

    float m0 = __ldg(wmix), m1 = __ldg(wmix + 1), m2 = __ldg(wmix + 2);
    float bm = __ldg(bmix);

    float cx = ay * bz - az * by;
    float cy = az * bx - ax * bz;
    float cz = ax * by - ay * bx;

    size_t p = (size_t)gw * (DDIM * 3) + lane * 3;
    out[p + 0] = ax * m0 + bx * m1 + cx * m2 + bm;
    out[p + 1] = ay * m0 + by * m1 + cy * m2 + bm;
    out[p + 2] = az * m0 + bz * m1 + cz * m2 + bm;
}

// ---------------- launch ----------------
extern "C" void kernel_launch(void* const* d_in, const int* in_sizes, int n_in,
                              void* d_out, int out_size)
{
    const float* x    = (const float*)d_in[0];
    const float* rij  = (const float*)d_in[1];
    const float* vij  = (const float*)d_in[2];
    const int*   src  = (const int*)  d_in[3];
    const int*   dst  = (const int*)  d_in[4];
    const float* W1   = (const float*)d_in[5];
    const float* b1   = (const float*)d_in[6];
    const float* W2   = (const float*)d_in[7];
    const float* b2   = (const float*)d_in[8];
    const float* W1b  = (const float*)d_in[9];
    const float* b1b  = (const float*)d_in[10];
    const float* W2b  = (const float*)d_in[11];
    const float* b2b  = (const float*)d_in[12];
    const float* wmix = (const float*)d_in[13];
    const float* bmix = (const float*)d_in[14];
    float* out = (float*)d_out;

    int N = in_sizes[0] / FDIM;
    int E = in_sizes[1];
    if (N > NMAX) N = NMAX;
    if (E > EMAX) E = EMAX;

    cudaFuncSetAttribute(transform_kernel,
                         cudaFuncAttributeMaxDynamicSharedMemorySize, SM_TOTAL);

    // prep: split weights + x into bf16 hi/lo
    prep_w_kernel<<<40, 256>>>(W1, W1b, W2, W2b);
    int n4 = N * FDIM / 4;
    prep_x_kernel<<<(n4 + 255) / 256, 256>>>(x, n4);

    dim3 gT((N + 127) / 128, 2);
    transform_kernel<<<gT, 256, SM_TOTAL>>>(b1, b2, b1b, b2b, N);

    int gE = (E + 255) / 256;
    int gN = (N + 255) / 256;
    int nb = (N + 2047) / 2048;

    zero_cnt_kernel<<<gN, 256>>>(N);
    count_kernel<<<(E / 2 + 255) / 256, 256>>>(dst, rij, E);
    scan1_kernel<<<nb, 256>>>(N);
    scan2_kernel<<<1, 32>>>(nb);
    scan3_kernel<<<gN, 256>>>(N);
    scatter_kernel<<<gE, 256>>>(src, dst, rij, vij, E);

    int gG = (N * 32 + 255) / 256;
    gather_kernel<<<gG, 256>>>(wmix, bmix, out, N);
}

// round 8
// speedup vs baseline: 2.6171x; 1.1302x over previous
#include <cuda_runtime.h>
#include <cuda_bf16.h>
#include <cstdint>

#define NMAX   50000
#define EMAX   800000
#define FDIM   128
#define DDIM   32
#define CUT    5.0f
#define PI_F   3.14159265358979323846f

// ---------------- device scratch (static, allocation-free) ----------------
__device__ float  g_q [NMAX * DDIM];
__device__ float  g_q2[NMAX * DDIM];
__device__ int    g_cnt[NMAX];
__device__ int    g_off[NMAX];
__device__ int    g_cur[NMAX];
__device__ int    g_bsum[64];
__device__ float4 g_cwv[EMAX];
// pre-split bf16 operands: [part 0=hi 1=lo]
__device__ __nv_bfloat16 g_xsp [2][NMAX * FDIM];
__device__ __nv_bfloat16 g_w1sp[2][2][FDIM * FDIM];   // [branch][part]
__device__ __nv_bfloat16 g_w2sp[2][2][FDIM * DDIM];

__device__ __forceinline__ float swish_f(float v) {
    return v * __fdividef(1.0f, 1.0f + __expf(-v));
}

// ---------------- helpers (baseline PTX only) -----------------------------
__device__ __forceinline__ uint32_t smem_u32(const void* p) {
    uint32_t a;
    asm("{ .reg .u64 t; cvta.to.shared.u64 t, %1; cvt.u32.u64 %0, t; }"
        : "=r"(a) : "l"(p));
    return a;
}
__device__ __forceinline__ void ldsm_x4(uint32_t* r, uint32_t addr) {
    asm volatile("ldmatrix.sync.aligned.m8n8.x4.shared.b16 {%0,%1,%2,%3}, [%4];"
                 : "=r"(r[0]), "=r"(r[1]), "=r"(r[2]), "=r"(r[3]) : "r"(addr));
}
__device__ __forceinline__ void ldsm_x4t(uint32_t* r, uint32_t addr) {
    asm volatile("ldmatrix.sync.aligned.m8n8.x4.trans.shared.b16 {%0,%1,%2,%3}, [%4];"
                 : "=r"(r[0]), "=r"(r[1]), "=r"(r[2]), "=r"(r[3]) : "r"(addr));
}
__device__ __forceinline__ void mma16816(float* c, const uint32_t* a,
                                         const uint32_t* b) {
    asm volatile(
        "mma.sync.aligned.m16n8k16.row.col.f32.bf16.bf16.f32 "
        "{%0,%1,%2,%3}, {%4,%5,%6,%7}, {%8,%9}, {%0,%1,%2,%3};"
        : "+f"(c[0]), "+f"(c[1]), "+f"(c[2]), "+f"(c[3])
        : "r"(a[0]), "r"(a[1]), "r"(a[2]), "r"(a[3]), "r"(b[0]), "r"(b[1]));
}
__device__ __forceinline__ uint32_t pack_bf(float a, float b) {
    __nv_bfloat16 ha = __float2bfloat16(a);
    __nv_bfloat16 hb = __float2bfloat16(b);
    return (uint32_t)__bfloat16_as_ushort(ha)
         | ((uint32_t)__bfloat16_as_ushort(hb) << 16);
}
__device__ __forceinline__ void cpa16(uint32_t d, const void* s, int sz) {
    asm volatile("cp.async.cg.shared.global [%0], [%1], 16, %2;"
                 :: "r"(d), "l"(s), "r"(sz) : "memory");
}
__device__ __forceinline__ void cpa_commit_wait() {
    asm volatile("cp.async.commit_group;" ::: "memory");
    asm volatile("cp.async.wait_group 0;" ::: "memory");
}
__device__ __forceinline__ void split_bf(float v, __nv_bfloat16& h, __nv_bfloat16& l) {
    h = __float2bfloat16(v);
    l = __float2bfloat16(v - __bfloat162float(h));
}

// ---------------- fused prep: weights (blocks 0..39) + x (rest) -----------
__global__ void prep_kernel(const float* __restrict__ x,
                            const float* __restrict__ W1a,
                            const float* __restrict__ W1b,
                            const float* __restrict__ W2a,
                            const float* __restrict__ W2b, int n4) {
    if (blockIdx.x < 40) {
        int i = blockIdx.x * 256 + threadIdx.x;     // float4 index
        const float* srcs[4] = {W1a, W1b, W2a, W2b};
        int which, local;
        if (i < 8192)       { which = i >> 12;                local = i & 4095; }
        else if (i < 10240) { which = 2 + ((i - 8192) >> 10); local = (i - 8192) & 1023; }
        else return;
        float4 v = *reinterpret_cast<const float4*>(srcs[which] + 4 * local);
        __nv_bfloat16 h[4], l[4];
        split_bf(v.x, h[0], l[0]); split_bf(v.y, h[1], l[1]);
        split_bf(v.z, h[2], l[2]); split_bf(v.w, h[3], l[3]);
        uint2 hv = make_uint2(pack_bf(v.x, v.y), pack_bf(v.z, v.w));
        uint2 lv = make_uint2(
            pack_bf(__bfloat162float(l[0]), __bfloat162float(l[1])),
            pack_bf(__bfloat162float(l[2]), __bfloat162float(l[3])));
        if (which < 2) {
            *reinterpret_cast<uint2*>(&g_w1sp[which][0][4 * local]) = hv;
            *reinterpret_cast<uint2*>(&g_w1sp[which][1][4 * local]) = lv;
        } else {
            *reinterpret_cast<uint2*>(&g_w2sp[which - 2][0][4 * local]) = hv;
            *reinterpret_cast<uint2*>(&g_w2sp[which - 2][1][4 * local]) = lv;
        }
    } else {
        int i = (blockIdx.x - 40) * 256 + threadIdx.x;
        if (i >= n4) return;
        float4 v = *reinterpret_cast<const float4*>(x + 4 * (size_t)i);
        __nv_bfloat16 h[4], l[4];
        split_bf(v.x, h[0], l[0]); split_bf(v.y, h[1], l[1]);
        split_bf(v.z, h[2], l[2]); split_bf(v.w, h[3], l[3]);
        *reinterpret_cast<uint2*>(&g_xsp[0][4 * (size_t)i]) =
            make_uint2(pack_bf(v.x, v.y), pack_bf(v.z, v.w));
        *reinterpret_cast<uint2*>(&g_xsp[1][4 * (size_t)i]) = make_uint2(
            pack_bf(__bfloat162float(l[0]), __bfloat162float(l[1])),
            pack_bf(__bfloat162float(l[2]), __bfloat162float(l[3])));
    }
}

// smem layout (bf16, padded strides for conflict-free ldmatrix)
#define LDA   136
#define LDB2  40
#define SA_HI  0
#define SA_LO  (SA_HI  + 128 * LDA * 2)
#define SB1_HI (SA_LO  + 128 * LDA * 2)
#define SB1_LO (SB1_HI + 128 * LDA * 2)
#define SB2_HI (SB1_LO + 128 * LDA * 2)
#define SB2_LO (SB2_HI + 128 * LDB2 * 2)
#define SM_TOTAL (SB2_LO + 128 * LDB2 * 2)   // 159744 bytes

// ============ node transform: mma.sync bf16x3, cp.async preamble ==========
__global__ __launch_bounds__(256, 1) void transform_kernel(
    const float* __restrict__ b1a, const float* __restrict__ b2a,
    const float* __restrict__ b1b, const float* __restrict__ b2b,
    int nrows)
{
    extern __shared__ char smc[];
    const uint32_t sb = smem_u32(smc);

    const int branch = blockIdx.y;
    const float* b1 = branch ? b1b : b1a;
    const float* b2 = branch ? b2b : b2a;
    float* q_out = branch ? g_q2 : g_q;

    const int tid  = threadIdx.x;
    const int wid  = tid >> 5;
    const int lane = tid & 31;
    const int row0 = blockIdx.x * 128;

    // ---- async load pre-split tiles ----
    for (int i = tid; i < 2048; i += 256) {           // A: 128 rows x 16 chunks
        int r = i >> 4, ch = (i & 15) << 3;
        int row = row0 + r;
        int rc = row < nrows ? row : (nrows - 1);
        int sz = row < nrows ? 16 : 0;
        cpa16(sb + SA_HI + (r * LDA + ch) * 2, &g_xsp[0][(size_t)rc * 128 + ch], sz);
        cpa16(sb + SA_LO + (r * LDA + ch) * 2, &g_xsp[1][(size_t)rc * 128 + ch], sz);
    }
    for (int i = tid; i < 2048; i += 256) {           // B1
        int k = i >> 4, ch = (i & 15) << 3;
        cpa16(sb + SB1_HI + (k * LDA + ch) * 2, &g_w1sp[branch][0][k * 128 + ch], 16);
        cpa16(sb + SB1_LO + (k * LDA + ch) * 2, &g_w1sp[branch][1][k * 128 + ch], 16);
    }
    for (int i = tid; i < 512; i += 256) {            // B2
        int k = i >> 2, ch = (i & 3) << 3;
        cpa16(sb + SB2_HI + (k * LDB2 + ch) * 2, &g_w2sp[branch][0][k * 32 + ch], 16);
        cpa16(sb + SB2_LO + (k * LDB2 + ch) * 2, &g_w2sp[branch][1][k * 32 + ch], 16);
    }
    cpa_commit_wait();
    __syncthreads();

    // ======== layer1: C[128][128] = x @ W1, warp tile 32 rows x 64 cols ====
    const int wm = (wid & 3) * 32;
    const int wn = (wid >> 2) * 64;
    float acc[2][8][4];
    #pragma unroll
    for (int mt = 0; mt < 2; mt++)
        #pragma unroll
        for (int nt = 0; nt < 8; nt++)
            #pragma unroll
            for (int r = 0; r < 4; r++) acc[mt][nt][r] = 0.f;

    const int arow = lane & 15, ac8 = (lane >> 4) << 3;
    #pragma unroll
    for (int ks = 0; ks < 8; ks++) {
        const int k0 = ks << 4;
        uint32_t aH[2][4], aL[2][4];
        #pragma unroll
        for (int mt = 0; mt < 2; mt++) {
            uint32_t off = ((wm + mt * 16 + arow) * LDA + k0 + ac8) * 2;
            ldsm_x4(aH[mt], sb + SA_HI + off);
            ldsm_x4(aL[mt], sb + SA_LO + off);
        }
        uint32_t bH[4][4], bL[4][4];
        #pragma unroll
        for (int g = 0; g < 4; g++) {
            uint32_t off = ((k0 + arow) * LDA + wn + g * 16 + ac8) * 2;
            ldsm_x4t(bH[g], sb + SB1_HI + off);
            ldsm_x4t(bL[g], sb + SB1_LO + off);
        }
        #pragma unroll
        for (int mt = 0; mt < 2; mt++)
            #pragma unroll
            for (int nt = 0; nt < 8; nt++) {
                const uint32_t* bh = &bH[nt >> 1][(nt & 1) * 2];
                const uint32_t* bl = &bL[nt >> 1][(nt & 1) * 2];
                mma16816(acc[mt][nt], aH[mt], bh);
                mma16816(acc[mt][nt], aH[mt], bl);
                mma16816(acc[mt][nt], aL[mt], bh);
            }
    }
    __syncthreads();

    // ---- epilogue 1: h = swish(C + b1), split -> sA hi/lo ----
    {
        const int rbase = lane >> 2;
        const int cbase = (lane & 3) << 1;
        #pragma unroll
        for (int mt = 0; mt < 2; mt++)
            #pragma unroll
            for (int nt = 0; nt < 8; nt++) {
                int col = wn + nt * 8 + cbase;
                float g0 = __ldg(b1 + col), g1 = __ldg(b1 + col + 1);
                #pragma unroll
                for (int hh = 0; hh < 2; hh++) {
                    int row = wm + mt * 16 + rbase + hh * 8;
                    float v0 = swish_f(acc[mt][nt][2 * hh]     + g0);
                    float v1 = swish_f(acc[mt][nt][2 * hh + 1] + g1);
                    float h0 = __bfloat162float(__float2bfloat16(v0));
                    float h1 = __bfloat162float(__float2bfloat16(v1));
                    uint32_t o = (row * LDA + col) * 2;
                    *reinterpret_cast<uint32_t*>(smc + SA_HI + o) = pack_bf(v0, v1);
                    *reinterpret_cast<uint32_t*>(smc + SA_LO + o) =
                        pack_bf(v0 - h0, v1 - h1);
                }
            }
    }
    __syncthreads();

    // ======== layer2: q[128][32] = h @ W2, warp tile 16 rows x 32 cols =====
    const int m0 = wid << 4;
    float acc2[4][4];
    #pragma unroll
    for (int nt = 0; nt < 4; nt++)
        #pragma unroll
        for (int r = 0; r < 4; r++) acc2[nt][r] = 0.f;

    #pragma unroll
    for (int ks = 0; ks < 8; ks++) {
        const int k0 = ks << 4;
        uint32_t aH[4], aL[4];
        uint32_t offa = ((m0 + arow) * LDA + k0 + ac8) * 2;
        ldsm_x4(aH, sb + SA_HI + offa);
        ldsm_x4(aL, sb + SA_LO + offa);
        uint32_t bH[2][4], bL[2][4];
        #pragma unroll
        for (int g = 0; g < 2; g++) {
            uint32_t off = ((k0 + arow) * LDB2 + g * 16 + ac8) * 2;
            ldsm_x4t(bH[g], sb + SB2_HI + off);
            ldsm_x4t(bL[g], sb + SB2_LO + off);
        }
        #pragma unroll
        for (int nt = 0; nt < 4; nt++) {
            const uint32_t* bh = &bH[nt >> 1][(nt & 1) * 2];
            const uint32_t* bl = &bL[nt >> 1][(nt & 1) * 2];
            mma16816(acc2[nt], aH, bh);
            mma16816(acc2[nt], aH, bl);
            mma16816(acc2[nt], aL, bh);
        }
    }

    // ---- epilogue 2: q = swish(C2 + b2) -> gmem ----
    {
        const int rbase = lane >> 2;
        const int cbase = (lane & 3) << 1;
        #pragma unroll
        for (int nt = 0; nt < 4; nt++) {
            int col = nt * 8 + cbase;
            float g0 = __ldg(b2 + col), g1 = __ldg(b2 + col + 1);
            #pragma unroll
            for (int hh = 0; hh < 2; hh++) {
                int row = row0 + m0 + rbase + hh * 8;
                if (row < nrows) {
                    float* qp = q_out + (size_t)row * DDIM + col;
                    qp[0] = swish_f(acc2[nt][2 * hh]     + g0);
                    qp[1] = swish_f(acc2[nt][2 * hh + 1] + g1);
                }
            }
        }
    }
}

// ---------------- CSR build ----------------
__global__ void zero_cnt_kernel(int n) {
    int i = blockIdx.x * blockDim.x + threadIdx.x;
    if (i < n) g_cnt[i] = 0;
}

__global__ void count_kernel(const int* __restrict__ dst,
                             const float* __restrict__ rij, int E) {
    int e = (blockIdx.x * blockDim.x + threadIdx.x) * 2;
    if (e + 1 < E) {
        float2 r2 = *reinterpret_cast<const float2*>(rij + e);
        int2   d2 = *reinterpret_cast<const int2*>(dst + e);
        if (r2.x < CUT) atomicAdd(&g_cnt[d2.x], 1);
        if (r2.y < CUT) atomicAdd(&g_cnt[d2.y], 1);
    } else if (e < E) {
        if (rij[e] < CUT) atomicAdd(&g_cnt[dst[e]], 1);
    }
}

__global__ void scan1_kernel(int n) {
    __shared__ int s[256];
    int base = blockIdx.x * 2048 + threadIdx.x * 8;
    int v[8];
    int sum = 0;
    #pragma unroll
    for (int j = 0; j < 8; j++) {
        int idx = base + j;
        int t = (idx < n) ? g_cnt[idx] : 0;
        v[j] = sum;
        sum += t;
    }
    s[threadIdx.x] = sum;
    __syncthreads();
    for (int off = 1; off < 256; off <<= 1) {
        int t = (threadIdx.x >= off) ? s[threadIdx.x - off] : 0;
        __syncthreads();
        s[threadIdx.x] += t;
        __syncthreads();
    }
    int excl = s[threadIdx.x] - sum;
    if (threadIdx.x == 255) g_bsum[blockIdx.x] = s[255];
    #pragma unroll
    for (int j = 0; j < 8; j++) {
        int idx = base + j;
        if (idx < n) g_off[idx] = excl + v[j];
    }
}

__global__ void scan2_kernel(int nb) {
    if (threadIdx.x == 0) {
        int a = 0;
        for (int i = 0; i < nb; i++) { int t = g_bsum[i]; g_bsum[i] = a; a += t; }
    }
}

__global__ void scan3_kernel(int n) {
    int i = blockIdx.x * blockDim.x + threadIdx.x;
    if (i < n) {
        int o = g_off[i] + g_bsum[i >> 11];
        g_off[i] = o;
        g_cur[i] = o;
    }
}

__global__ void scatter_kernel(const int* __restrict__ src,
                               const int* __restrict__ dst,
                               const float* __restrict__ rij,
                               const float* __restrict__ vij, int E) {
    int e = blockIdx.x * blockDim.x + threadIdx.x;
    if (e >= E) return;
    float r = rij[e];
    if (r < CUT) {
        float c = 0.5f * (cosf(PI_F * r / CUT) + 1.0f);
        int p = atomicAdd(&g_cur[dst[e]], 1);
        g_cwv[p] = make_float4(c * vij[3 * e], c * vij[3 * e + 1],
                               c * vij[3 * e + 2], __int_as_float(src[e]));
    }
}

// ---------------- gather + cross + mix, one warp per node, lane = d --------
__global__ __launch_bounds__(256) void gather_kernel(
    const float* __restrict__ wmix, const float* __restrict__ bmix,
    float* __restrict__ out, int nNodes)
{
    int gw   = (blockIdx.x * 256 + threadIdx.x) >> 5;
    int lane = threadIdx.x & 31;
    if (gw >= nNodes) return;

    int start = g_off[gw];
    int m     = g_cnt[gw];

    float ax = 0.f, ay = 0.f, az = 0.f;
    float bx = 0.f, by = 0.f, bz = 0.f;

    int i = 0;
    for (; i + 2 <= m; i += 2) {
        float4 w0 = __ldg(&g_cwv[start + i]);
        float4 w1 = __ldg(&g_cwv[start + i + 1]);
        int s0 = __float_as_int(w0.w);
        int s1 = __float_as_int(w1.w);
        float qa = __ldg(&g_q [s0 * DDIM + lane]);
        float pa = __ldg(&g_q2[s0 * DDIM + lane]);
        float qb = __ldg(&g_q [s1 * DDIM + lane]);
        float pb = __ldg(&g_q2[s1 * DDIM + lane]);
        ax = fmaf(w0.x, qa, ax); ax = fmaf(w1.x, qb, ax);
        ay = fmaf(w0.y, qa, ay); ay = fmaf(w1.y, qb, ay);
        az = fmaf(w0.z, qa, az); az = fmaf(w1.z, qb, az);
        bx = fmaf(w0.x, pa, bx); bx = fmaf(w1.x, pb, bx);
        by = fmaf(w0.y, pa, by); by = fmaf(w1.y, pb, by);
        bz = fmaf(w0.z, pa, bz); bz = fmaf(w1.z, pb, bz);
    }
    if (i < m) {
        float4 w0 = __ldg(&g_cwv[start + i]);
        int s0 = __float_as_int(w0.w);
        float qa = __ldg(&g_q [s0 * DDIM + lane]);
        float pa = __ldg(&g_q2[s0 * DDIM + lane]);
        ax = fmaf(w0.x, qa, ax);
        ay = fmaf(w0.y, qa, ay);
        az = fmaf(w0.z, qa, az);
        bx = fmaf(w0.x, pa, bx);
        by = fmaf(w0.y, pa, by);
        bz = fmaf(w0.z, pa, bz);
    }

    float m0 = __ldg(wmix), m1 = __ldg(wmix + 1), m2 = __ldg(wmix + 2);
    float bm = __ldg(bmix);

    float cx = ay * bz - az * by;
    float cy = az * bx - ax * bz;
    float cz = ax * by - ay * bx;

    size_t p = (size_t)gw * (DDIM * 3) + lane * 3;
    out[p + 0] = ax * m0 + bx * m1 + cx * m2 + bm;
    out[p + 1] = ay * m0 + by * m1 + cy * m2 + bm;
    out[p + 2] = az * m0 + bz * m1 + cz * m2 + bm;
}

// ---------------- launch ----------------
extern "C" void kernel_launch(void* const* d_in, const int* in_sizes, int n_in,
                              void* d_out, int out_size)
{
    const float* x    = (const float*)d_in[0];
    const float* rij  = (const float*)d_in[1];
    const float* vij  = (const float*)d_in[2];
    const int*   src  = (const int*)  d_in[3];
    const int*   dst  = (const int*)  d_in[4];
    const float* W1   = (const float*)d_in[5];
    const float* b1   = (const float*)d_in[6];
    const float* W2   = (const float*)d_in[7];
    const float* b2   = (const float*)d_in[8];
    const float* W1b  = (const float*)d_in[9];
    const float* b1b  = (const float*)d_in[10];
    const float* W2b  = (const float*)d_in[11];
    const float* b2b  = (const float*)d_in[12];
    const float* wmix = (const float*)d_in[13];
    const float* bmix = (const float*)d_in[14];
    float* out = (float*)d_out;

    int N = in_sizes[0] / FDIM;
    int E = in_sizes[1];
    if (N > NMAX) N = NMAX;
    if (E > EMAX) E = EMAX;

    cudaFuncSetAttribute(transform_kernel,
                         cudaFuncAttributeMaxDynamicSharedMemorySize, SM_TOTAL);

    int gE = (E + 255) / 256;
    int gN = (N + 255) / 256;
    int nb = (N + 2047) / 2048;
    int n4 = N * FDIM / 4;

    // fork: CSR chain on side stream, transform chain on capture stream
    cudaStream_t s2;
    cudaStreamCreateWithFlags(&s2, cudaStreamNonBlocking);
    cudaEvent_t evFork, evJoin;
    cudaEventCreateWithFlags(&evFork, cudaEventDisableTiming);
    cudaEventCreateWithFlags(&evJoin, cudaEventDisableTiming);

    cudaEventRecord(evFork, 0);
    cudaStreamWaitEvent(s2, evFork, 0);

    // ---- side stream: CSR build ----
    zero_cnt_kernel<<<gN, 256, 0, s2>>>(N);
    count_kernel<<<(E / 2 + 255) / 256, 256, 0, s2>>>(dst, rij, E);
    scan1_kernel<<<nb, 256, 0, s2>>>(N);
    scan2_kernel<<<1, 32, 0, s2>>>(nb);
    scan3_kernel<<<gN, 256, 0, s2>>>(N);
    scatter_kernel<<<gE, 256, 0, s2>>>(src, dst, rij, vij, E);
    cudaEventRecord(evJoin, s2);

    // ---- capture stream: prep + transform ----
    prep_kernel<<<40 + (n4 + 255) / 256, 256>>>(x, W1, W1b, W2, W2b, n4);
    dim3 gT((N + 127) / 128, 2);
    transform_kernel<<<gT, 256, SM_TOTAL>>>(b1, b2, b1b, b2b, N);

    // join, then gather
    cudaStreamWaitEvent(0, evJoin, 0);
    int gG = (N * 32 + 255) / 256;
    gather_kernel<<<gG, 256>>>(wmix, bmix, out, N);

    cudaEventDestroy(evFork);
    cudaEventDestroy(evJoin);
    cudaStreamDestroy(s2);
}

// round 9
// speedup vs baseline: 2.6309x; 1.0053x over previous
#include <cuda_runtime.h>
#include <cuda_bf16.h>
#include <cstdint>

#define NMAX   50000
#define EMAX   800000
#define FDIM   128
#define DDIM   32
#define CUT    5.0f
#define PI_F   3.14159265358979323846f

// ---------------- device scratch (static, allocation-free) ----------------
__device__ float  g_q [NMAX * DDIM];
__device__ float  g_q2[NMAX * DDIM];
__device__ int    g_cnt[NMAX];
__device__ int    g_off[NMAX];
__device__ int    g_cur[NMAX];
__device__ int    g_bsum[64];
__device__ float4 g_cwv[EMAX];

__device__ __forceinline__ float swish_f(float v) {
    return v * __fdividef(1.0f, 1.0f + __expf(-v));
}

// ---------------- helpers (baseline PTX only) -----------------------------
__device__ __forceinline__ uint32_t smem_u32(const void* p) {
    uint32_t a;
    asm("{ .reg .u64 t; cvta.to.shared.u64 t, %1; cvt.u32.u64 %0, t; }"
        : "=r"(a) : "l"(p));
    return a;
}
__device__ __forceinline__ void ldsm_x4(uint32_t* r, uint32_t addr) {
    asm volatile("ldmatrix.sync.aligned.m8n8.x4.shared.b16 {%0,%1,%2,%3}, [%4];"
                 : "=r"(r[0]), "=r"(r[1]), "=r"(r[2]), "=r"(r[3]) : "r"(addr));
}
__device__ __forceinline__ void ldsm_x4t(uint32_t* r, uint32_t addr) {
    asm volatile("ldmatrix.sync.aligned.m8n8.x4.trans.shared.b16 {%0,%1,%2,%3}, [%4];"
                 : "=r"(r[0]), "=r"(r[1]), "=r"(r[2]), "=r"(r[3]) : "r"(addr));
}
__device__ __forceinline__ void mma16816(float* c, const uint32_t* a,
                                         const uint32_t* b) {
    asm volatile(
        "mma.sync.aligned.m16n8k16.row.col.f32.bf16.bf16.f32 "
        "{%0,%1,%2,%3}, {%4,%5,%6,%7}, {%8,%9}, {%0,%1,%2,%3};"
        : "+f"(c[0]), "+f"(c[1]), "+f"(c[2]), "+f"(c[3])
        : "r"(a[0]), "r"(a[1]), "r"(a[2]), "r"(a[3]), "r"(b[0]), "r"(b[1]));
}
__device__ __forceinline__ uint32_t pack_bf(float a, float b) {
    __nv_bfloat16 ha = __float2bfloat16(a);
    __nv_bfloat16 hb = __float2bfloat16(b);
    return (uint32_t)__bfloat16_as_ushort(ha)
         | ((uint32_t)__bfloat16_as_ushort(hb) << 16);
}
// split float4 -> packed hi uint2 / lo uint2
__device__ __forceinline__ void split4(float4 v, uint2& hv, uint2& lv) {
    float hx = __bfloat162float(__float2bfloat16(v.x));
    float hy = __bfloat162float(__float2bfloat16(v.y));
    float hz = __bfloat162float(__float2bfloat16(v.z));
    float hw = __bfloat162float(__float2bfloat16(v.w));
    hv = make_uint2(pack_bf(v.x, v.y), pack_bf(v.z, v.w));
    lv = make_uint2(pack_bf(v.x - hx, v.y - hy), pack_bf(v.z - hz, v.w - hw));
}

// smem layout (bf16, padded strides for conflict-free ldmatrix)
#define LDA   136
#define LDB2  40
#define SA_HI  0
#define SA_LO  (SA_HI  + 128 * LDA * 2)
#define SB1_HI (SA_LO  + 128 * LDA * 2)
#define SB1_LO (SB1_HI + 128 * LDA * 2)
#define SB2_HI (SB1_LO + 128 * LDA * 2)
#define SB2_LO (SB2_HI + 128 * LDB2 * 2)
#define SM_TOTAL (SB2_LO + 128 * LDB2 * 2)   // 159744 bytes

#define PERSIST_X 74   // blocks per branch (one per SM, 2 branches -> 148)

// ==== persistent node transform: weights converted once, tiles looped =====
__global__ __launch_bounds__(256, 1) void transform_kernel(
    const float* __restrict__ x,
    const float* __restrict__ W1a, const float* __restrict__ b1a,
    const float* __restrict__ W2a, const float* __restrict__ b2a,
    const float* __restrict__ W1b, const float* __restrict__ b1b,
    const float* __restrict__ W2b, const float* __restrict__ b2b,
    int nrows, int ntiles)
{
    extern __shared__ char smc[];
    const uint32_t sb = smem_u32(smc);

    const int branch = blockIdx.y;
    const float* W1 = branch ? W1b : W1a;
    const float* b1 = branch ? b1b : b1a;
    const float* W2 = branch ? W2b : W2a;
    const float* b2 = branch ? b2b : b2a;
    float* q_out = branch ? g_q2 : g_q;

    const int tid  = threadIdx.x;
    const int wid  = tid >> 5;
    const int lane = tid & 31;

    // ---- convert weights once: W1 -> SB1 hi/lo, W2 -> SB2 hi/lo ----
    for (int i = tid; i < 4096; i += 256) {
        int k = i >> 5, c4 = (i & 31) << 2;
        uint2 hv, lv;
        split4(*reinterpret_cast<const float4*>(W1 + k * 128 + c4), hv, lv);
        *reinterpret_cast<uint2*>(smc + SB1_HI + (k * LDA + c4) * 2) = hv;
        *reinterpret_cast<uint2*>(smc + SB1_LO + (k * LDA + c4) * 2) = lv;
    }
    for (int i = tid; i < 1024; i += 256) {
        int k = i >> 3, c4 = (i & 7) << 2;
        uint2 hv, lv;
        split4(*reinterpret_cast<const float4*>(W2 + k * 32 + c4), hv, lv);
        *reinterpret_cast<uint2*>(smc + SB2_HI + (k * LDB2 + c4) * 2) = hv;
        *reinterpret_cast<uint2*>(smc + SB2_LO + (k * LDB2 + c4) * 2) = lv;
    }

    const int wm = (wid & 3) * 32;
    const int wn = (wid >> 2) * 64;
    const int arow = lane & 15, ac8 = (lane >> 4) << 3;
    const int rbase = lane >> 2;
    const int cbase = (lane & 3) << 1;
    const int m0 = wid << 4;

    for (int t = blockIdx.x; t < ntiles; t += PERSIST_X) {
        const int row0 = t * 128;

        // ---- convert x tile fp32 -> sA hi/lo ----
        __syncthreads();   // prior iteration's MMA2 reads of sA done
        for (int i = tid; i < 2048; i += 256) {
            int r = i >> 4, c4 = (i & 15) << 3;   // 8 floats per iter (2x float4)
            int row = row0 + r;
            float4 v0 = make_float4(0.f, 0.f, 0.f, 0.f);
            float4 v1 = v0;
            if (row < nrows) {
                const float* xp = x + (size_t)row * 128 + c4;
                v0 = *reinterpret_cast<const float4*>(xp);
                v1 = *reinterpret_cast<const float4*>(xp + 4);
            }
            uint2 h0, l0, h1, l1;
            split4(v0, h0, l0);
            split4(v1, h1, l1);
            uint32_t o = (r * LDA + c4) * 2;
            *reinterpret_cast<uint4*>(smc + SA_HI + o) =
                make_uint4(h0.x, h0.y, h1.x, h1.y);
            *reinterpret_cast<uint4*>(smc + SA_LO + o) =
                make_uint4(l0.x, l0.y, l1.x, l1.y);
        }
        __syncthreads();

        // ======== layer1: C[128][128] = x @ W1 ========
        float acc[2][8][4];
        #pragma unroll
        for (int mt = 0; mt < 2; mt++)
            #pragma unroll
            for (int nt = 0; nt < 8; nt++)
                #pragma unroll
                for (int r = 0; r < 4; r++) acc[mt][nt][r] = 0.f;

        #pragma unroll
        for (int ks = 0; ks < 8; ks++) {
            const int k0 = ks << 4;
            uint32_t aH[2][4], aL[2][4];
            #pragma unroll
            for (int mt = 0; mt < 2; mt++) {
                uint32_t off = ((wm + mt * 16 + arow) * LDA + k0 + ac8) * 2;
                ldsm_x4(aH[mt], sb + SA_HI + off);
                ldsm_x4(aL[mt], sb + SA_LO + off);
            }
            uint32_t bH[4][4], bL[4][4];
            #pragma unroll
            for (int g = 0; g < 4; g++) {
                uint32_t off = ((k0 + arow) * LDA + wn + g * 16 + ac8) * 2;
                ldsm_x4t(bH[g], sb + SB1_HI + off);
                ldsm_x4t(bL[g], sb + SB1_LO + off);
            }
            #pragma unroll
            for (int mt = 0; mt < 2; mt++)
                #pragma unroll
                for (int nt = 0; nt < 8; nt++) {
                    const uint32_t* bh = &bH[nt >> 1][(nt & 1) * 2];
                    const uint32_t* bl = &bL[nt >> 1][(nt & 1) * 2];
                    mma16816(acc[mt][nt], aH[mt], bh);
                    mma16816(acc[mt][nt], aH[mt], bl);
                    mma16816(acc[mt][nt], aL[mt], bh);
                }
        }
        __syncthreads();   // sA reads done before overwrite with h

        // ---- epilogue 1: h = swish(C + b1), split -> sA hi/lo ----
        #pragma unroll
        for (int mt = 0; mt < 2; mt++)
            #pragma unroll
            for (int nt = 0; nt < 8; nt++) {
                int col = wn + nt * 8 + cbase;
                float g0 = __ldg(b1 + col), g1 = __ldg(b1 + col + 1);
                #pragma unroll
                for (int hh = 0; hh < 2; hh++) {
                    int row = wm + mt * 16 + rbase + hh * 8;
                    float v0 = swish_f(acc[mt][nt][2 * hh]     + g0);
                    float v1 = swish_f(acc[mt][nt][2 * hh + 1] + g1);
                    float h0 = __bfloat162float(__float2bfloat16(v0));
                    float h1 = __bfloat162float(__float2bfloat16(v1));
                    uint32_t o = (row * LDA + col) * 2;
                    *reinterpret_cast<uint32_t*>(smc + SA_HI + o) = pack_bf(v0, v1);
                    *reinterpret_cast<uint32_t*>(smc + SA_LO + o) =
                        pack_bf(v0 - h0, v1 - h1);
                }
            }
        __syncthreads();

        // ======== layer2: q[128][32] = h @ W2 ========
        float acc2[4][4];
        #pragma unroll
        for (int nt = 0; nt < 4; nt++)
            #pragma unroll
            for (int r = 0; r < 4; r++) acc2[nt][r] = 0.f;

        #pragma unroll
        for (int ks = 0; ks < 8; ks++) {
            const int k0 = ks << 4;
            uint32_t aH[4], aL[4];
            uint32_t offa = ((m0 + arow) * LDA + k0 + ac8) * 2;
            ldsm_x4(aH, sb + SA_HI + offa);
            ldsm_x4(aL, sb + SA_LO + offa);
            uint32_t bH[2][4], bL[2][4];
            #pragma unroll
            for (int g = 0; g < 2; g++) {
                uint32_t off = ((k0 + arow) * LDB2 + g * 16 + ac8) * 2;
                ldsm_x4t(bH[g], sb + SB2_HI + off);
                ldsm_x4t(bL[g], sb + SB2_LO + off);
            }
            #pragma unroll
            for (int nt = 0; nt < 4; nt++) {
                const uint32_t* bh = &bH[nt >> 1][(nt & 1) * 2];
                const uint32_t* bl = &bL[nt >> 1][(nt & 1) * 2];
                mma16816(acc2[nt], aH, bh);
                mma16816(acc2[nt], aH, bl);
                mma16816(acc2[nt], aL, bh);
            }
        }

        // ---- epilogue 2: q = swish(C2 + b2) -> gmem ----
        #pragma unroll
        for (int nt = 0; nt < 4; nt++) {
            int col = nt * 8 + cbase;
            float g0 = __ldg(b2 + col), g1 = __ldg(b2 + col + 1);
            #pragma unroll
            for (int hh = 0; hh < 2; hh++) {
                int row = row0 + m0 + rbase + hh * 8;
                if (row < nrows) {
                    float* qp = q_out + (size_t)row * DDIM + col;
                    qp[0] = swish_f(acc2[nt][2 * hh]     + g0);
                    qp[1] = swish_f(acc2[nt][2 * hh + 1] + g1);
                }
            }
        }
        // loop-top __syncthreads() protects sA before next conversion
    }
}

// ---------------- CSR build ----------------
__global__ void zero_cnt_kernel(int n) {
    int i = blockIdx.x * blockDim.x + threadIdx.x;
    if (i < n) g_cnt[i] = 0;
}

__global__ void count_kernel(const int* __restrict__ dst,
                             const float* __restrict__ rij, int E) {
    int e = (blockIdx.x * blockDim.x + threadIdx.x) * 2;
    if (e + 1 < E) {
        float2 r2 = *reinterpret_cast<const float2*>(rij + e);
        int2   d2 = *reinterpret_cast<const int2*>(dst + e);
        if (r2.x < CUT) atomicAdd(&g_cnt[d2.x], 1);
        if (r2.y < CUT) atomicAdd(&g_cnt[d2.y], 1);
    } else if (e < E) {
        if (rij[e] < CUT) atomicAdd(&g_cnt[dst[e]], 1);
    }
}

__global__ void scan1_kernel(int n) {
    __shared__ int s[256];
    int base = blockIdx.x * 2048 + threadIdx.x * 8;
    int v[8];
    int sum = 0;
    #pragma unroll
    for (int j = 0; j < 8; j++) {
        int idx = base + j;
        int t = (idx < n) ? g_cnt[idx] : 0;
        v[j] = sum;
        sum += t;
    }
    s[threadIdx.x] = sum;
    __syncthreads();
    for (int off = 1; off < 256; off <<= 1) {
        int t = (threadIdx.x >= off) ? s[threadIdx.x - off] : 0;
        __syncthreads();
        s[threadIdx.x] += t;
        __syncthreads();
    }
    int excl = s[threadIdx.x] - sum;
    if (threadIdx.x == 255) g_bsum[blockIdx.x] = s[255];
    #pragma unroll
    for (int j = 0; j < 8; j++) {
        int idx = base + j;
        if (idx < n) g_off[idx] = excl + v[j];
    }
}

__global__ void scan2_kernel(int nb) {
    if (threadIdx.x == 0) {
        int a = 0;
        for (int i = 0; i < nb; i++) { int t = g_bsum[i]; g_bsum[i] = a; a += t; }
    }
}

__global__ void scan3_kernel(int n) {
    int i = blockIdx.x * blockDim.x + threadIdx.x;
    if (i < n) {
        int o = g_off[i] + g_bsum[i >> 11];
        g_off[i] = o;
        g_cur[i] = o;
    }
}

__global__ void scatter_kernel(const int* __restrict__ src,
                               const int* __restrict__ dst,
                               const float* __restrict__ rij,
                               const float* __restrict__ vij, int E) {
    int e = blockIdx.x * blockDim.x + threadIdx.x;
    if (e >= E) return;
    float r = rij[e];
    if (r < CUT) {
        float c = 0.5f * (cosf(PI_F * r / CUT) + 1.0f);
        int p = atomicAdd(&g_cur[dst[e]], 1);
        g_cwv[p] = make_float4(c * vij[3 * e], c * vij[3 * e + 1],
                               c * vij[3 * e + 2], __int_as_float(src[e]));
    }
}

// ---------------- gather + cross + mix, one warp per node, lane = d --------
__global__ __launch_bounds__(256) void gather_kernel(
    const float* __restrict__ wmix, const float* __restrict__ bmix,
    float* __restrict__ out, int nNodes)
{
    int gw   = (blockIdx.x * 256 + threadIdx.x) >> 5;
    int lane = threadIdx.x & 31;
    if (gw >= nNodes) return;

    int start = g_off[gw];
    int m     = g_cnt[gw];

    float ax = 0.f, ay = 0.f, az = 0.f;
    float bx = 0.f, by = 0.f, bz = 0.f;

    int i = 0;
    for (; i + 2 <= m; i += 2) {
        float4 w0 = __ldg(&g_cwv[start + i]);
        float4 w1 = __ldg(&g_cwv[start + i + 1]);
        int s0 = __float_as_int(w0.w);
        int s1 = __float_as_int(w1.w);
        float qa = __ldg(&g_q [s0 * DDIM + lane]);
        float pa = __ldg(&g_q2[s0 * DDIM + lane]);
        float qb = __ldg(&g_q [s1 * DDIM + lane]);
        float pb = __ldg(&g_q2[s1 * DDIM + lane]);
        ax = fmaf(w0.x, qa, ax); ax = fmaf(w1.x, qb, ax);
        ay = fmaf(w0.y, qa, ay); ay = fmaf(w1.y, qb, ay);
        az = fmaf(w0.z, qa, az); az = fmaf(w1.z, qb, az);
        bx = fmaf(w0.x, pa, bx); bx = fmaf(w1.x, pb, bx);
        by = fmaf(w0.y, pa, by); by = fmaf(w1.y, pb, by);
        bz = fmaf(w0.z, pa, bz); bz = fmaf(w1.z, pb, bz);
    }
    if (i < m) {
        float4 w0 = __ldg(&g_cwv[start + i]);
        int s0 = __float_as_int(w0.w);
        float qa = __ldg(&g_q [s0 * DDIM + lane]);
        float pa = __ldg(&g_q2[s0 * DDIM + lane]);
        ax = fmaf(w0.x, qa, ax);
        ay = fmaf(w0.y, qa, ay);
        az = fmaf(w0.z, qa, az);
        bx = fmaf(w0.x, pa, bx);
        by = fmaf(w0.y, pa, by);
        bz = fmaf(w0.z, pa, bz);
    }

    float m0 = __ldg(wmix), m1 = __ldg(wmix + 1), m2 = __ldg(wmix + 2);
    float bm = __ldg(bmix);

    float cx = ay * bz - az * by;
    float cy = az * bx - ax * bz;
    float cz = ax * by - ay * bx;

    size_t p = (size_t)gw * (DDIM * 3) + lane * 3;
    out[p + 0] = ax * m0 + bx * m1 + cx * m2 + bm;
    out[p + 1] = ay * m0 + by * m1 + cy * m2 + bm;
    out[p + 2] = az * m0 + bz * m1 + cz * m2 + bm;
}

// ---------------- launch ----------------
extern "C" void kernel_launch(void* const* d_in, const int* in_sizes, int n_in,
                              void* d_out, int out_size)
{
    const float* x    = (const float*)d_in[0];
    const float* rij  = (const float*)d_in[1];
    const float* vij  = (const float*)d_in[2];
    const int*   src  = (const int*)  d_in[3];
    const int*   dst  = (const int*)  d_in[4];
    const float* W1   = (const float*)d_in[5];
    const float* b1   = (const float*)d_in[6];
    const float* W2   = (const float*)d_in[7];
    const float* b2   = (const float*)d_in[8];
    const float* W1b  = (const float*)d_in[9];
    const float* b1b  = (const float*)d_in[10];
    const float* W2b  = (const float*)d_in[11];
    const float* b2b  = (const float*)d_in[12];
    const float* wmix = (const float*)d_in[13];
    const float* bmix = (const float*)d_in[14];
    float* out = (float*)d_out;

    int N = in_sizes[0] / FDIM;
    int E = in_sizes[1];
    if (N > NMAX) N = NMAX;
    if (E > EMAX) E = EMAX;

    cudaFuncSetAttribute(transform_kernel,
                         cudaFuncAttributeMaxDynamicSharedMemorySize, SM_TOTAL);

    int gE = (E + 255) / 256;
    int gN = (N + 255) / 256;
    int nb = (N + 2047) / 2048;
    int ntiles = (N + 127) / 128;

    // fork: CSR chain on side stream, transform chain on capture stream
    cudaStream_t s2;
    cudaStreamCreateWithFlags(&s2, cudaStreamNonBlocking);
    cudaEvent_t evFork, evJoin;
    cudaEventCreateWithFlags(&evFork, cudaEventDisableTiming);
    cudaEventCreateWithFlags(&evJoin, cudaEventDisableTiming);

    cudaEventRecord(evFork, 0);
    cudaStreamWaitEvent(s2, evFork, 0);

    // ---- side stream: CSR build ----
    zero_cnt_kernel<<<gN, 256, 0, s2>>>(N);
    count_kernel<<<(E / 2 + 255) / 256, 256, 0, s2>>>(dst, rij, E);
    scan1_kernel<<<nb, 256, 0, s2>>>(N);
    scan2_kernel<<<1, 32, 0, s2>>>(nb);
    scan3_kernel<<<gN, 256, 0, s2>>>(N);
    scatter_kernel<<<gE, 256, 0, s2>>>(src, dst, rij, vij, E);
    cudaEventRecord(evJoin, s2);

    // ---- capture stream: persistent transform (no prep) ----
    dim3 gT(PERSIST_X, 2);
    transform_kernel<<<gT, 256, SM_TOTAL>>>(x, W1, b1, W2, b2,
                                            W1b, b1b, W2b, b2b, N, ntiles);

    // join, then gather
    cudaStreamWaitEvent(0, evJoin, 0);
    int gG = (N * 32 + 255) / 256;
    gather_kernel<<<gG, 256>>>(wmix, bmix, out, N);

    cudaEventDestroy(evFork);
    cudaEventDestroy(evJoin);
    cudaStreamDestroy(s2);
}

// round 10
// speedup vs baseline: 2.6485x; 1.0067x over previous
#include <cuda_runtime.h>
#include <cuda_bf16.h>
#include <cstdint>

#define NMAX   50000
#define EMAX   800000
#define FDIM   128
#define DDIM   32
#define CUT    5.0f
#define PI_F   3.14159265358979323846f

// ---------------- device scratch (static, allocation-free) ----------------
__device__ float  g_q [NMAX * DDIM];
__device__ float  g_q2[NMAX * DDIM];
__device__ int    g_cnt[NMAX];
__device__ int    g_off[NMAX];
__device__ int    g_cur[NMAX];
__device__ int    g_bsum[64];
__device__ float4 g_cwv[EMAX];

__device__ __forceinline__ float swish_f(float v) {
    return v * __fdividef(1.0f, 1.0f + __expf(-v));
}

// ---------------- helpers (baseline PTX only) -----------------------------
__device__ __forceinline__ uint32_t smem_u32(const void* p) {
    uint32_t a;
    asm("{ .reg .u64 t; cvta.to.shared.u64 t, %1; cvt.u32.u64 %0, t; }"
        : "=r"(a) : "l"(p));
    return a;
}
__device__ __forceinline__ void ldsm_x4(uint32_t* r, uint32_t addr) {
    asm volatile("ldmatrix.sync.aligned.m8n8.x4.shared.b16 {%0,%1,%2,%3}, [%4];"
                 : "=r"(r[0]), "=r"(r[1]), "=r"(r[2]), "=r"(r[3]) : "r"(addr));
}
__device__ __forceinline__ void ldsm_x4t(uint32_t* r, uint32_t addr) {
    asm volatile("ldmatrix.sync.aligned.m8n8.x4.trans.shared.b16 {%0,%1,%2,%3}, [%4];"
                 : "=r"(r[0]), "=r"(r[1]), "=r"(r[2]), "=r"(r[3]) : "r"(addr));
}
__device__ __forceinline__ void mma16816(float* c, const uint32_t* a,
                                         const uint32_t* b) {
    asm volatile(
        "mma.sync.aligned.m16n8k16.row.col.f32.bf16.bf16.f32 "
        "{%0,%1,%2,%3}, {%4,%5,%6,%7}, {%8,%9}, {%0,%1,%2,%3};"
        : "+f"(c[0]), "+f"(c[1]), "+f"(c[2]), "+f"(c[3])
        : "r"(a[0]), "r"(a[1]), "r"(a[2]), "r"(a[3]), "r"(b[0]), "r"(b[1]));
}
__device__ __forceinline__ uint32_t pack_bf(float a, float b) {
    __nv_bfloat16 ha = __float2bfloat16(a);
    __nv_bfloat16 hb = __float2bfloat16(b);
    return (uint32_t)__bfloat16_as_ushort(ha)
         | ((uint32_t)__bfloat16_as_ushort(hb) << 16);
}
// split float4 -> packed hi uint2 / lo uint2
__device__ __forceinline__ void split4(float4 v, uint2& hv, uint2& lv) {
    float hx = __bfloat162float(__float2bfloat16(v.x));
    float hy = __bfloat162float(__float2bfloat16(v.y));
    float hz = __bfloat162float(__float2bfloat16(v.z));
    float hw = __bfloat162float(__float2bfloat16(v.w));
    hv = make_uint2(pack_bf(v.x, v.y), pack_bf(v.z, v.w));
    lv = make_uint2(pack_bf(v.x - hx, v.y - hy), pack_bf(v.z - hz, v.w - hw));
}

// smem layout (bf16, padded strides for conflict-free ldmatrix)
#define LDA   136
#define LDB2  40
#define SA_HI  0
#define SA_LO  (SA_HI  + 128 * LDA * 2)
#define SB1_HI (SA_LO  + 128 * LDA * 2)
#define SB1_LO (SB1_HI + 128 * LDA * 2)
#define SB2_HI (SB1_LO + 128 * LDA * 2)
#define SB2_LO (SB2_HI + 128 * LDB2 * 2)
#define SM_TOTAL (SB2_LO + 128 * LDB2 * 2)   // 159744 bytes

#define PERSIST_X 74   // blocks per branch (one per SM, 2 branches -> 148)

// ==== persistent node transform: weights converted once, tiles looped =====
__global__ __launch_bounds__(256, 1) void transform_kernel(
    const float* __restrict__ x,
    const float* __restrict__ W1a, const float* __restrict__ b1a,
    const float* __restrict__ W2a, const float* __restrict__ b2a,
    const float* __restrict__ W1b, const float* __restrict__ b1b,
    const float* __restrict__ W2b, const float* __restrict__ b2b,
    int nrows, int ntiles)
{
    extern __shared__ char smc[];
    const uint32_t sb = smem_u32(smc);

    const int branch = blockIdx.y;
    const float* W1 = branch ? W1b : W1a;
    const float* b1 = branch ? b1b : b1a;
    const float* W2 = branch ? W2b : W2a;
    const float* b2 = branch ? b2b : b2a;
    float* q_out = branch ? g_q2 : g_q;

    const int tid  = threadIdx.x;
    const int wid  = tid >> 5;
    const int lane = tid & 31;

    // ---- convert weights once: W1 -> SB1 hi/lo, W2 -> SB2 hi/lo ----
    for (int i = tid; i < 4096; i += 256) {
        int k = i >> 5, c4 = (i & 31) << 2;
        uint2 hv, lv;
        split4(*reinterpret_cast<const float4*>(W1 + k * 128 + c4), hv, lv);
        *reinterpret_cast<uint2*>(smc + SB1_HI + (k * LDA + c4) * 2) = hv;
        *reinterpret_cast<uint2*>(smc + SB1_LO + (k * LDA + c4) * 2) = lv;
    }
    for (int i = tid; i < 1024; i += 256) {
        int k = i >> 3, c4 = (i & 7) << 2;
        uint2 hv, lv;
        split4(*reinterpret_cast<const float4*>(W2 + k * 32 + c4), hv, lv);
        *reinterpret_cast<uint2*>(smc + SB2_HI + (k * LDB2 + c4) * 2) = hv;
        *reinterpret_cast<uint2*>(smc + SB2_LO + (k * LDB2 + c4) * 2) = lv;
    }

    const int wm = (wid & 3) * 32;
    const int wn = (wid >> 2) * 64;
    const int arow = lane & 15, ac8 = (lane >> 4) << 3;
    const int rbase = lane >> 2;
    const int cbase = (lane & 3) << 1;
    const int m0 = wid << 4;

    for (int t = blockIdx.x; t < ntiles; t += PERSIST_X) {
        const int row0 = t * 128;

        // ---- convert x tile fp32 -> sA hi/lo ----
        __syncthreads();   // prior iteration's MMA2 reads of sA done
        for (int i = tid; i < 2048; i += 256) {
            int r = i >> 4, c4 = (i & 15) << 3;   // 8 floats per iter (2x float4)
            int row = row0 + r;
            float4 v0 = make_float4(0.f, 0.f, 0.f, 0.f);
            float4 v1 = v0;
            if (row < nrows) {
                const float* xp = x + (size_t)row * 128 + c4;
                v0 = *reinterpret_cast<const float4*>(xp);
                v1 = *reinterpret_cast<const float4*>(xp + 4);
            }
            uint2 h0, l0, h1, l1;
            split4(v0, h0, l0);
            split4(v1, h1, l1);
            uint32_t o = (r * LDA + c4) * 2;
            *reinterpret_cast<uint4*>(smc + SA_HI + o) =
                make_uint4(h0.x, h0.y, h1.x, h1.y);
            *reinterpret_cast<uint4*>(smc + SA_LO + o) =
                make_uint4(l0.x, l0.y, l1.x, l1.y);
        }
        __syncthreads();

        // ======== layer1: C[128][128] = x @ W1 ========
        float acc[2][8][4];
        #pragma unroll
        for (int mt = 0; mt < 2; mt++)
            #pragma unroll
            for (int nt = 0; nt < 8; nt++)
                #pragma unroll
                for (int r = 0; r < 4; r++) acc[mt][nt][r] = 0.f;

        #pragma unroll
        for (int ks = 0; ks < 8; ks++) {
            const int k0 = ks << 4;
            uint32_t aH[2][4], aL[2][4];
            #pragma unroll
            for (int mt = 0; mt < 2; mt++) {
                uint32_t off = ((wm + mt * 16 + arow) * LDA + k0 + ac8) * 2;
                ldsm_x4(aH[mt], sb + SA_HI + off);
                ldsm_x4(aL[mt], sb + SA_LO + off);
            }
            uint32_t bH[4][4], bL[4][4];
            #pragma unroll
            for (int g = 0; g < 4; g++) {
                uint32_t off = ((k0 + arow) * LDA + wn + g * 16 + ac8) * 2;
                ldsm_x4t(bH[g], sb + SB1_HI + off);
                ldsm_x4t(bL[g], sb + SB1_LO + off);
            }
            // term-major order: all 16 independent accs per term ->
            // per-acc reuse distance 16 >= HMMA latency (no RAW drain).
            // Per-acc accumulation order unchanged (hh, hl, lh per kstep).
            #pragma unroll
            for (int mt = 0; mt < 2; mt++)
                #pragma unroll
                for (int nt = 0; nt < 8; nt++)
                    mma16816(acc[mt][nt], aH[mt], &bH[nt >> 1][(nt & 1) * 2]);
            #pragma unroll
            for (int mt = 0; mt < 2; mt++)
                #pragma unroll
                for (int nt = 0; nt < 8; nt++)
                    mma16816(acc[mt][nt], aH[mt], &bL[nt >> 1][(nt & 1) * 2]);
            #pragma unroll
            for (int mt = 0; mt < 2; mt++)
                #pragma unroll
                for (int nt = 0; nt < 8; nt++)
                    mma16816(acc[mt][nt], aL[mt], &bH[nt >> 1][(nt & 1) * 2]);
        }
        __syncthreads();   // sA reads done before overwrite with h

        // ---- epilogue 1: h = swish(C + b1), split -> sA hi/lo ----
        #pragma unroll
        for (int mt = 0; mt < 2; mt++)
            #pragma unroll
            for (int nt = 0; nt < 8; nt++) {
                int col = wn + nt * 8 + cbase;
                float g0 = __ldg(b1 + col), g1 = __ldg(b1 + col + 1);
                #pragma unroll
                for (int hh = 0; hh < 2; hh++) {
                    int row = wm + mt * 16 + rbase + hh * 8;
                    float v0 = swish_f(acc[mt][nt][2 * hh]     + g0);
                    float v1 = swish_f(acc[mt][nt][2 * hh + 1] + g1);
                    float h0 = __bfloat162float(__float2bfloat16(v0));
                    float h1 = __bfloat162float(__float2bfloat16(v1));
                    uint32_t o = (row * LDA + col) * 2;
                    *reinterpret_cast<uint32_t*>(smc + SA_HI + o) = pack_bf(v0, v1);
                    *reinterpret_cast<uint32_t*>(smc + SA_LO + o) =
                        pack_bf(v0 - h0, v1 - h1);
                }
            }
        __syncthreads();

        // ======== layer2: q[128][32] = h @ W2 ========
        float acc2[4][4];
        #pragma unroll
        for (int nt = 0; nt < 4; nt++)
            #pragma unroll
            for (int r = 0; r < 4; r++) acc2[nt][r] = 0.f;

        #pragma unroll
        for (int ks = 0; ks < 8; ks++) {
            const int k0 = ks << 4;
            uint32_t aH[4], aL[4];
            uint32_t offa = ((m0 + arow) * LDA + k0 + ac8) * 2;
            ldsm_x4(aH, sb + SA_HI + offa);
            ldsm_x4(aL, sb + SA_LO + offa);
            uint32_t bH[2][4], bL[2][4];
            #pragma unroll
            for (int g = 0; g < 2; g++) {
                uint32_t off = ((k0 + arow) * LDB2 + g * 16 + ac8) * 2;
                ldsm_x4t(bH[g], sb + SB2_HI + off);
                ldsm_x4t(bL[g], sb + SB2_LO + off);
            }
            // term-major order (reuse distance 4)
            #pragma unroll
            for (int nt = 0; nt < 4; nt++)
                mma16816(acc2[nt], aH, &bH[nt >> 1][(nt & 1) * 2]);
            #pragma unroll
            for (int nt = 0; nt < 4; nt++)
                mma16816(acc2[nt], aH, &bL[nt >> 1][(nt & 1) * 2]);
            #pragma unroll
            for (int nt = 0; nt < 4; nt++)
                mma16816(acc2[nt], aL, &bH[nt >> 1][(nt & 1) * 2]);
        }

        // ---- epilogue 2: q = swish(C2 + b2) -> gmem ----
        #pragma unroll
        for (int nt = 0; nt < 4; nt++) {
            int col = nt * 8 + cbase;
            float g0 = __ldg(b2 + col), g1 = __ldg(b2 + col + 1);
            #pragma unroll
            for (int hh = 0; hh < 2; hh++) {
                int row = row0 + m0 + rbase + hh * 8;
                if (row < nrows) {
                    float* qp = q_out + (size_t)row * DDIM + col;
                    qp[0] = swish_f(acc2[nt][2 * hh]     + g0);
                    qp[1] = swish_f(acc2[nt][2 * hh + 1] + g1);
                }
            }
        }
        // loop-top __syncthreads() protects sA before next conversion
    }
}

// ---------------- CSR build ----------------
__global__ void zero_cnt_kernel(int n) {
    int i = blockIdx.x * blockDim.x + threadIdx.x;
    if (i < n) g_cnt[i] = 0;
}

__global__ void count_kernel(const int* __restrict__ dst,
                             const float* __restrict__ rij, int E) {
    int e = (blockIdx.x * blockDim.x + threadIdx.x) * 2;
    if (e + 1 < E) {
        float2 r2 = *reinterpret_cast<const float2*>(rij + e);
        int2   d2 = *reinterpret_cast<const int2*>(dst + e);
        if (r2.x < CUT) atomicAdd(&g_cnt[d2.x], 1);
        if (r2.y < CUT) atomicAdd(&g_cnt[d2.y], 1);
    } else if (e < E) {
        if (rij[e] < CUT) atomicAdd(&g_cnt[dst[e]], 1);
    }
}

__global__ void scan1_kernel(int n) {
    __shared__ int s[256];
    int base = blockIdx.x * 2048 + threadIdx.x * 8;
    int v[8];
    int sum = 0;
    #pragma unroll
    for (int j = 0; j < 8; j++) {
        int idx = base + j;
        int t = (idx < n) ? g_cnt[idx] : 0;
        v[j] = sum;
        sum += t;
    }
    s[threadIdx.x] = sum;
    __syncthreads();
    for (int off = 1; off < 256; off <<= 1) {
        int t = (threadIdx.x >= off) ? s[threadIdx.x - off] : 0;
        __syncthreads();
        s[threadIdx.x] += t;
        __syncthreads();
    }
    int excl = s[threadIdx.x] - sum;
    if (threadIdx.x == 255) g_bsum[blockIdx.x] = s[255];
    #pragma unroll
    for (int j = 0; j < 8; j++) {
        int idx = base + j;
        if (idx < n) g_off[idx] = excl + v[j];
    }
}

__global__ void scan2_kernel(int nb) {
    if (threadIdx.x == 0) {
        int a = 0;
        for (int i = 0; i < nb; i++) { int t = g_bsum[i]; g_bsum[i] = a; a += t; }
    }
}

__global__ void scan3_kernel(int n) {
    int i = blockIdx.x * blockDim.x + threadIdx.x;
    if (i < n) {
        int o = g_off[i] + g_bsum[i >> 11];
        g_off[i] = o;
        g_cur[i] = o;
    }
}

__global__ void scatter_kernel(const int* __restrict__ src,
                               const int* __restrict__ dst,
                               const float* __restrict__ rij,
                               const float* __restrict__ vij, int E) {
    int e = blockIdx.x * blockDim.x + threadIdx.x;
    if (e >= E) return;
    float r = rij[e];
    if (r < CUT) {
        float c = 0.5f * (cosf(PI_F * r / CUT) + 1.0f);
        int p = atomicAdd(&g_cur[dst[e]], 1);
        g_cwv[p] = make_float4(c * vij[3 * e], c * vij[3 * e + 1],
                               c * vij[3 * e + 2], __int_as_float(src[e]));
    }
}

// ---------------- gather + cross + mix, one warp per node, lane = d --------
__global__ __launch_bounds__(256) void gather_kernel(
    const float* __restrict__ wmix, const float* __restrict__ bmix,
    float* __restrict__ out, int nNodes)
{
    int gw   = (blockIdx.x * 256 + threadIdx.x) >> 5;
    int lane = threadIdx.x & 31;
    if (gw >= nNodes) return;

    int start = g_off[gw];
    int m     = g_cnt[gw];

    float ax = 0.f, ay = 0.f, az = 0.f;
    float bx = 0.f, by = 0.f, bz = 0.f;

    int i = 0;
    for (; i + 2 <= m; i += 2) {
        float4 w0 = __ldg(&g_cwv[start + i]);
        float4 w1 = __ldg(&g_cwv[start + i + 1]);
        int s0 = __float_as_int(w0.w);
        int s1 = __float_as_int(w1.w);
        float qa = __ldg(&g_q [s0 * DDIM + lane]);
        float pa = __ldg(&g_q2[s0 * DDIM + lane]);
        float qb = __ldg(&g_q [s1 * DDIM + lane]);
        float pb = __ldg(&g_q2[s1 * DDIM + lane]);
        ax = fmaf(w0.x, qa, ax); ax = fmaf(w1.x, qb, ax);
        ay = fmaf(w0.y, qa, ay); ay = fmaf(w1.y, qb, ay);
        az = fmaf(w0.z, qa, az); az = fmaf(w1.z, qb, az);
        bx = fmaf(w0.x, pa, bx); bx = fmaf(w1.x, pb, bx);
        by = fmaf(w0.y, pa, by); by = fmaf(w1.y, pb, by);
        bz = fmaf(w0.z, pa, bz); bz = fmaf(w1.z, pb, bz);
    }
    if (i < m) {
        float4 w0 = __ldg(&g_cwv[start + i]);
        int s0 = __float_as_int(w0.w);
        float qa = __ldg(&g_q [s0 * DDIM + lane]);
        float pa = __ldg(&g_q2[s0 * DDIM + lane]);
        ax = fmaf(w0.x, qa, ax);
        ay = fmaf(w0.y, qa, ay);
        az = fmaf(w0.z, qa, az);
        bx = fmaf(w0.x, pa, bx);
        by = fmaf(w0.y, pa, by);
        bz = fmaf(w0.z, pa, bz);
    }

    float m0 = __ldg(wmix), m1 = __ldg(wmix + 1), m2 = __ldg(wmix + 2);
    float bm = __ldg(bmix);

    float cx = ay * bz - az * by;
    float cy = az * bx - ax * bz;
    float cz = ax * by - ay * bx;

    size_t p = (size_t)gw * (DDIM * 3) + lane * 3;
    out[p + 0] = ax * m0 + bx * m1 + cx * m2 + bm;
    out[p + 1] = ay * m0 + by * m1 + cy * m2 + bm;
    out[p + 2] = az * m0 + bz * m1 + cz * m2 + bm;
}

// ---------------- launch ----------------
extern "C" void kernel_launch(void* const* d_in, const int* in_sizes, int n_in,
                              void* d_out, int out_size)
{
    const float* x    = (const float*)d_in[0];
    const float* rij  = (const float*)d_in[1];
    const float* vij  = (const float*)d_in[2];
    const int*   src  = (const int*)  d_in[3];
    const int*   dst  = (const int*)  d_in[4];
    const float* W1   = (const float*)d_in[5];
    const float* b1   = (const float*)d_in[6];
    const float* W2   = (const float*)d_in[7];
    const float* b2   = (const float*)d_in[8];
    const float* W1b  = (const float*)d_in[9];
    const float* b1b  = (const float*)d_in[10];
    const float* W2b  = (const float*)d_in[11];
    const float* b2b  = (const float*)d_in[12];
    const float* wmix = (const float*)d_in[13];
    const float* bmix = (const float*)d_in[14];
    float* out = (float*)d_out;

    int N = in_sizes[0] / FDIM;
    int E = in_sizes[1];
    if (N > NMAX) N = NMAX;
    if (E > EMAX) E = EMAX;

    cudaFuncSetAttribute(transform_kernel,
                         cudaFuncAttributeMaxDynamicSharedMemorySize, SM_TOTAL);

    int gE = (E + 255) / 256;
    int gN = (N + 255) / 256;
    int nb = (N + 2047) / 2048;
    int ntiles = (N + 127) / 128;

    // fork: CSR chain on side stream, transform chain on capture stream
    cudaStream_t s2;
    cudaStreamCreateWithFlags(&s2, cudaStreamNonBlocking);
    cudaEvent_t evFork, evJoin;
    cudaEventCreateWithFlags(&evFork, cudaEventDisableTiming);
    cudaEventCreateWithFlags(&evJoin, cudaEventDisableTiming);

    cudaEventRecord(evFork, 0);
    cudaStreamWaitEvent(s2, evFork, 0);

    // ---- side stream: CSR build ----
    zero_cnt_kernel<<<gN, 256, 0, s2>>>(N);
    count_kernel<<<(E / 2 + 255) / 256, 256, 0, s2>>>(dst, rij, E);
    scan1_kernel<<<nb, 256, 0, s2>>>(N);
    scan2_kernel<<<1, 32, 0, s2>>>(nb);
    scan3_kernel<<<gN, 256, 0, s2>>>(N);
    scatter_kernel<<<gE, 256, 0, s2>>>(src, dst, rij, vij, E);
    cudaEventRecord(evJoin, s2);

    // ---- capture stream: persistent transform ----
    dim3 gT(PERSIST_X, 2);
    transform_kernel<<<gT, 256, SM_TOTAL>>>(x, W1, b1, W2, b2,
                                            W1b, b1b, W2b, b2b, N, ntiles);

    // join, then gather
    cudaStreamWaitEvent(0, evJoin, 0);
    int gG = (N * 32 + 255) / 256;
    gather_kernel<<<gG, 256>>>(wmix, bmix, out, N);

    cudaEventDestroy(evFork);
    cudaEventDestroy(evJoin);
    cudaStreamDestroy(s2);
}

// round 11
// speedup vs baseline: 3.0213x; 1.1408x over previous
#include <cuda_runtime.h>
#include <cuda_bf16.h>
#include <cstdint>

#define NMAX   50000
#define EMAX   800000
#define FDIM   128
#define DDIM   32
#define CUT    5.0f
#define PI_F   3.14159265358979323846f

// ---------------- device scratch (static, allocation-free) ----------------
__device__ float  g_q [NMAX * DDIM];
__device__ float  g_q2[NMAX * DDIM];
__device__ int    g_cnt[NMAX];
__device__ int    g_off[NMAX];
__device__ int    g_cur[NMAX];
__device__ int    g_bsum[64];
__device__ float4 g_cwv[EMAX];

// swish via tanh.approx: v*sigmoid(v) = 0.5v*(1+tanh(0.5v)); 1 MUFU.
__device__ __forceinline__ float swish_f(float v) {
    float t, h = 0.5f * v;
    asm("tanh.approx.f32 %0, %1;" : "=f"(t) : "f"(h));
    return fmaf(h, t, h);
}

// ---------------- helpers (baseline PTX only) -----------------------------
__device__ __forceinline__ uint32_t smem_u32(const void* p) {
    uint32_t a;
    asm("{ .reg .u64 t; cvta.to.shared.u64 t, %1; cvt.u32.u64 %0, t; }"
        : "=r"(a) : "l"(p));
    return a;
}
__device__ __forceinline__ void ldsm_x4(uint32_t* r, uint32_t addr) {
    asm volatile("ldmatrix.sync.aligned.m8n8.x4.shared.b16 {%0,%1,%2,%3}, [%4];"
                 : "=r"(r[0]), "=r"(r[1]), "=r"(r[2]), "=r"(r[3]) : "r"(addr));
}
__device__ __forceinline__ void ldsm_x4t(uint32_t* r, uint32_t addr) {
    asm volatile("ldmatrix.sync.aligned.m8n8.x4.trans.shared.b16 {%0,%1,%2,%3}, [%4];"
                 : "=r"(r[0]), "=r"(r[1]), "=r"(r[2]), "=r"(r[3]) : "r"(addr));
}
__device__ __forceinline__ void mma16816(float* c, const uint32_t* a,
                                         const uint32_t* b) {
    asm volatile(
        "mma.sync.aligned.m16n8k16.row.col.f32.bf16.bf16.f32 "
        "{%0,%1,%2,%3}, {%4,%5,%6,%7}, {%8,%9}, {%0,%1,%2,%3};"
        : "+f"(c[0]), "+f"(c[1]), "+f"(c[2]), "+f"(c[3])
        : "r"(a[0]), "r"(a[1]), "r"(a[2]), "r"(a[3]), "r"(b[0]), "r"(b[1]));
}
// packed rn convert: lo -> low half, hi -> high half (same rounding as before)
__device__ __forceinline__ uint32_t cvt2_bf(float lo, float hi) {
    uint32_t r;
    asm("cvt.rn.bf16x2.f32 %0, %1, %2;" : "=r"(r) : "f"(hi), "f"(lo));
    return r;
}
// split float4 -> packed hi uint2 / lo uint2 (bit-identical to scalar split)
__device__ __forceinline__ void split4(float4 v, uint2& hv, uint2& lv) {
    uint32_t h01 = cvt2_bf(v.x, v.y);
    uint32_t h23 = cvt2_bf(v.z, v.w);
    float hx = __uint_as_float(h01 << 16);
    float hy = __uint_as_float(h01 & 0xFFFF0000u);
    float hz = __uint_as_float(h23 << 16);
    float hw = __uint_as_float(h23 & 0xFFFF0000u);
    hv = make_uint2(h01, h23);
    lv = make_uint2(cvt2_bf(v.x - hx, v.y - hy), cvt2_bf(v.z - hz, v.w - hw));
}

// smem layout (bf16, padded strides for conflict-free ldmatrix)
#define LDA   136
#define LDB2  40
#define SA_HI  0
#define SA_LO  (SA_HI  + 128 * LDA * 2)
#define SB1_HI (SA_LO  + 128 * LDA * 2)
#define SB1_LO (SB1_HI + 128 * LDA * 2)
#define SB2_HI (SB1_LO + 128 * LDA * 2)
#define SB2_LO (SB2_HI + 128 * LDB2 * 2)
#define SM_TOTAL (SB2_LO + 128 * LDB2 * 2)   // 159744 bytes

#define PERSIST_X 74   // blocks per branch (one per SM, 2 branches -> 148)

// ==== persistent node transform: weights converted once, tiles looped =====
__global__ __launch_bounds__(256, 1) void transform_kernel(
    const float* __restrict__ x,
    const float* __restrict__ W1a, const float* __restrict__ b1a,
    const float* __restrict__ W2a, const float* __restrict__ b2a,
    const float* __restrict__ W1b, const float* __restrict__ b1b,
    const float* __restrict__ W2b, const float* __restrict__ b2b,
    int nrows, int ntiles)
{
    extern __shared__ char smc[];
    const uint32_t sb = smem_u32(smc);

    const int branch = blockIdx.y;
    const float* W1 = branch ? W1b : W1a;
    const float* b1 = branch ? b1b : b1a;
    const float* W2 = branch ? W2b : W2a;
    const float* b2 = branch ? b2b : b2a;
    float* q_out = branch ? g_q2 : g_q;

    const int tid  = threadIdx.x;
    const int wid  = tid >> 5;
    const int lane = tid & 31;

    // ---- convert weights once: W1 -> SB1 hi/lo, W2 -> SB2 hi/lo ----
    for (int i = tid; i < 4096; i += 256) {
        int k = i >> 5, c4 = (i & 31) << 2;
        uint2 hv, lv;
        split4(*reinterpret_cast<const float4*>(W1 + k * 128 + c4), hv, lv);
        *reinterpret_cast<uint2*>(smc + SB1_HI + (k * LDA + c4) * 2) = hv;
        *reinterpret_cast<uint2*>(smc + SB1_LO + (k * LDA + c4) * 2) = lv;
    }
    for (int i = tid; i < 1024; i += 256) {
        int k = i >> 3, c4 = (i & 7) << 2;
        uint2 hv, lv;
        split4(*reinterpret_cast<const float4*>(W2 + k * 32 + c4), hv, lv);
        *reinterpret_cast<uint2*>(smc + SB2_HI + (k * LDB2 + c4) * 2) = hv;
        *reinterpret_cast<uint2*>(smc + SB2_LO + (k * LDB2 + c4) * 2) = lv;
    }

    const int wm = (wid & 3) * 32;
    const int wn = (wid >> 2) * 64;
    const int arow = lane & 15, ac8 = (lane >> 4) << 3;
    const int rbase = lane >> 2;
    const int cbase = (lane & 3) << 1;
    const int m0 = wid << 4;

    for (int t = blockIdx.x; t < ntiles; t += PERSIST_X) {
        const int row0 = t * 128;

        // ---- convert x tile fp32 -> sA hi/lo ----
        __syncthreads();   // prior iteration's MMA2 reads of sA done
        for (int i = tid; i < 2048; i += 256) {
            int r = i >> 4, c4 = (i & 15) << 3;   // 8 floats per iter
            int row = row0 + r;
            float4 v0 = make_float4(0.f, 0.f, 0.f, 0.f);
            float4 v1 = v0;
            if (row < nrows) {
                const float* xp = x + (size_t)row * 128 + c4;
                v0 = *reinterpret_cast<const float4*>(xp);
                v1 = *reinterpret_cast<const float4*>(xp + 4);
            }
            uint2 h0, l0, h1, l1;
            split4(v0, h0, l0);
            split4(v1, h1, l1);
            uint32_t o = (r * LDA + c4) * 2;
            *reinterpret_cast<uint4*>(smc + SA_HI + o) =
                make_uint4(h0.x, h0.y, h1.x, h1.y);
            *reinterpret_cast<uint4*>(smc + SA_LO + o) =
                make_uint4(l0.x, l0.y, l1.x, l1.y);
        }
        __syncthreads();

        // ======== layer1: C[128][128] = x @ W1 ========
        float acc[2][8][4];
        #pragma unroll
        for (int mt = 0; mt < 2; mt++)
            #pragma unroll
            for (int nt = 0; nt < 8; nt++)
                #pragma unroll
                for (int r = 0; r < 4; r++) acc[mt][nt][r] = 0.f;

        #pragma unroll
        for (int ks = 0; ks < 8; ks++) {
            const int k0 = ks << 4;
            uint32_t aH[2][4], aL[2][4];
            #pragma unroll
            for (int mt = 0; mt < 2; mt++) {
                uint32_t off = ((wm + mt * 16 + arow) * LDA + k0 + ac8) * 2;
                ldsm_x4(aH[mt], sb + SA_HI + off);
                ldsm_x4(aL[mt], sb + SA_LO + off);
            }
            uint32_t bH[4][4], bL[4][4];
            #pragma unroll
            for (int g = 0; g < 4; g++) {
                uint32_t off = ((k0 + arow) * LDA + wn + g * 16 + ac8) * 2;
                ldsm_x4t(bH[g], sb + SB1_HI + off);
                ldsm_x4t(bL[g], sb + SB1_LO + off);
            }
            #pragma unroll
            for (int mt = 0; mt < 2; mt++)
                #pragma unroll
                for (int nt = 0; nt < 8; nt++)
                    mma16816(acc[mt][nt], aH[mt], &bH[nt >> 1][(nt & 1) * 2]);
            #pragma unroll
            for (int mt = 0; mt < 2; mt++)
                #pragma unroll
                for (int nt = 0; nt < 8; nt++)
                    mma16816(acc[mt][nt], aH[mt], &bL[nt >> 1][(nt & 1) * 2]);
            #pragma unroll
            for (int mt = 0; mt < 2; mt++)
                #pragma unroll
                for (int nt = 0; nt < 8; nt++)
                    mma16816(acc[mt][nt], aL[mt], &bH[nt >> 1][(nt & 1) * 2]);
        }
        __syncthreads();   // sA reads done before overwrite with h

        // ---- epilogue 1: h = swish(C + b1), split -> sA hi/lo ----
        #pragma unroll
        for (int mt = 0; mt < 2; mt++)
            #pragma unroll
            for (int nt = 0; nt < 8; nt++) {
                int col = wn + nt * 8 + cbase;
                float g0 = __ldg(b1 + col), g1 = __ldg(b1 + col + 1);
                #pragma unroll
                for (int hh = 0; hh < 2; hh++) {
                    int row = wm + mt * 16 + rbase + hh * 8;
                    float v0 = swish_f(acc[mt][nt][2 * hh]     + g0);
                    float v1 = swish_f(acc[mt][nt][2 * hh + 1] + g1);
                    uint32_t hp = cvt2_bf(v0, v1);
                    float h0 = __uint_as_float(hp << 16);
                    float h1 = __uint_as_float(hp & 0xFFFF0000u);
                    uint32_t o = (row * LDA + col) * 2;
                    *reinterpret_cast<uint32_t*>(smc + SA_HI + o) = hp;
                    *reinterpret_cast<uint32_t*>(smc + SA_LO + o) =
                        cvt2_bf(v0 - h0, v1 - h1);
                }
            }
        __syncthreads();

        // ======== layer2: q[128][32] = h @ W2 ========
        float acc2[4][4];
        #pragma unroll
        for (int nt = 0; nt < 4; nt++)
            #pragma unroll
            for (int r = 0; r < 4; r++) acc2[nt][r] = 0.f;

        #pragma unroll
        for (int ks = 0; ks < 8; ks++) {
            const int k0 = ks << 4;
            uint32_t aH[4], aL[4];
            uint32_t offa = ((m0 + arow) * LDA + k0 + ac8) * 2;
            ldsm_x4(aH, sb + SA_HI + offa);
            ldsm_x4(aL, sb + SA_LO + offa);
            uint32_t bH[2][4], bL[2][4];
            #pragma unroll
            for (int g = 0; g < 2; g++) {
                uint32_t off = ((k0 + arow) * LDB2 + g * 16 + ac8) * 2;
                ldsm_x4t(bH[g], sb + SB2_HI + off);
                ldsm_x4t(bL[g], sb + SB2_LO + off);
            }
            #pragma unroll
            for (int nt = 0; nt < 4; nt++)
                mma16816(acc2[nt], aH, &bH[nt >> 1][(nt & 1) * 2]);
            #pragma unroll
            for (int nt = 0; nt < 4; nt++)
                mma16816(acc2[nt], aH, &bL[nt >> 1][(nt & 1) * 2]);
            #pragma unroll
            for (int nt = 0; nt < 4; nt++)
                mma16816(acc2[nt], aL, &bH[nt >> 1][(nt & 1) * 2]);
        }

        // ---- epilogue 2: q = swish(C2 + b2) -> gmem (float2 stores) ----
        #pragma unroll
        for (int nt = 0; nt < 4; nt++) {
            int col = nt * 8 + cbase;
            float g0 = __ldg(b2 + col), g1 = __ldg(b2 + col + 1);
            #pragma unroll
            for (int hh = 0; hh < 2; hh++) {
                int row = row0 + m0 + rbase + hh * 8;
                if (row < nrows) {
                    float2 o2;
                    o2.x = swish_f(acc2[nt][2 * hh]     + g0);
                    o2.y = swish_f(acc2[nt][2 * hh + 1] + g1);
                    *reinterpret_cast<float2*>(q_out + (size_t)row * DDIM + col) = o2;
                }
            }
        }
        // loop-top __syncthreads() protects sA before next conversion
    }
}

// ---------------- CSR build ----------------
__global__ void zero_cnt_kernel(int n) {
    int i = blockIdx.x * blockDim.x + threadIdx.x;
    if (i < n) g_cnt[i] = 0;
}

__global__ void count_kernel(const int* __restrict__ dst,
                             const float* __restrict__ rij, int E) {
    int e = (blockIdx.x * blockDim.x + threadIdx.x) * 2;
    if (e + 1 < E) {
        float2 r2 = *reinterpret_cast<const float2*>(rij + e);
        int2   d2 = *reinterpret_cast<const int2*>(dst + e);
        if (r2.x < CUT) atomicAdd(&g_cnt[d2.x], 1);
        if (r2.y < CUT) atomicAdd(&g_cnt[d2.y], 1);
    } else if (e < E) {
        if (rij[e] < CUT) atomicAdd(&g_cnt[dst[e]], 1);
    }
}

__global__ void scan1_kernel(int n) {
    __shared__ int s[256];
    int base = blockIdx.x * 2048 + threadIdx.x * 8;
    int v[8];
    int sum = 0;
    #pragma unroll
    for (int j = 0; j < 8; j++) {
        int idx = base + j;
        int t = (idx < n) ? g_cnt[idx] : 0;
        v[j] = sum;
        sum += t;
    }
    s[threadIdx.x] = sum;
    __syncthreads();
    for (int off = 1; off < 256; off <<= 1) {
        int t = (threadIdx.x >= off) ? s[threadIdx.x - off] : 0;
        __syncthreads();
        s[threadIdx.x] += t;
        __syncthreads();
    }
    int excl = s[threadIdx.x] - sum;
    if (threadIdx.x == 255) g_bsum[blockIdx.x] = s[255];
    #pragma unroll
    for (int j = 0; j < 8; j++) {
        int idx = base + j;
        if (idx < n) g_off[idx] = excl + v[j];
    }
}

__global__ void scan2_kernel(int nb) {
    if (threadIdx.x == 0) {
        int a = 0;
        for (int i = 0; i < nb; i++) { int t = g_bsum[i]; g_bsum[i] = a; a += t; }
    }
}

__global__ void scan3_kernel(int n) {
    int i = blockIdx.x * blockDim.x + threadIdx.x;
    if (i < n) {
        int o = g_off[i] + g_bsum[i >> 11];
        g_off[i] = o;
        g_cur[i] = o;
    }
}

__global__ void scatter_kernel(const int* __restrict__ src,
                               const int* __restrict__ dst,
                               const float* __restrict__ rij,
                               const float* __restrict__ vij, int E) {
    int e = blockIdx.x * blockDim.x + threadIdx.x;
    if (e >= E) return;
    float r = rij[e];
    if (r < CUT) {
        float c = 0.5f * (cosf(PI_F * r / CUT) + 1.0f);
        int p = atomicAdd(&g_cur[dst[e]], 1);
        g_cwv[p] = make_float4(c * vij[3 * e], c * vij[3 * e + 1],
                               c * vij[3 * e + 2], __int_as_float(src[e]));
    }
}

// ---------------- gather + cross + mix, one warp per node, lane = d --------
__global__ __launch_bounds__(256) void gather_kernel(
    const float* __restrict__ wmix, const float* __restrict__ bmix,
    float* __restrict__ out, int nNodes)
{
    int gw   = (blockIdx.x * 256 + threadIdx.x) >> 5;
    int lane = threadIdx.x & 31;
    if (gw >= nNodes) return;

    int start = g_off[gw];
    int m     = g_cnt[gw];

    float ax = 0.f, ay = 0.f, az = 0.f;
    float bx = 0.f, by = 0.f, bz = 0.f;

    int i = 0;
    for (; i + 4 <= m; i += 4) {
        float4 w0 = __ldg(&g_cwv[start + i]);
        float4 w1 = __ldg(&g_cwv[start + i + 1]);
        float4 w2 = __ldg(&g_cwv[start + i + 2]);
        float4 w3 = __ldg(&g_cwv[start + i + 3]);
        int s0 = __float_as_int(w0.w);
        int s1 = __float_as_int(w1.w);
        int s2 = __float_as_int(w2.w);
        int s3 = __float_as_int(w3.w);
        float qa = __ldg(&g_q [s0 * DDIM + lane]);
        float qb = __ldg(&g_q [s1 * DDIM + lane]);
        float qc = __ldg(&g_q [s2 * DDIM + lane]);
        float qd = __ldg(&g_q [s3 * DDIM + lane]);
        float pa = __ldg(&g_q2[s0 * DDIM + lane]);
        float pb = __ldg(&g_q2[s1 * DDIM + lane]);
        float pc = __ldg(&g_q2[s2 * DDIM + lane]);
        float pd = __ldg(&g_q2[s3 * DDIM + lane]);
        ax = fmaf(w0.x, qa, ax); ax = fmaf(w1.x, qb, ax);
        ax = fmaf(w2.x, qc, ax); ax = fmaf(w3.x, qd, ax);
        ay = fmaf(w0.y, qa, ay); ay = fmaf(w1.y, qb, ay);
        ay = fmaf(w2.y, qc, ay); ay = fmaf(w3.y, qd, ay);
        az = fmaf(w0.z, qa, az); az = fmaf(w1.z, qb, az);
        az = fmaf(w2.z, qc, az); az = fmaf(w3.z, qd, az);
        bx = fmaf(w0.x, pa, bx); bx = fmaf(w1.x, pb, bx);
        bx = fmaf(w2.x, pc, bx); bx = fmaf(w3.x, pd, bx);
        by = fmaf(w0.y, pa, by); by = fmaf(w1.y, pb, by);
        by = fmaf(w2.y, pc, by); by = fmaf(w3.y, pd, by);
        bz = fmaf(w0.z, pa, bz); bz = fmaf(w1.z, pb, bz);
        bz = fmaf(w2.z, pc, bz); bz = fmaf(w3.z, pd, bz);
    }
    for (; i < m; i++) {
        float4 w0 = __ldg(&g_cwv[start + i]);
        int s0 = __float_as_int(w0.w);
        float qa = __ldg(&g_q [s0 * DDIM + lane]);
        float pa = __ldg(&g_q2[s0 * DDIM + lane]);
        ax = fmaf(w0.x, qa, ax);
        ay = fmaf(w0.y, qa, ay);
        az = fmaf(w0.z, qa, az);
        bx = fmaf(w0.x, pa, bx);
        by = fmaf(w0.y, pa, by);
        bz = fmaf(w0.z, pa, bz);
    }

    float m0 = __ldg(wmix), m1 = __ldg(wmix + 1), m2 = __ldg(wmix + 2);
    float bm = __ldg(bmix);

    float cx = ay * bz - az * by;
    float cy = az * bx - ax * bz;
    float cz = ax * by - ay * bx;

    size_t p = (size_t)gw * (DDIM * 3) + lane * 3;
    out[p + 0] = ax * m0 + bx * m1 + cx * m2 + bm;
    out[p + 1] = ay * m0 + by * m1 + cy * m2 + bm;
    out[p + 2] = az * m0 + bz * m1 + cz * m2 + bm;
}

// ---------------- launch ----------------
extern "C" void kernel_launch(void* const* d_in, const int* in_sizes, int n_in,
                              void* d_out, int out_size)
{
    const float* x    = (const float*)d_in[0];
    const float* rij  = (const float*)d_in[1];
    const float* vij  = (const float*)d_in[2];
    const int*   src  = (const int*)  d_in[3];
    const int*   dst  = (const int*)  d_in[4];
    const float* W1   = (const float*)d_in[5];
    const float* b1   = (const float*)d_in[6];
    const float* W2   = (const float*)d_in[7];
    const float* b2   = (const float*)d_in[8];
    const float* W1b  = (const float*)d_in[9];
    const float* b1b  = (const float*)d_in[10];
    const float* W2b  = (const float*)d_in[11];
    const float* b2b  = (const float*)d_in[12];
    const float* wmix = (const float*)d_in[13];
    const float* bmix = (const float*)d_in[14];
    float* out = (float*)d_out;

    int N = in_sizes[0] / FDIM;
    int E = in_sizes[1];
    if (N > NMAX) N = NMAX;
    if (E > EMAX) E = EMAX;

    cudaFuncSetAttribute(transform_kernel,
                         cudaFuncAttributeMaxDynamicSharedMemorySize, SM_TOTAL);

    int gE = (E + 255) / 256;
    int gN = (N + 255) / 256;
    int nb = (N + 2047) / 2048;
    int ntiles = (N + 127) / 128;

    // fork: CSR chain on side stream, transform chain on capture stream
    cudaStream_t s2;
    cudaStreamCreateWithFlags(&s2, cudaStreamNonBlocking);
    cudaEvent_t evFork, evJoin;
    cudaEventCreateWithFlags(&evFork, cudaEventDisableTiming);
    cudaEventCreateWithFlags(&evJoin, cudaEventDisableTiming);

    cudaEventRecord(evFork, 0);
    cudaStreamWaitEvent(s2, evFork, 0);

    // ---- side stream: CSR build ----
    zero_cnt_kernel<<<gN, 256, 0, s2>>>(N);
    count_kernel<<<(E / 2 + 255) / 256, 256, 0, s2>>>(dst, rij, E);
    scan1_kernel<<<nb, 256, 0, s2>>>(N);
    scan2_kernel<<<1, 32, 0, s2>>>(nb);
    scan3_kernel<<<gN, 256, 0, s2>>>(N);
    scatter_kernel<<<gE, 256, 0, s2>>>(src, dst, rij, vij, E);
    cudaEventRecord(evJoin, s2);

    // ---- capture stream: persistent transform ----
    dim3 gT(PERSIST_X, 2);
    transform_kernel<<<gT, 256, SM_TOTAL>>>(x, W1, b1, W2, b2,
                                            W1b, b1b, W2b, b2b, N, ntiles);

    // join, then gather
    cudaStreamWaitEvent(0, evJoin, 0);
    int gG = (N * 32 + 255) / 256;
    gather_kernel<<<gG, 256>>>(wmix, bmix, out, N);

    cudaEventDestroy(evFork);
    cudaEventDestroy(evJoin);
    cudaStreamDestroy(s2);
}

// round 12
// speedup vs baseline: 3.2148x; 1.0640x over previous
#include <cuda_runtime.h>
#include <cuda_bf16.h>
#include <cstdint>

#define NMAX   50000
#define EMAX   800000
#define FDIM   128
#define DDIM   32
#define CUT    5.0f
#define PI_F   3.14159265358979323846f

// ---------------- device scratch (static, allocation-free) ----------------
__device__ float  g_q [NMAX * DDIM];
__device__ float  g_q2[NMAX * DDIM];
__device__ int    g_cnt[NMAX];
__device__ int    g_off[NMAX];
__device__ int    g_cur[NMAX];
__device__ int    g_bsum[64];
__device__ float4 g_cwv[EMAX];

// swish via tanh.approx: v*sigmoid(v) = 0.5v*(1+tanh(0.5v)); 1 MUFU.
__device__ __forceinline__ float swish_f(float v) {
    float t, h = 0.5f * v;
    asm("tanh.approx.f32 %0, %1;" : "=f"(t) : "f"(h));
    return fmaf(h, t, h);
}

// ---------------- helpers (baseline PTX only) -----------------------------
__device__ __forceinline__ uint32_t smem_u32(const void* p) {
    uint32_t a;
    asm("{ .reg .u64 t; cvta.to.shared.u64 t, %1; cvt.u32.u64 %0, t; }"
        : "=r"(a) : "l"(p));
    return a;
}
__device__ __forceinline__ void ldsm_x4(uint32_t* r, uint32_t addr) {
    asm volatile("ldmatrix.sync.aligned.m8n8.x4.shared.b16 {%0,%1,%2,%3}, [%4];"
                 : "=r"(r[0]), "=r"(r[1]), "=r"(r[2]), "=r"(r[3]) : "r"(addr));
}
__device__ __forceinline__ void ldsm_x4t(uint32_t* r, uint32_t addr) {
    asm volatile("ldmatrix.sync.aligned.m8n8.x4.trans.shared.b16 {%0,%1,%2,%3}, [%4];"
                 : "=r"(r[0]), "=r"(r[1]), "=r"(r[2]), "=r"(r[3]) : "r"(addr));
}
__device__ __forceinline__ void mma16816(float* c, const uint32_t* a,
                                         const uint32_t* b) {
    asm volatile(
        "mma.sync.aligned.m16n8k16.row.col.f32.bf16.bf16.f32 "
        "{%0,%1,%2,%3}, {%4,%5,%6,%7}, {%8,%9}, {%0,%1,%2,%3};"
        : "+f"(c[0]), "+f"(c[1]), "+f"(c[2]), "+f"(c[3])
        : "r"(a[0]), "r"(a[1]), "r"(a[2]), "r"(a[3]), "r"(b[0]), "r"(b[1]));
}
// packed rn convert: lo -> low half, hi -> high half
__device__ __forceinline__ uint32_t cvt2_bf(float lo, float hi) {
    uint32_t r;
    asm("cvt.rn.bf16x2.f32 %0, %1, %2;" : "=r"(r) : "f"(hi), "f"(lo));
    return r;
}
// split float4 -> packed hi uint2 / lo uint2
__device__ __forceinline__ void split4(float4 v, uint2& hv, uint2& lv) {
    uint32_t h01 = cvt2_bf(v.x, v.y);
    uint32_t h23 = cvt2_bf(v.z, v.w);
    float hx = __uint_as_float(h01 << 16);
    float hy = __uint_as_float(h01 & 0xFFFF0000u);
    float hz = __uint_as_float(h23 << 16);
    float hw = __uint_as_float(h23 & 0xFFFF0000u);
    hv = make_uint2(h01, h23);
    lv = make_uint2(cvt2_bf(v.x - hx, v.y - hy), cvt2_bf(v.z - hz, v.w - hw));
}

// smem layout (bf16, padded strides for conflict-free ldmatrix)
#define LDA   136
#define LDB2  40
#define SA_HI  0
#define SA_LO  (SA_HI  + 128 * LDA * 2)
#define SB1_HI (SA_LO  + 128 * LDA * 2)
#define SB1_LO (SB1_HI + 128 * LDA * 2)
#define SB2_HI (SB1_LO + 128 * LDA * 2)
#define SB2_LO (SB2_HI + 128 * LDB2 * 2)
#define SM_TOTAL (SB2_LO + 128 * LDB2 * 2)   // 159744 bytes

#define PERSIST_X 74   // blocks per branch (one per SM, 2 branches -> 148)
#define TTHREADS  512

// ==== persistent node transform, 512 threads (16 warps) ====================
__global__ __launch_bounds__(TTHREADS, 1) void transform_kernel(
    const float* __restrict__ x,
    const float* __restrict__ W1a, const float* __restrict__ b1a,
    const float* __restrict__ W2a, const float* __restrict__ b2a,
    const float* __restrict__ W1b, const float* __restrict__ b1b,
    const float* __restrict__ W2b, const float* __restrict__ b2b,
    int nrows, int ntiles)
{
    extern __shared__ char smc[];
    const uint32_t sb = smem_u32(smc);

    const int branch = blockIdx.y;
    const float* W1 = branch ? W1b : W1a;
    const float* b1 = branch ? b1b : b1a;
    const float* W2 = branch ? W2b : W2a;
    const float* b2 = branch ? b2b : b2a;
    float* q_out = branch ? g_q2 : g_q;

    const int tid  = threadIdx.x;
    const int wid  = tid >> 5;          // 0..15
    const int lane = tid & 31;

    // ---- convert weights once: W1 -> SB1 hi/lo, W2 -> SB2 hi/lo ----
    for (int i = tid; i < 4096; i += TTHREADS) {
        int k = i >> 5, c4 = (i & 31) << 2;
        uint2 hv, lv;
        split4(*reinterpret_cast<const float4*>(W1 + k * 128 + c4), hv, lv);
        *reinterpret_cast<uint2*>(smc + SB1_HI + (k * LDA + c4) * 2) = hv;
        *reinterpret_cast<uint2*>(smc + SB1_LO + (k * LDA + c4) * 2) = lv;
    }
    for (int i = tid; i < 1024; i += TTHREADS) {
        int k = i >> 3, c4 = (i & 7) << 2;
        uint2 hv, lv;
        split4(*reinterpret_cast<const float4*>(W2 + k * 32 + c4), hv, lv);
        *reinterpret_cast<uint2*>(smc + SB2_HI + (k * LDB2 + c4) * 2) = hv;
        *reinterpret_cast<uint2*>(smc + SB2_LO + (k * LDB2 + c4) * 2) = lv;
    }

    // layer1: warp tile 16 rows x 64 cols (16 warps cover 128x128)
    const int wm = (wid & 7) << 4;      // 0..112
    const int wn = (wid >> 3) << 6;     // 0 or 64
    // layer2: warp tile 16 rows x 16 cols
    const int m0 = (wid & 7) << 4;      // 0..112
    const int cg = (wid >> 3) << 4;     // 0 or 16
    const int arow = lane & 15, ac8 = (lane >> 4) << 3;
    const int rbase = lane >> 2;
    const int cbase = (lane & 3) << 1;

    for (int t = blockIdx.x; t < ntiles; t += PERSIST_X) {
        const int row0 = t * 128;

        // ---- convert x tile fp32 -> sA hi/lo ----
        __syncthreads();   // prior iteration's layer2 reads of sA done
        for (int i = tid; i < 2048; i += TTHREADS) {
            int r = i >> 4, c4 = (i & 15) << 3;
            int row = row0 + r;
            float4 v0 = make_float4(0.f, 0.f, 0.f, 0.f);
            float4 v1 = v0;
            if (row < nrows) {
                const float* xp = x + (size_t)row * 128 + c4;
                v0 = *reinterpret_cast<const float4*>(xp);
                v1 = *reinterpret_cast<const float4*>(xp + 4);
            }
            uint2 h0, l0, h1, l1;
            split4(v0, h0, l0);
            split4(v1, h1, l1);
            uint32_t o = (r * LDA + c4) * 2;
            *reinterpret_cast<uint4*>(smc + SA_HI + o) =
                make_uint4(h0.x, h0.y, h1.x, h1.y);
            *reinterpret_cast<uint4*>(smc + SA_LO + o) =
                make_uint4(l0.x, l0.y, l1.x, l1.y);
        }
        __syncthreads();

        // ======== layer1: C[128][128] = x @ W1 ========
        float acc[8][4];
        #pragma unroll
        for (int nt = 0; nt < 8; nt++)
            #pragma unroll
            for (int r = 0; r < 4; r++) acc[nt][r] = 0.f;

        #pragma unroll
        for (int ks = 0; ks < 8; ks++) {
            const int k0 = ks << 4;
            uint32_t aH[4], aL[4];
            {
                uint32_t off = ((wm + arow) * LDA + k0 + ac8) * 2;
                ldsm_x4(aH, sb + SA_HI + off);
                ldsm_x4(aL, sb + SA_LO + off);
            }
            uint32_t bH[4][4], bL[4][4];
            #pragma unroll
            for (int g = 0; g < 4; g++) {
                uint32_t off = ((k0 + arow) * LDA + wn + g * 16 + ac8) * 2;
                ldsm_x4t(bH[g], sb + SB1_HI + off);
                ldsm_x4t(bL[g], sb + SB1_LO + off);
            }
            // term-major (per-acc accumulation order: hh, hl, lh)
            #pragma unroll
            for (int nt = 0; nt < 8; nt++)
                mma16816(acc[nt], aH, &bH[nt >> 1][(nt & 1) * 2]);
            #pragma unroll
            for (int nt = 0; nt < 8; nt++)
                mma16816(acc[nt], aH, &bL[nt >> 1][(nt & 1) * 2]);
            #pragma unroll
            for (int nt = 0; nt < 8; nt++)
                mma16816(acc[nt], aL, &bH[nt >> 1][(nt & 1) * 2]);
        }
        __syncthreads();   // sA reads done before overwrite with h

        // ---- epilogue 1: h = swish(C + b1), split -> sA hi/lo ----
        #pragma unroll
        for (int nt = 0; nt < 8; nt++) {
            int col = wn + nt * 8 + cbase;
            float g0 = __ldg(b1 + col), g1 = __ldg(b1 + col + 1);
            #pragma unroll
            for (int hh = 0; hh < 2; hh++) {
                int row = wm + rbase + hh * 8;
                float v0 = swish_f(acc[nt][2 * hh]     + g0);
                float v1 = swish_f(acc[nt][2 * hh + 1] + g1);
                uint32_t hp = cvt2_bf(v0, v1);
                float h0 = __uint_as_float(hp << 16);
                float h1 = __uint_as_float(hp & 0xFFFF0000u);
                uint32_t o = (row * LDA + col) * 2;
                *reinterpret_cast<uint32_t*>(smc + SA_HI + o) = hp;
                *reinterpret_cast<uint32_t*>(smc + SA_LO + o) =
                    cvt2_bf(v0 - h0, v1 - h1);
            }
        }
        __syncthreads();

        // ======== layer2: q[128][32] = h @ W2; warp tile 16x16 ========
        float acc2[2][4];
        #pragma unroll
        for (int nt = 0; nt < 2; nt++)
            #pragma unroll
            for (int r = 0; r < 4; r++) acc2[nt][r] = 0.f;

        #pragma unroll
        for (int ks = 0; ks < 8; ks++) {
            const int k0 = ks << 4;
            uint32_t aH[4], aL[4];
            uint32_t offa = ((m0 + arow) * LDA + k0 + ac8) * 2;
            ldsm_x4(aH, sb + SA_HI + offa);
            ldsm_x4(aL, sb + SA_LO + offa);
            uint32_t bH[4], bL[4];
            {
                uint32_t off = ((k0 + arow) * LDB2 + cg + ac8) * 2;
                ldsm_x4t(bH, sb + SB2_HI + off);
                ldsm_x4t(bL, sb + SB2_LO + off);
            }
            #pragma unroll
            for (int nt = 0; nt < 2; nt++)
                mma16816(acc2[nt], aH, &bH[nt * 2]);
            #pragma unroll
            for (int nt = 0; nt < 2; nt++)
                mma16816(acc2[nt], aH, &bL[nt * 2]);
            #pragma unroll
            for (int nt = 0; nt < 2; nt++)
                mma16816(acc2[nt], aL, &bH[nt * 2]);
        }

        // ---- epilogue 2: q = swish(C2 + b2) -> gmem (float2 stores) ----
        #pragma unroll
        for (int nt = 0; nt < 2; nt++) {
            int col = cg + nt * 8 + cbase;
            float g0 = __ldg(b2 + col), g1 = __ldg(b2 + col + 1);
            #pragma unroll
            for (int hh = 0; hh < 2; hh++) {
                int row = row0 + m0 + rbase + hh * 8;
                if (row < nrows) {
                    float2 o2;
                    o2.x = swish_f(acc2[nt][2 * hh]     + g0);
                    o2.y = swish_f(acc2[nt][2 * hh + 1] + g1);
                    *reinterpret_cast<float2*>(q_out + (size_t)row * DDIM + col) = o2;
                }
            }
        }
        // loop-top __syncthreads() protects sA before next conversion
    }
}

// ---------------- CSR build ----------------
__global__ void zero_cnt_kernel(int n) {
    int i = blockIdx.x * blockDim.x + threadIdx.x;
    if (i < n) g_cnt[i] = 0;
}

__global__ void count_kernel(const int* __restrict__ dst,
                             const float* __restrict__ rij, int E) {
    int e = (blockIdx.x * blockDim.x + threadIdx.x) * 2;
    if (e + 1 < E) {
        float2 r2 = *reinterpret_cast<const float2*>(rij + e);
        int2   d2 = *reinterpret_cast<const int2*>(dst + e);
        if (r2.x < CUT) atomicAdd(&g_cnt[d2.x], 1);
        if (r2.y < CUT) atomicAdd(&g_cnt[d2.y], 1);
    } else if (e < E) {
        if (rij[e] < CUT) atomicAdd(&g_cnt[dst[e]], 1);
    }
}

__global__ void scan1_kernel(int n) {
    __shared__ int s[256];
    int base = blockIdx.x * 2048 + threadIdx.x * 8;
    int v[8];
    int sum = 0;
    #pragma unroll
    for (int j = 0; j < 8; j++) {
        int idx = base + j;
        int t = (idx < n) ? g_cnt[idx] : 0;
        v[j] = sum;
        sum += t;
    }
    s[threadIdx.x] = sum;
    __syncthreads();
    for (int off = 1; off < 256; off <<= 1) {
        int t = (threadIdx.x >= off) ? s[threadIdx.x - off] : 0;
        __syncthreads();
        s[threadIdx.x] += t;
        __syncthreads();
    }
    int excl = s[threadIdx.x] - sum;
    if (threadIdx.x == 255) g_bsum[blockIdx.x] = s[255];
    #pragma unroll
    for (int j = 0; j < 8; j++) {
        int idx = base + j;
        if (idx < n) g_off[idx] = excl + v[j];
    }
}

__global__ void scan2_kernel(int nb) {
    if (threadIdx.x == 0) {
        int a = 0;
        for (int i = 0; i < nb; i++) { int t = g_bsum[i]; g_bsum[i] = a; a += t; }
    }
}

__global__ void scan3_kernel(int n) {
    int i = blockIdx.x * blockDim.x + threadIdx.x;
    if (i < n) {
        int o = g_off[i] + g_bsum[i >> 11];
        g_off[i] = o;
        g_cur[i] = o;
    }
}

__global__ void scatter_kernel(const int* __restrict__ src,
                               const int* __restrict__ dst,
                               const float* __restrict__ rij,
                               const float* __restrict__ vij, int E) {
    int e = blockIdx.x * blockDim.x + threadIdx.x;
    if (e >= E) return;
    float r = rij[e];
    if (r < CUT) {
        float c = 0.5f * (cosf(PI_F * r / CUT) + 1.0f);
        int p = atomicAdd(&g_cur[dst[e]], 1);
        g_cwv[p] = make_float4(c * vij[3 * e], c * vij[3 * e + 1],
                               c * vij[3 * e + 2], __int_as_float(src[e]));
    }
}

// ---------------- gather + cross + mix, one warp per node, lane = d --------
__global__ __launch_bounds__(256) void gather_kernel(
    const float* __restrict__ wmix, const float* __restrict__ bmix,
    float* __restrict__ out, int nNodes)
{
    int gw   = (blockIdx.x * 256 + threadIdx.x) >> 5;
    int lane = threadIdx.x & 31;
    if (gw >= nNodes) return;

    int start = g_off[gw];
    int m     = g_cnt[gw];

    float ax = 0.f, ay = 0.f, az = 0.f;
    float bx = 0.f, by = 0.f, bz = 0.f;

    int i = 0;
    for (; i + 4 <= m; i += 4) {
        float4 w0 = __ldg(&g_cwv[start + i]);
        float4 w1 = __ldg(&g_cwv[start + i + 1]);
        float4 w2 = __ldg(&g_cwv[start + i + 2]);
        float4 w3 = __ldg(&g_cwv[start + i + 3]);
        int s0 = __float_as_int(w0.w);
        int s1 = __float_as_int(w1.w);
        int s2 = __float_as_int(w2.w);
        int s3 = __float_as_int(w3.w);
        float qa = __ldg(&g_q [s0 * DDIM + lane]);
        float qb = __ldg(&g_q [s1 * DDIM + lane]);
        float qc = __ldg(&g_q [s2 * DDIM + lane]);
        float qd = __ldg(&g_q [s3 * DDIM + lane]);
        float pa = __ldg(&g_q2[s0 * DDIM + lane]);
        float pb = __ldg(&g_q2[s1 * DDIM + lane]);
        float pc = __ldg(&g_q2[s2 * DDIM + lane]);
        float pd = __ldg(&g_q2[s3 * DDIM + lane]);
        ax = fmaf(w0.x, qa, ax); ax = fmaf(w1.x, qb, ax);
        ax = fmaf(w2.x, qc, ax); ax = fmaf(w3.x, qd, ax);
        ay = fmaf(w0.y, qa, ay); ay = fmaf(w1.y, qb, ay);
        ay = fmaf(w2.y, qc, ay); ay = fmaf(w3.y, qd, ay);
        az = fmaf(w0.z, qa, az); az = fmaf(w1.z, qb, az);
        az = fmaf(w2.z, qc, az); az = fmaf(w3.z, qd, az);
        bx = fmaf(w0.x, pa, bx); bx = fmaf(w1.x, pb, bx);
        bx = fmaf(w2.x, pc, bx); bx = fmaf(w3.x, pd, bx);
        by = fmaf(w0.y, pa, by); by = fmaf(w1.y, pb, by);
        by = fmaf(w2.y, pc, by); by = fmaf(w3.y, pd, by);
        bz = fmaf(w0.z, pa, bz); bz = fmaf(w1.z, pb, bz);
        bz = fmaf(w2.z, pc, bz); bz = fmaf(w3.z, pd, bz);
    }
    for (; i < m; i++) {
        float4 w0 = __ldg(&g_cwv[start + i]);
        int s0 = __float_as_int(w0.w);
        float qa = __ldg(&g_q [s0 * DDIM + lane]);
        float pa = __ldg(&g_q2[s0 * DDIM + lane]);
        ax = fmaf(w0.x, qa, ax);
        ay = fmaf(w0.y, qa, ay);
        az = fmaf(w0.z, qa, az);
        bx = fmaf(w0.x, pa, bx);
        by = fmaf(w0.y, pa, by);
        bz = fmaf(w0.z, pa, bz);
    }

    float m0 = __ldg(wmix), m1 = __ldg(wmix + 1), m2 = __ldg(wmix + 2);
    float bm = __ldg(bmix);

    float cx = ay * bz - az * by;
    float cy = az * bx - ax * bz;
    float cz = ax * by - ay * bx;

    size_t p = (size_t)gw * (DDIM * 3) + lane * 3;
    out[p + 0] = ax * m0 + bx * m1 + cx * m2 + bm;
    out[p + 1] = ay * m0 + by * m1 + cy * m2 + bm;
    out[p + 2] = az * m0 + bz * m1 + cz * m2 + bm;
}

// ---------------- launch ----------------
extern "C" void kernel_launch(void* const* d_in, const int* in_sizes, int n_in,
                              void* d_out, int out_size)
{
    const float* x    = (const float*)d_in[0];
    const float* rij  = (const float*)d_in[1];
    const float* vij  = (const float*)d_in[2];
    const int*   src  = (const int*)  d_in[3];
    const int*   dst  = (const int*)  d_in[4];
    const float* W1   = (const float*)d_in[5];
    const float* b1   = (const float*)d_in[6];
    const float* W2   = (const float*)d_in[7];
    const float* b2   = (const float*)d_in[8];
    const float* W1b  = (const float*)d_in[9];
    const float* b1b  = (const float*)d_in[10];
    const float* W2b  = (const float*)d_in[11];
    const float* b2b  = (const float*)d_in[12];
    const float* wmix = (const float*)d_in[13];
    const float* bmix = (const float*)d_in[14];
    float* out = (float*)d_out;

    int N = in_sizes[0] / FDIM;
    int E = in_sizes[1];
    if (N > NMAX) N = NMAX;
    if (E > EMAX) E = EMAX;

    cudaFuncSetAttribute(transform_kernel,
                         cudaFuncAttributeMaxDynamicSharedMemorySize, SM_TOTAL);

    int gE = (E + 255) / 256;
    int gN = (N + 255) / 256;
    int nb = (N + 2047) / 2048;
    int ntiles = (N + 127) / 128;

    // fork: CSR chain on side stream, transform chain on capture stream
    cudaStream_t s2;
    cudaStreamCreateWithFlags(&s2, cudaStreamNonBlocking);
    cudaEvent_t evFork, evJoin;
    cudaEventCreateWithFlags(&evFork, cudaEventDisableTiming);
    cudaEventCreateWithFlags(&evJoin, cudaEventDisableTiming);

    cudaEventRecord(evFork, 0);
    cudaStreamWaitEvent(s2, evFork, 0);

    // ---- side stream: CSR build ----
    zero_cnt_kernel<<<gN, 256, 0, s2>>>(N);
    count_kernel<<<(E / 2 + 255) / 256, 256, 0, s2>>>(dst, rij, E);
    scan1_kernel<<<nb, 256, 0, s2>>>(N);
    scan2_kernel<<<1, 32, 0, s2>>>(nb);
    scan3_kernel<<<gN, 256, 0, s2>>>(N);
    scatter_kernel<<<gE, 256, 0, s2>>>(src, dst, rij, vij, E);
    cudaEventRecord(evJoin, s2);

    // ---- capture stream: persistent transform ----
    dim3 gT(PERSIST_X, 2);
    transform_kernel<<<gT, TTHREADS, SM_TOTAL>>>(x, W1, b1, W2, b2,
                                                 W1b, b1b, W2b, b2b, N, ntiles);

    // join, then gather
    cudaStreamWaitEvent(0, evJoin, 0);
    int gG = (N * 32 + 255) / 256;
    gather_kernel<<<gG, 256>>>(wmix, bmix, out, N);

    cudaEventDestroy(evFork);
    cudaEventDestroy(evJoin);
    cudaStreamDestroy(s2);
}

// round 13
// speedup vs baseline: 3.4840x; 1.0837x over previous
#include <cuda_runtime.h>
#include <cuda_bf16.h>
#include <cstdint>

#define NMAX   50000
#define EMAX   800000
#define FDIM   128
#define DDIM   32
#define CUT    5.0f
#define PI_F   3.14159265358979323846f

// ---------------- device scratch (static, allocation-free) ----------------
__device__ float  g_q [NMAX * DDIM];
__device__ float  g_q2[NMAX * DDIM];
__device__ int    g_cnt[NMAX];
__device__ int    g_off[NMAX];
__device__ int    g_cur[NMAX];
__device__ int    g_bsum[64];
__device__ float4 g_cwv[EMAX];

// swish via tanh.approx: v*sigmoid(v) = 0.5v*(1+tanh(0.5v)); 1 MUFU.
__device__ __forceinline__ float swish_f(float v) {
    float t, h = 0.5f * v;
    asm("tanh.approx.f32 %0, %1;" : "=f"(t) : "f"(h));
    return fmaf(h, t, h);
}

// ---------------- helpers (baseline PTX only) -----------------------------
__device__ __forceinline__ uint32_t smem_u32(const void* p) {
    uint32_t a;
    asm("{ .reg .u64 t; cvta.to.shared.u64 t, %1; cvt.u32.u64 %0, t; }"
        : "=r"(a) : "l"(p));
    return a;
}
__device__ __forceinline__ void ldsm_x4(uint32_t* r, uint32_t addr) {
    asm volatile("ldmatrix.sync.aligned.m8n8.x4.shared.b16 {%0,%1,%2,%3}, [%4];"
                 : "=r"(r[0]), "=r"(r[1]), "=r"(r[2]), "=r"(r[3]) : "r"(addr));
}
__device__ __forceinline__ void ldsm_x4t(uint32_t* r, uint32_t addr) {
    asm volatile("ldmatrix.sync.aligned.m8n8.x4.trans.shared.b16 {%0,%1,%2,%3}, [%4];"
                 : "=r"(r[0]), "=r"(r[1]), "=r"(r[2]), "=r"(r[3]) : "r"(addr));
}
__device__ __forceinline__ void mma16816(float* c, const uint32_t* a,
                                         const uint32_t* b) {
    asm volatile(
        "mma.sync.aligned.m16n8k16.row.col.f32.bf16.bf16.f32 "
        "{%0,%1,%2,%3}, {%4,%5,%6,%7}, {%8,%9}, {%0,%1,%2,%3};"
        : "+f"(c[0]), "+f"(c[1]), "+f"(c[2]), "+f"(c[3])
        : "r"(a[0]), "r"(a[1]), "r"(a[2]), "r"(a[3]), "r"(b[0]), "r"(b[1]));
}
// packed rn convert: lo -> low half, hi -> high half
__device__ __forceinline__ uint32_t cvt2_bf(float lo, float hi) {
    uint32_t r;
    asm("cvt.rn.bf16x2.f32 %0, %1, %2;" : "=r"(r) : "f"(hi), "f"(lo));
    return r;
}
// split float4 -> packed hi uint2 / lo uint2
__device__ __forceinline__ void split4(float4 v, uint2& hv, uint2& lv) {
    uint32_t h01 = cvt2_bf(v.x, v.y);
    uint32_t h23 = cvt2_bf(v.z, v.w);
    float hx = __uint_as_float(h01 << 16);
    float hy = __uint_as_float(h01 & 0xFFFF0000u);
    float hz = __uint_as_float(h23 << 16);
    float hw = __uint_as_float(h23 & 0xFFFF0000u);
    hv = make_uint2(h01, h23);
    lv = make_uint2(cvt2_bf(v.x - hx, v.y - hy), cvt2_bf(v.z - hz, v.w - hw));
}

// smem layout (bf16, padded strides for conflict-free ldmatrix)
#define LDA    136
#define LDB2   40
#define MTILE  64
#define SA_HI  0
#define SA_LO  (SA_HI  + MTILE * LDA * 2)   // 17408
#define SB1_HI (SA_LO  + MTILE * LDA * 2)   // 34816
#define SB1_LO (SB1_HI + 128 * LDA * 2)     // 69632
#define SB2_HI (SB1_LO + 128 * LDA * 2)     // 104448
#define SB2_LO (SB2_HI + 128 * LDB2 * 2)    // 114688
#define SM_TOTAL (SB2_LO + 128 * LDB2 * 2)  // 124928 bytes

#define PERSIST_X 74
#define TTHREADS  512

// ==== persistent node transform, 64-row tiles, register prefetch ==========
__global__ __launch_bounds__(TTHREADS, 1) void transform_kernel(
    const float* __restrict__ x,
    const float* __restrict__ W1a, const float* __restrict__ b1a,
    const float* __restrict__ W2a, const float* __restrict__ b2a,
    const float* __restrict__ W1b, const float* __restrict__ b1b,
    const float* __restrict__ W2b, const float* __restrict__ b2b,
    int nrows, int ntiles)
{
    extern __shared__ char smc[];
    const uint32_t sb = smem_u32(smc);

    const int branch = blockIdx.y;
    const float* W1 = branch ? W1b : W1a;
    const float* b1 = branch ? b1b : b1a;
    const float* W2 = branch ? W2b : W2a;
    const float* b2 = branch ? b2b : b2a;
    float* q_out = branch ? g_q2 : g_q;

    const int tid  = threadIdx.x;
    const int wid  = tid >> 5;          // 0..15
    const int lane = tid & 31;

    // ---- convert weights once ----
    for (int i = tid; i < 4096; i += TTHREADS) {
        int k = i >> 5, c4 = (i & 31) << 2;
        uint2 hv, lv;
        split4(*reinterpret_cast<const float4*>(W1 + k * 128 + c4), hv, lv);
        *reinterpret_cast<uint2*>(smc + SB1_HI + (k * LDA + c4) * 2) = hv;
        *reinterpret_cast<uint2*>(smc + SB1_LO + (k * LDA + c4) * 2) = lv;
    }
    for (int i = tid; i < 1024; i += TTHREADS) {
        int k = i >> 3, c4 = (i & 7) << 2;
        uint2 hv, lv;
        split4(*reinterpret_cast<const float4*>(W2 + k * 32 + c4), hv, lv);
        *reinterpret_cast<uint2*>(smc + SB2_HI + (k * LDB2 + c4) * 2) = hv;
        *reinterpret_cast<uint2*>(smc + SB2_LO + (k * LDB2 + c4) * 2) = lv;
    }

    // layer1: 16 warps cover 64x128: warp tile 16 rows x 32 cols
    const int wm = (wid & 3) << 4;      // 0..48
    const int wn = (wid >> 2) << 5;     // 0,32,64,96
    // layer2 (warps 0-7): warp tile 16 rows x 16 cols
    const int m0 = (wid & 3) << 4;
    const int cg = (wid >> 2) << 4;     // 0 or 16 (valid for wid<8)
    const int arow = lane & 15, ac8 = (lane >> 4) << 3;
    const int rbase = lane >> 2;
    const int cbase = (lane & 3) << 1;

    // per-thread prefetch regs: 2 chunks x 8 floats
    float4 pf[2][2];
    const int pr[2]  = {tid >> 3, (tid + 512) >> 3};          // rows 0..63,64..127->(i>>4)
    // NOTE index math below mirrors convert loop: i = tid + j*512; r=i>>4; c4=(i&15)<<3
    auto do_prefetch = [&](int t2) {
        #pragma unroll
        for (int j = 0; j < 2; j++) {
            int i = tid + j * 512;
            int r = i >> 4, c4 = (i & 15) << 3;
            int row = t2 * MTILE + r;
            if (t2 < ntiles && row < nrows) {
                const float* xp = x + (size_t)row * 128 + c4;
                pf[j][0] = *reinterpret_cast<const float4*>(xp);
                pf[j][1] = *reinterpret_cast<const float4*>(xp + 4);
            } else {
                pf[j][0] = make_float4(0.f, 0.f, 0.f, 0.f);
                pf[j][1] = pf[j][0];
            }
        }
    };
    (void)pr;

    do_prefetch(blockIdx.x);

    for (int t = blockIdx.x; t < ntiles; t += PERSIST_X) {
        const int row0 = t * MTILE;

        // ---- convert prefetched x -> sA hi/lo ----
        __syncthreads();   // prior iteration's layer2 reads of sA done
        #pragma unroll
        for (int j = 0; j < 2; j++) {
            int i = tid + j * 512;
            int r = i >> 4, c4 = (i & 15) << 3;
            uint2 h0, l0, h1, l1;
            split4(pf[j][0], h0, l0);
            split4(pf[j][1], h1, l1);
            uint32_t o = (r * LDA + c4) * 2;
            *reinterpret_cast<uint4*>(smc + SA_HI + o) =
                make_uint4(h0.x, h0.y, h1.x, h1.y);
            *reinterpret_cast<uint4*>(smc + SA_LO + o) =
                make_uint4(l0.x, l0.y, l1.x, l1.y);
        }
        __syncthreads();

        // ======== layer1: C[64][128] = x @ W1 ========
        float acc[4][4];
        #pragma unroll
        for (int nt = 0; nt < 4; nt++)
            #pragma unroll
            for (int r = 0; r < 4; r++) acc[nt][r] = 0.f;

        #pragma unroll
        for (int ks = 0; ks < 8; ks++) {
            const int k0 = ks << 4;
            uint32_t aH[4], aL[4];
            {
                uint32_t off = ((wm + arow) * LDA + k0 + ac8) * 2;
                ldsm_x4(aH, sb + SA_HI + off);
                ldsm_x4(aL, sb + SA_LO + off);
            }
            uint32_t bH[2][4], bL[2][4];
            #pragma unroll
            for (int g = 0; g < 2; g++) {
                uint32_t off = ((k0 + arow) * LDA + wn + g * 16 + ac8) * 2;
                ldsm_x4t(bH[g], sb + SB1_HI + off);
                ldsm_x4t(bL[g], sb + SB1_LO + off);
            }
            // per-acc accumulation order: hh, hl, lh (unchanged)
            #pragma unroll
            for (int nt = 0; nt < 4; nt++)
                mma16816(acc[nt], aH, &bH[nt >> 1][(nt & 1) * 2]);
            #pragma unroll
            for (int nt = 0; nt < 4; nt++)
                mma16816(acc[nt], aH, &bL[nt >> 1][(nt & 1) * 2]);
            #pragma unroll
            for (int nt = 0; nt < 4; nt++)
                mma16816(acc[nt], aL, &bH[nt >> 1][(nt & 1) * 2]);
        }
        __syncthreads();   // sA reads done before overwrite with h

        // ---- epilogue 1: h = swish(C + b1), split -> sA hi/lo ----
        #pragma unroll
        for (int nt = 0; nt < 4; nt++) {
            int col = wn + nt * 8 + cbase;
            float g0 = __ldg(b1 + col), g1 = __ldg(b1 + col + 1);
            #pragma unroll
            for (int hh = 0; hh < 2; hh++) {
                int row = wm + rbase + hh * 8;
                float v0 = swish_f(acc[nt][2 * hh]     + g0);
                float v1 = swish_f(acc[nt][2 * hh + 1] + g1);
                uint32_t hp = cvt2_bf(v0, v1);
                float h0 = __uint_as_float(hp << 16);
                float h1 = __uint_as_float(hp & 0xFFFF0000u);
                uint32_t o = (row * LDA + col) * 2;
                *reinterpret_cast<uint32_t*>(smc + SA_HI + o) = hp;
                *reinterpret_cast<uint32_t*>(smc + SA_LO + o) =
                    cvt2_bf(v0 - h0, v1 - h1);
            }
        }
        __syncthreads();

        // ---- issue prefetch for next tile (hides LDG under layer2) ----
        do_prefetch(t + PERSIST_X);

        // ======== layer2: q[64][32] = h @ W2; warps 0-7 ========
        if (wid < 8) {
            float acc2[2][4];
            #pragma unroll
            for (int nt = 0; nt < 2; nt++)
                #pragma unroll
                for (int r = 0; r < 4; r++) acc2[nt][r] = 0.f;

            #pragma unroll
            for (int ks = 0; ks < 8; ks++) {
                const int k0 = ks << 4;
                uint32_t aH[4], aL[4];
                uint32_t offa = ((m0 + arow) * LDA + k0 + ac8) * 2;
                ldsm_x4(aH, sb + SA_HI + offa);
                ldsm_x4(aL, sb + SA_LO + offa);
                uint32_t bH[4], bL[4];
                {
                    uint32_t off = ((k0 + arow) * LDB2 + cg + ac8) * 2;
                    ldsm_x4t(bH, sb + SB2_HI + off);
                    ldsm_x4t(bL, sb + SB2_LO + off);
                }
                #pragma unroll
                for (int nt = 0; nt < 2; nt++)
                    mma16816(acc2[nt], aH, &bH[nt * 2]);
                #pragma unroll
                for (int nt = 0; nt < 2; nt++)
                    mma16816(acc2[nt], aH, &bL[nt * 2]);
                #pragma unroll
                for (int nt = 0; nt < 2; nt++)
                    mma16816(acc2[nt], aL, &bH[nt * 2]);
            }

            // ---- epilogue 2: q = swish(C2 + b2) -> gmem ----
            #pragma unroll
            for (int nt = 0; nt < 2; nt++) {
                int col = cg + nt * 8 + cbase;
                float g0 = __ldg(b2 + col), g1 = __ldg(b2 + col + 1);
                #pragma unroll
                for (int hh = 0; hh < 2; hh++) {
                    int row = row0 + m0 + rbase + hh * 8;
                    if (row < nrows) {
                        float2 o2;
                        o2.x = swish_f(acc2[nt][2 * hh]     + g0);
                        o2.y = swish_f(acc2[nt][2 * hh + 1] + g1);
                        *reinterpret_cast<float2*>(q_out + (size_t)row * DDIM + col) = o2;
                    }
                }
            }
        }
        // loop-top __syncthreads() protects sA before next conversion
    }
}

// ---------------- CSR build ----------------
__global__ void zero_cnt_kernel(int n) {
    int i = blockIdx.x * blockDim.x + threadIdx.x;
    if (i < n) g_cnt[i] = 0;
}

__global__ void count_kernel(const int* __restrict__ dst,
                             const float* __restrict__ rij, int E) {
    int e = (blockIdx.x * blockDim.x + threadIdx.x) * 2;
    if (e + 1 < E) {
        float2 r2 = *reinterpret_cast<const float2*>(rij + e);
        int2   d2 = *reinterpret_cast<const int2*>(dst + e);
        if (r2.x < CUT) atomicAdd(&g_cnt[d2.x], 1);
        if (r2.y < CUT) atomicAdd(&g_cnt[d2.y], 1);
    } else if (e < E) {
        if (rij[e] < CUT) atomicAdd(&g_cnt[dst[e]], 1);
    }
}

__global__ void scan1_kernel(int n) {
    __shared__ int s[256];
    int base = blockIdx.x * 2048 + threadIdx.x * 8;
    int v[8];
    int sum = 0;
    #pragma unroll
    for (int j = 0; j < 8; j++) {
        int idx = base + j;
        int t = (idx < n) ? g_cnt[idx] : 0;
        v[j] = sum;
        sum += t;
    }
    s[threadIdx.x] = sum;
    __syncthreads();
    for (int off = 1; off < 256; off <<= 1) {
        int t = (threadIdx.x >= off) ? s[threadIdx.x - off] : 0;
        __syncthreads();
        s[threadIdx.x] += t;
        __syncthreads();
    }
    int excl = s[threadIdx.x] - sum;
    if (threadIdx.x == 255) g_bsum[blockIdx.x] = s[255];
    #pragma unroll
    for (int j = 0; j < 8; j++) {
        int idx = base + j;
        if (idx < n) g_off[idx] = excl + v[j];
    }
}

__global__ void scan2_kernel(int nb) {
    if (threadIdx.x == 0) {
        int a = 0;
        for (int i = 0; i < nb; i++) { int t = g_bsum[i]; g_bsum[i] = a; a += t; }
    }
}

__global__ void scan3_kernel(int n) {
    int i = blockIdx.x * blockDim.x + threadIdx.x;
    if (i < n) {
        int o = g_off[i] + g_bsum[i >> 11];
        g_off[i] = o;
        g_cur[i] = o;
    }
}

__global__ void scatter_kernel(const int* __restrict__ src,
                               const int* __restrict__ dst,
                               const float* __restrict__ rij,
                               const float* __restrict__ vij, int E) {
    int e = blockIdx.x * blockDim.x + threadIdx.x;
    if (e >= E) return;
    float r = rij[e];
    if (r < CUT) {
        float c = 0.5f * (cosf(PI_F * r / CUT) + 1.0f);
        int p = atomicAdd(&g_cur[dst[e]], 1);
        g_cwv[p] = make_float4(c * vij[3 * e], c * vij[3 * e + 1],
                               c * vij[3 * e + 2], __int_as_float(src[e]));
    }
}

// ---------------- gather + cross + mix, one warp per node, lane = d --------
__global__ __launch_bounds__(256) void gather_kernel(
    const float* __restrict__ wmix, const float* __restrict__ bmix,
    float* __restrict__ out, int nNodes)
{
    int gw   = (blockIdx.x * 256 + threadIdx.x) >> 5;
    int lane = threadIdx.x & 31;
    if (gw >= nNodes) return;

    int start = g_off[gw];
    int m     = g_cnt[gw];

    float ax = 0.f, ay = 0.f, az = 0.f;
    float bx = 0.f, by = 0.f, bz = 0.f;

    int i = 0;
    for (; i + 4 <= m; i += 4) {
        float4 w0 = __ldg(&g_cwv[start + i]);
        float4 w1 = __ldg(&g_cwv[start + i + 1]);
        float4 w2 = __ldg(&g_cwv[start + i + 2]);
        float4 w3 = __ldg(&g_cwv[start + i + 3]);
        int s0 = __float_as_int(w0.w);
        int s1 = __float_as_int(w1.w);
        int s2 = __float_as_int(w2.w);
        int s3 = __float_as_int(w3.w);
        float qa = __ldg(&g_q [s0 * DDIM + lane]);
        float qb = __ldg(&g_q [s1 * DDIM + lane]);
        float qc = __ldg(&g_q [s2 * DDIM + lane]);
        float qd = __ldg(&g_q [s3 * DDIM + lane]);
        float pa = __ldg(&g_q2[s0 * DDIM + lane]);
        float pb = __ldg(&g_q2[s1 * DDIM + lane]);
        float pc = __ldg(&g_q2[s2 * DDIM + lane]);
        float pd = __ldg(&g_q2[s3 * DDIM + lane]);
        ax = fmaf(w0.x, qa, ax); ax = fmaf(w1.x, qb, ax);
        ax = fmaf(w2.x, qc, ax); ax = fmaf(w3.x, qd, ax);
        ay = fmaf(w0.y, qa, ay); ay = fmaf(w1.y, qb, ay);
        ay = fmaf(w2.y, qc, ay); ay = fmaf(w3.y, qd, ay);
        az = fmaf(w0.z, qa, az); az = fmaf(w1.z, qb, az);
        az = fmaf(w2.z, qc, az); az = fmaf(w3.z, qd, az);
        bx = fmaf(w0.x, pa, bx); bx = fmaf(w1.x, pb, bx);
        bx = fmaf(w2.x, pc, bx); bx = fmaf(w3.x, pd, bx);
        by = fmaf(w0.y, pa, by); by = fmaf(w1.y, pb, by);
        by = fmaf(w2.y, pc, by); by = fmaf(w3.y, pd, by);
        bz = fmaf(w0.z, pa, bz); bz = fmaf(w1.z, pb, bz);
        bz = fmaf(w2.z, pc, bz); bz = fmaf(w3.z, pd, bz);
    }
    for (; i < m; i++) {
        float4 w0 = __ldg(&g_cwv[start + i]);
        int s0 = __float_as_int(w0.w);
        float qa = __ldg(&g_q [s0 * DDIM + lane]);
        float pa = __ldg(&g_q2[s0 * DDIM + lane]);
        ax = fmaf(w0.x, qa, ax);
        ay = fmaf(w0.y, qa, ay);
        az = fmaf(w0.z, qa, az);
        bx = fmaf(w0.x, pa, bx);
        by = fmaf(w0.y, pa, by);
        bz = fmaf(w0.z, pa, bz);
    }

    float m0 = __ldg(wmix), m1 = __ldg(wmix + 1), m2 = __ldg(wmix + 2);
    float bm = __ldg(bmix);

    float cx = ay * bz - az * by;
    float cy = az * bx - ax * bz;
    float cz = ax * by - ay * bx;

    size_t p = (size_t)gw * (DDIM * 3) + lane * 3;
    out[p + 0] = ax * m0 + bx * m1 + cx * m2 + bm;
    out[p + 1] = ay * m0 + by * m1 + cy * m2 + bm;
    out[p + 2] = az * m0 + bz * m1 + cz * m2 + bm;
}

// ---------------- launch ----------------
extern "C" void kernel_launch(void* const* d_in, const int* in_sizes, int n_in,
                              void* d_out, int out_size)
{
    const float* x    = (const float*)d_in[0];
    const float* rij  = (const float*)d_in[1];
    const float* vij  = (const float*)d_in[2];
    const int*   src  = (const int*)  d_in[3];
    const int*   dst  = (const int*)  d_in[4];
    const float* W1   = (const float*)d_in[5];
    const float* b1   = (const float*)d_in[6];
    const float* W2   = (const float*)d_in[7];
    const float* b2   = (const float*)d_in[8];
    const float* W1b  = (const float*)d_in[9];
    const float* b1b  = (const float*)d_in[10];
    const float* W2b  = (const float*)d_in[11];
    const float* b2b  = (const float*)d_in[12];
    const float* wmix = (const float*)d_in[13];
    const float* bmix = (const float*)d_in[14];
    float* out = (float*)d_out;

    int N = in_sizes[0] / FDIM;
    int E = in_sizes[1];
    if (N > NMAX) N = NMAX;
    if (E > EMAX) E = EMAX;

    cudaFuncSetAttribute(transform_kernel,
                         cudaFuncAttributeMaxDynamicSharedMemorySize, SM_TOTAL);

    int gE = (E + 255) / 256;
    int gN = (N + 255) / 256;
    int nb = (N + 2047) / 2048;
    int ntiles = (N + MTILE - 1) / MTILE;

    // fork: CSR chain on side stream, transform chain on capture stream
    cudaStream_t s2;
    cudaStreamCreateWithFlags(&s2, cudaStreamNonBlocking);
    cudaEvent_t evFork, evJoin;
    cudaEventCreateWithFlags(&evFork, cudaEventDisableTiming);
    cudaEventCreateWithFlags(&evJoin, cudaEventDisableTiming);

    cudaEventRecord(evFork, 0);
    cudaStreamWaitEvent(s2, evFork, 0);

    // ---- side stream: CSR build ----
    zero_cnt_kernel<<<gN, 256, 0, s2>>>(N);
    count_kernel<<<(E / 2 + 255) / 256, 256, 0, s2>>>(dst, rij, E);
    scan1_kernel<<<nb, 256, 0, s2>>>(N);
    scan2_kernel<<<1, 32, 0, s2>>>(nb);
    scan3_kernel<<<gN, 256, 0, s2>>>(N);
    scatter_kernel<<<gE, 256, 0, s2>>>(src, dst, rij, vij, E);
    cudaEventRecord(evJoin, s2);

    // ---- capture stream: persistent transform ----
    dim3 gT(PERSIST_X, 2);
    transform_kernel<<<gT, TTHREADS, SM_TOTAL>>>(x, W1, b1, W2, b2,
                                                 W1b, b1b, W2b, b2b, N, ntiles);

    // join, then gather
    cudaStreamWaitEvent(0, evJoin, 0);
    int gG = (N * 32 + 255) / 256;
    gather_kernel<<<gG, 256>>>(wmix, bmix, out, N);

    cudaEventDestroy(evFork);
    cudaEventDestroy(evJoin);
    cudaStreamDestroy(s2);
}